// round 8
// baseline (speedup 1.0000x reference)
#include <cuda_runtime.h>
#include <cuda_bf16.h>
#include <cuda_fp16.h>
#include <math.h>

// Problem dims
#define Tt 16
#define Mm 1024
#define Hh 128
#define ROWS 16384
#define MAXD 128
#define NL_TR 5

// ---------------- scratch (device globals; no allocations) ----------------
__device__ float g_h[ROWS * 384];          // transformer QKV fp32
__device__ __half g_hh[ROWS * 512];        // GAT projections, fp16, head-minor [row][d][head]
__device__ float g_ss[ROWS * 4];
__device__ float g_sd[ROWS * 4];
__device__ unsigned char g_m[ROWS];
__device__ int g_cnt[ROWS];
__device__ unsigned short g_nbr[ROWS * MAXD];
__device__ float g_xs[ROWS * Hh];
__device__ float g_c[16];                  // gat0 score scalars
__device__ float g_pe[Tt * Hh];            // sinusoidal PE table
__device__ __nv_bfloat16 g_xah[ROWS * Hh], g_xal[ROWS * Hh];
__device__ __nv_bfloat16 g_xbh[ROWS * Hh], g_xbl[ROWS * Hh];
__device__ __nv_bfloat16 g_xsh[ROWS * Hh], g_xsl[ROWS * Hh];
__device__ __nv_bfloat16 g_atth[ROWS * Hh], g_attl[ROWS * Hh];
__device__ __nv_bfloat16 g_ffh[ROWS * 512], g_ffl[ROWS * 512];

#define WTOT 1310720
#define OFF_GAT 0
#define OFF_QKV 327680
#define OFF_WO  573440
#define OFF_FF1 655360
#define OFF_FF2 983040
__device__ __nv_bfloat16 g_wh[WTOT];
__device__ __nv_bfloat16 g_wl[WTOT];

__device__ __forceinline__ unsigned smem_u32(const void* p) {
    unsigned a;
    asm("{ .reg .u64 t; cvta.to.shared.u64 t, %1; cvt.u32.u64 %0, t; }" : "=r"(a) : "l"(p));
    return a;
}
__device__ __forceinline__ void ldmat4(unsigned& r0, unsigned& r1, unsigned& r2, unsigned& r3, unsigned addr) {
    asm volatile("ldmatrix.sync.aligned.m8n8.x4.shared.b16 {%0,%1,%2,%3}, [%4];"
        : "=r"(r0), "=r"(r1), "=r"(r2), "=r"(r3) : "r"(addr));
}
__device__ __forceinline__ void mma16816(float* c, unsigned a0, unsigned a1, unsigned a2, unsigned a3,
                                         unsigned b0, unsigned b1) {
    asm volatile("mma.sync.aligned.m16n8k16.row.col.f32.bf16.bf16.f32 "
        "{%0,%1,%2,%3}, {%4,%5,%6,%7}, {%8,%9}, {%0,%1,%2,%3};"
        : "+f"(c[0]), "+f"(c[1]), "+f"(c[2]), "+f"(c[3])
        : "r"(a0), "r"(a1), "r"(a2), "r"(a3), "r"(b0), "r"(b1));
}
__device__ __forceinline__ void cpa16(unsigned dst, const void* src) {
    asm volatile("cp.async.ca.shared.global [%0], [%1], 16;" :: "r"(dst), "l"(src));
}
#define CPA_COMMIT() asm volatile("cp.async.commit_group;" ::: "memory")
#define CPA_WAIT1() asm volatile("cp.async.wait_group 1;" ::: "memory")
#define CPA_WAIT0() asm volatile("cp.async.wait_group 0;" ::: "memory")

__device__ __forceinline__ unsigned pack_hi2(float a, float b) {
    __nv_bfloat16 ha = __float2bfloat16(a), hb = __float2bfloat16(b);
    return (unsigned)__bfloat16_as_ushort(ha) | ((unsigned)__bfloat16_as_ushort(hb) << 16);
}
__device__ __forceinline__ unsigned pack_lo2(float a, float b) {
    __nv_bfloat16 ha = __float2bfloat16(a), hb = __float2bfloat16(b);
    float la = a - __bfloat162float(ha), lb2 = b - __bfloat162float(hb);
    __nv_bfloat16 qa = __float2bfloat16(la), qb = __float2bfloat16(lb2);
    return (unsigned)__bfloat16_as_ushort(qa) | ((unsigned)__bfloat16_as_ushort(qb) << 16);
}

// SMEM: 2 stages x 4 planes, each 128 rows x 32 bf16 (80B stride)
#define TROW 80
#define PBUF (128 * TROW)
#define STAGE (4 * PBUF)
#define P_AHI 0
#define P_ALO PBUF
#define P_BHI (2 * PBUF)
#define P_BLO (3 * PBUF)
#define GSM_TOTAL (2 * STAGE)   // 81920 -> 2 CTA/SM

// ---------------- HMMA GEMM, planar bf16 A/B, cp.async double-buffered ----------------
// H16 != nullptr -> GAT mode: write fp16 head-minor h table [row][d][4] (head = blockIdx.x)
template <int ACT, bool RESID, bool SCORES, bool LNORM>
__global__ void __launch_bounds__(256, 2)
gemm_tc(const __nv_bfloat16* __restrict__ Ah, const __nv_bfloat16* __restrict__ Al,
        const __nv_bfloat16* __restrict__ Bh, const __nv_bfloat16* __restrict__ Bl,
        const float* __restrict__ bias, const float* __restrict__ Rr,
        float* __restrict__ C, __nv_bfloat16* __restrict__ Ch, __nv_bfloat16* __restrict__ Cl,
        __half* __restrict__ H16,
        const float* __restrict__ asrc, const float* __restrict__ adst,
        float* __restrict__ gss, float* __restrict__ gsd,
        const float* __restrict__ ls, const float* __restrict__ lb, int Nt, int Kt) {
    extern __shared__ char smem[];
    const unsigned sb = smem_u32(smem);
    const int tid = threadIdx.x;
    const int wid = tid >> 5, lane = tid & 31;
    const int wr = wid >> 1, wc = wid & 1;
    const int row0 = blockIdx.y * 128;
    const int col0 = blockIdx.x * 128;

    float acc[2][8][4];
#pragma unroll
    for (int mt = 0; mt < 2; mt++)
#pragma unroll
        for (int nt = 0; nt < 8; nt++)
#pragma unroll
            for (int e = 0; e < 4; e++) acc[mt][nt][e] = 0.f;

    const int ltile = lane >> 3, lrow = lane & 7;
    const int nch = Kt >> 5;

#define LOAD_CHUNK(cidx, s) do { \
    unsigned base = sb + (s) * STAGE; \
    _Pragma("unroll") \
    for (int j = 0; j < 2; j++) { \
        int i = tid + j * 256; \
        int rr = i >> 2, qq = i & 3; \
        unsigned off = (unsigned)(rr * TROW + qq * 16); \
        size_t ga = (size_t)(row0 + rr) * Kt + (cidx) * 32 + qq * 8; \
        size_t gb = (size_t)(col0 + rr) * Kt + (cidx) * 32 + qq * 8; \
        cpa16(base + P_AHI + off, Ah + ga); \
        cpa16(base + P_ALO + off, Al + ga); \
        cpa16(base + P_BHI + off, Bh + gb); \
        cpa16(base + P_BLO + off, Bl + gb); \
    } \
} while (0)

    LOAD_CHUNK(0, 0);
    CPA_COMMIT();

    for (int c = 0; c < nch; c++) {
        if (c + 1 < nch) {
            LOAD_CHUNK(c + 1, (c + 1) & 1);
            CPA_COMMIT();
            CPA_WAIT1();
        } else {
            CPA_WAIT0();
        }
        __syncthreads();
        unsigned base = sb + (c & 1) * STAGE;
#pragma unroll
        for (int ks = 0; ks < 2; ks++) {
            unsigned ah[2][4], al[2][4];
#pragma unroll
            for (int mt = 0; mt < 2; mt++) {
                int row = wr * 32 + mt * 16 + lrow + (ltile & 1) * 8;
                int kcol = ks * 16 + (ltile >> 1) * 8;
                unsigned off = (unsigned)(row * TROW + kcol * 2);
                ldmat4(ah[mt][0], ah[mt][1], ah[mt][2], ah[mt][3], base + P_AHI + off);
                ldmat4(al[mt][0], al[mt][1], al[mt][2], al[mt][3], base + P_ALO + off);
            }
#pragma unroll
            for (int g = 0; g < 4; g++) {
                int n = wc * 64 + g * 16 + lrow + (ltile >> 1) * 8;
                int kcol = ks * 16 + (ltile & 1) * 8;
                unsigned off = (unsigned)(n * TROW + kcol * 2);
                unsigned bh[4], bl[4];
                ldmat4(bh[0], bh[1], bh[2], bh[3], base + P_BHI + off);
                ldmat4(bl[0], bl[1], bl[2], bl[3], base + P_BLO + off);
#pragma unroll
                for (int mt = 0; mt < 2; mt++)
#pragma unroll
                    for (int half = 0; half < 2; half++) {
                        float* cc = acc[mt][g * 2 + half];
                        mma16816(cc, ah[mt][0], ah[mt][1], ah[mt][2], ah[mt][3],
                                 bh[half * 2], bh[half * 2 + 1]);
                        mma16816(cc, ah[mt][0], ah[mt][1], ah[mt][2], ah[mt][3],
                                 bl[half * 2], bl[half * 2 + 1]);
                        mma16816(cc, al[mt][0], al[mt][1], al[mt][2], al[mt][3],
                                 bh[half * 2], bh[half * 2 + 1]);
                    }
            }
        }
        __syncthreads();
    }
#undef LOAD_CHUNK

    float* stage = (float*)smem;
#pragma unroll
    for (int mt = 0; mt < 2; mt++)
#pragma unroll
        for (int nt = 0; nt < 8; nt++) {
            int row = wr * 32 + mt * 16 + (lane >> 2);
            int col = wc * 64 + nt * 8 + (lane & 3) * 2;
            float2 v0 = make_float2(acc[mt][nt][0], acc[mt][nt][1]);
            float2 v1 = make_float2(acc[mt][nt][2], acc[mt][nt][3]);
            *(float2*)(stage + (size_t)row * 132 + col) = v0;
            *(float2*)(stage + (size_t)(row + 8) * 132 + col) = v1;
        }
    __syncthreads();

    if (LNORM) {
        const int c = lane * 4;
        float4 bb = *(const float4*)(bias + c);
        float4 sv = *(const float4*)(ls + c);
        float4 bv = *(const float4*)(lb + c);
#pragma unroll 4
        for (int rr = 0; rr < 16; rr++) {
            int r = wid * 16 + rr;
            float4 v = *(float4*)(stage + (size_t)r * 132 + c);
            float4 res = *(const float4*)(Rr + (size_t)(row0 + r) * 128 + c);
            v.x += bb.x + res.x; v.y += bb.y + res.y;
            v.z += bb.z + res.z; v.w += bb.w + res.w;
            float s = v.x + v.y + v.z + v.w;
#pragma unroll
            for (int o = 16; o; o >>= 1) s += __shfl_xor_sync(0xFFFFFFFFu, s, o);
            float mean = s * (1.f / 128.f);
            float dx = v.x - mean, dy = v.y - mean, dz = v.z - mean, dw = v.w - mean;
            float qq = dx * dx + dy * dy + dz * dz + dw * dw;
#pragma unroll
            for (int o = 16; o; o >>= 1) qq += __shfl_xor_sync(0xFFFFFFFFu, qq, o);
            float rstd = rsqrtf(qq * (1.f / 128.f) + 1e-5f);
            float4 ov;
            ov.x = dx * rstd * sv.x + bv.x;
            ov.y = dy * rstd * sv.y + bv.y;
            ov.z = dz * rstd * sv.z + bv.z;
            ov.w = dw * rstd * sv.w + bv.w;
            if (C) *(float4*)(C + (size_t)(row0 + r) * 128 + c) = ov;
            if (Ch) {
                uint2 uh, ul;
                uh.x = pack_hi2(ov.x, ov.y); uh.y = pack_hi2(ov.z, ov.w);
                ul.x = pack_lo2(ov.x, ov.y); ul.y = pack_lo2(ov.z, ov.w);
                *(uint2*)(Ch + (size_t)(row0 + r) * 128 + c) = uh;
                *(uint2*)(Cl + (size_t)(row0 + r) * 128 + c) = ul;
            }
        }
    } else {
        for (int i = tid; i < 128 * 32; i += 256) {
            int r = i >> 5, q = i & 31;
            int c = q * 4;
            float4 v = *(float4*)(stage + (size_t)r * 132 + c);
            if (bias) {
                v.x += bias[col0 + c];
                v.y += bias[col0 + c + 1];
                v.z += bias[col0 + c + 2];
                v.w += bias[col0 + c + 3];
            }
            if (RESID) {
                float4 rr = *(const float4*)(Rr + (size_t)(row0 + r) * Nt + col0 + c);
                v.x += rr.x; v.y += rr.y; v.z += rr.z; v.w += rr.w;
            }
            if (ACT == 1) {
                v.x = fmaxf(v.x, 0.f); v.y = fmaxf(v.y, 0.f);
                v.z = fmaxf(v.z, 0.f); v.w = fmaxf(v.w, 0.f);
            }
            if (C) *(float4*)(C + (size_t)(row0 + r) * Nt + col0 + c) = v;
            if (H16) {
                // head-minor fp16: [row][d][head], d = c..c+3, head = blockIdx.x
                __half* hp = H16 + (size_t)(row0 + r) * 512 + (size_t)c * 4 + blockIdx.x;
                hp[0]  = __float2half(v.x);
                hp[4]  = __float2half(v.y);
                hp[8]  = __float2half(v.z);
                hp[12] = __float2half(v.w);
            }
            if (Ch) {
                uint2 uh, ul;
                uh.x = pack_hi2(v.x, v.y); uh.y = pack_hi2(v.z, v.w);
                ul.x = pack_lo2(v.x, v.y); ul.y = pack_lo2(v.z, v.w);
                *(uint2*)(Ch + (size_t)(row0 + r) * Nt + col0 + c) = uh;
                *(uint2*)(Cl + (size_t)(row0 + r) * Nt + col0 + c) = ul;
            }
        }
    }

    if (SCORES && tid < 128) {
        int r = tid;
        float s1 = 0.f, s2 = 0.f;
        const float* as = asrc + col0;
        const float* ad = adst + col0;
        const float* sp = stage + (size_t)r * 132;
#pragma unroll 8
        for (int c = 0; c < 128; c++) {
            float hv = sp[c];
            s1 += hv * as[c];
            s2 += hv * ad[c];
        }
        gss[(size_t)(row0 + r) * 4 + blockIdx.x] = s1;
        gsd[(size_t)(row0 + r) * 4 + blockIdx.x] = s2;
    }
}

// ---------------- weight pre-split; QKV packed per-layer [384, 128] ----------------
__global__ void split_weights(const float* __restrict__ gatW, const float* __restrict__ Wqkv,
                              const float* __restrict__ Wo, const float* __restrict__ Wff1,
                              const float* __restrict__ Wff2) {
    int idx = blockIdx.x * 256 + threadIdx.x;
    if (idx >= WTOT) return;
    float v;
    if (idx < OFF_QKV) {
        int i = idx >> 16, r = idx & 65535;
        int n = r >> 7, k = r & 127;
        v = gatW[(i << 16) + k * 512 + n];
    } else if (idx < OFF_WO) {
        int r0 = idx - OFF_QKV;
        int l = r0 / 49152;
        int rem = r0 - l * 49152;
        int n = rem >> 7, k = rem & 127;
        int s = n >> 7, nc = n & 127;
        v = Wqkv[((l * 3 + s) << 14) + k * 128 + nc];
    } else if (idx < OFF_FF1) {
        int r0 = idx - OFF_WO;
        int i = r0 >> 14, r = r0 & 16383;
        int n = r >> 7, k = r & 127;
        v = Wo[(i << 14) + k * 128 + n];
    } else if (idx < OFF_FF2) {
        int r0 = idx - OFF_FF1;
        int i = r0 >> 16, r = r0 & 65535;
        int n = r >> 7, k = r & 127;
        v = Wff1[(i << 16) + k * 512 + n];
    } else {
        int r0 = idx - OFF_FF2;
        int i = r0 >> 16, r = r0 & 65535;
        int n = r >> 9, k = r & 511;
        v = Wff2[(i << 16) + k * 128 + n];
    }
    __nv_bfloat16 h = __float2bfloat16(v);
    g_wh[idx] = h;
    g_wl[idx] = __float2bfloat16(v - __bfloat162float(h));
}

// ---------------- tiny precompute: gat0 score scalars + PE table (1 block) ----------------
__global__ void precompute(const float* __restrict__ W, const float* __restrict__ asrc,
                           const float* __restrict__ adst) {
    int tid = threadIdx.x;
    int wid = tid >> 5, lane = tid & 31;
    float a0s = 0.f, a1s = 0.f, a0d = 0.f, a1d = 0.f;
    for (int d = lane; d < 128; d += 32) {
        int c = wid * 128 + d;
        float w0 = W[c], w1 = W[512 + c], as = asrc[c], ad = adst[c];
        a0s += w0 * as; a1s += w1 * as; a0d += w0 * ad; a1d += w1 * ad;
    }
#pragma unroll
    for (int o = 16; o; o >>= 1) {
        a0s += __shfl_xor_sync(0xFFFFFFFFu, a0s, o);
        a1s += __shfl_xor_sync(0xFFFFFFFFu, a1s, o);
        a0d += __shfl_xor_sync(0xFFFFFFFFu, a0d, o);
        a1d += __shfl_xor_sync(0xFFFFFFFFu, a1d, o);
    }
    if (lane == 0) {
        g_c[wid] = a0s; g_c[4 + wid] = a1s; g_c[8 + wid] = a0d; g_c[12 + wid] = a1d;
    }
    for (int i = tid; i < Tt * Hh; i += 128) {
        int t = i >> 7, d = i & 127;
        float freq = expf(-(float)(d & ~1) * (9.210340371976184f / 128.f));
        float ang = (float)t * freq;
        g_pe[i] = (d & 1) ? cosf(ang) : sinf(ang);
    }
}

// ---------------- mask + self-loop init ----------------
__global__ void mask_init(const unsigned char* __restrict__ ego) {
    int idx = blockIdx.x * 256 + threadIdx.x;
    if (idx >= ROWS) return;
    int t = idx >> 10;
    int mm = idx & 1023;
    int b = mm >> 8;
    int n = mm & 255;
    unsigned char v = ego[(b * Tt + t) * 256 + n] ? 1 : 0;
    g_m[idx] = v;
    g_cnt[idx] = v ? 1 : 0;
    g_nbr[idx * MAXD] = (unsigned short)mm;
}

// ---------------- neighbor-list build ----------------
__global__ void build_nbr(const float* __restrict__ A) {
    int tj = blockIdx.x >> 2;
    int i = ((blockIdx.x & 3) << 8) + threadIdx.x;
    if (!g_m[tj]) return;
    int t = tj >> 10;
    int j = tj & 1023;
    if (i == j) return;
    float a = A[(size_t)tj * 1024 + i];
    int ti = (t << 10) + i;
    if (a != 0.f && g_m[ti]) {
        int pos = atomicAdd(&g_cnt[ti], 1);
        if (pos < MAXD) g_nbr[ti * MAXD + pos] = (unsigned short)j;
    }
}

// ---------------- GAT layer-0: streaming projection (FIN=2), fp16 head-minor + scalar scores ----------------
__global__ void gat0(const float* __restrict__ x, const float* __restrict__ W) {
    int idx = blockIdx.x * 256 + threadIdx.x;   // ROWS*512
    int row = idx >> 9;
    int c2 = idx & 511;        // head-minor position: d*4 + head
    int hh = c2 & 3, d = c2 >> 2;
    float x0 = x[row * 2], x1 = x[row * 2 + 1];
    int c = hh * 128 + d;      // weight index (head-major)
    g_hh[idx] = __float2half(x0 * W[c] + x1 * W[512 + c]);
    if (c2 < 8) {
        int isd = c2 >> 2;     // 0: src, 1: dst
        float v = x0 * g_c[hh + isd * 8] + x1 * g_c[hh + 4 + isd * 8];
        if (isd == 0) g_ss[row * 4 + hh] = v;
        else g_sd[row * 4 + hh] = v;
    }
}

// ---------------- sparse segment-softmax + aggregation (fp16 head-minor gather) ----------------
__global__ void gat_agg(const float* __restrict__ bias,
                        __nv_bfloat16* __restrict__ xh, __nv_bfloat16* __restrict__ xl) {
    int row = blockIdx.x;
    int tid = threadIdx.x;
    if (!g_m[row]) {
        xh[(size_t)row * 128 + tid] = __float2bfloat16(0.f);
        xl[(size_t)row * 128 + tid] = __float2bfloat16(0.f);
        return;
    }
    int t = row >> 10;

    __shared__ unsigned short nb[MAXD];
    __shared__ float w[4][MAXD];

    int cnt = g_cnt[row];
    if (cnt > MAXD) cnt = MAXD;
    if (tid < cnt) nb[tid] = g_nbr[(size_t)row * MAXD + tid];

    if (tid < cnt) {
        int jr = (t << 10) + nb[tid];
#pragma unroll
        for (int hh = 0; hh < 4; hh++) {
            float z = g_sd[row * 4 + hh] + g_ss[jr * 4 + hh];
            w[hh][tid] = (z > 0.f) ? z : 0.2f * z;
        }
    } else {
#pragma unroll
        for (int hh = 0; hh < 4; hh++) w[hh][tid] = -INFINITY;
    }
    __syncthreads();

    {
        int wh = tid >> 5, lane = tid & 31;
        float v0 = w[wh][lane], v1 = w[wh][lane + 32], v2 = w[wh][lane + 64], v3 = w[wh][lane + 96];
        float mx = fmaxf(fmaxf(v0, v1), fmaxf(v2, v3));
#pragma unroll
        for (int o = 16; o; o >>= 1) mx = fmaxf(mx, __shfl_xor_sync(0xFFFFFFFFu, mx, o));
        float e0 = expf(v0 - mx), e1 = expf(v1 - mx), e2 = expf(v2 - mx), e3 = expf(v3 - mx);
        float s = e0 + e1 + e2 + e3;
#pragma unroll
        for (int o = 16; o; o >>= 1) s += __shfl_xor_sync(0xFFFFFFFFu, s, o);
        float inv = 1.f / s;
        w[wh][lane] = e0 * inv;
        w[wh][lane + 32] = e1 * inv;
        w[wh][lane + 64] = e2 * inv;
        w[wh][lane + 96] = e3 * inv;
    }
    __syncthreads();

    // gather: one uint2 (4 heads, fp16) per neighbor per thread
    float acc0 = 0.f, acc1 = 0.f, acc2 = 0.f, acc3 = 0.f;
    const __half* hb = g_hh + (((size_t)(t << 10)) << 9) + (tid << 2);
    int j = 0;
    for (; j + 4 <= cnt; j += 4) {
        uint2 q0 = *(const uint2*)(hb + ((size_t)nb[j] << 9));
        uint2 q1 = *(const uint2*)(hb + ((size_t)nb[j + 1] << 9));
        uint2 q2 = *(const uint2*)(hb + ((size_t)nb[j + 2] << 9));
        uint2 q3 = *(const uint2*)(hb + ((size_t)nb[j + 3] << 9));
        float2 a01 = __half22float2(*(__half2*)&q0.x), a23 = __half22float2(*(__half2*)&q0.y);
        float2 b01 = __half22float2(*(__half2*)&q1.x), b23 = __half22float2(*(__half2*)&q1.y);
        float2 c01 = __half22float2(*(__half2*)&q2.x), c23 = __half22float2(*(__half2*)&q2.y);
        float2 d01 = __half22float2(*(__half2*)&q3.x), d23 = __half22float2(*(__half2*)&q3.y);
        acc0 += w[0][j] * a01.x + w[1][j] * a01.y + w[2][j] * a23.x + w[3][j] * a23.y;
        acc1 += w[0][j + 1] * b01.x + w[1][j + 1] * b01.y + w[2][j + 1] * b23.x + w[3][j + 1] * b23.y;
        acc2 += w[0][j + 2] * c01.x + w[1][j + 2] * c01.y + w[2][j + 2] * c23.x + w[3][j + 2] * c23.y;
        acc3 += w[0][j + 3] * d01.x + w[1][j + 3] * d01.y + w[2][j + 3] * d23.x + w[3][j + 3] * d23.y;
    }
    for (; j < cnt; j++) {
        uint2 q0 = *(const uint2*)(hb + ((size_t)nb[j] << 9));
        float2 a01 = __half22float2(*(__half2*)&q0.x), a23 = __half22float2(*(__half2*)&q0.y);
        acc0 += w[0][j] * a01.x + w[1][j] * a01.y + w[2][j] * a23.x + w[3][j] * a23.y;
    }
    float o = (acc0 + acc1 + acc2 + acc3) * 0.25f + bias[tid];
    o = fmaxf(o, 0.f);
    __nv_bfloat16 hi = __float2bfloat16(o);
    xh[(size_t)row * 128 + tid] = hi;
    xl[(size_t)row * 128 + tid] = __float2bfloat16(o - __bfloat162float(hi));
}

// ---------------- transpose to sequence layout + PE (table lookup) ----------------
__global__ void to_seq(const __nv_bfloat16* __restrict__ xh, const __nv_bfloat16* __restrict__ xl) {
    int idx = blockIdx.x * 256 + threadIdx.x;
    int row = idx >> 7;
    int d = idx & 127;
    int t = row >> 10;
    int mm = row & 1023;
    float x = __bfloat162float(xh[idx]) + __bfloat162float(xl[idx]);
    float v = x + g_pe[t * 128 + d];
    size_t sidx = ((size_t)mm * Tt + t) * Hh + d;
    g_xs[sidx] = v;
    __nv_bfloat16 hi = __float2bfloat16(v);
    g_xsh[sidx] = hi;
    g_xsl[sidx] = __float2bfloat16(v - __bfloat162float(hi));
}

// ---------------- per-sequence attention (T=16, 4 heads of 32), packed QKV ----------------
__global__ void attn_kernel(const float* __restrict__ QKV,
                            __nv_bfloat16* __restrict__ Oh, __nv_bfloat16* __restrict__ Ol) {
    __shared__ float sq[16][128], sk[16][128], sv[16][128];
    int m = blockIdx.x;
    int tid = threadIdx.x;
    size_t base = (size_t)m * 16 * 384;
    for (int idx = tid; idx < 2048; idx += 128) {
        int t = idx >> 7, d = idx & 127;
        size_t p = base + (size_t)t * 384 + d;
        sq[t][d] = QKV[p];
        sk[t][d] = QKV[p + 128];
        sv[t][d] = QKV[p + 256];
    }
    __syncthreads();
    int h = tid >> 5;
    int tq = (tid >> 1) & 15;
    int half = tid & 1;
    const float scale = 0.17677669529663687f;
    float sc[16];
    float mx = -1e30f;
#pragma unroll
    for (int tk = 0; tk < 16; tk++) {
        float s = 0.f;
#pragma unroll
        for (int dd = 0; dd < 16; dd++) {
            int d = half * 16 + dd;
            s += sq[tq][h * 32 + d] * sk[tk][h * 32 + d];
        }
        s += __shfl_xor_sync(0xFFFFFFFFu, s, 1);
        s *= scale;
        sc[tk] = s;
        mx = fmaxf(mx, s);
    }
    float sum = 0.f;
#pragma unroll
    for (int tk = 0; tk < 16; tk++) { sc[tk] = expf(sc[tk] - mx); sum += sc[tk]; }
    float inv = 1.f / sum;
    size_t ob = (size_t)m * 16 * 128 + (size_t)tq * 128 + h * 32 + half * 16;
#pragma unroll
    for (int dd = 0; dd < 16; dd++) {
        int d = half * 16 + dd;
        float o = 0.f;
#pragma unroll
        for (int tk = 0; tk < 16; tk++) o += sc[tk] * sv[tk][h * 32 + d];
        o *= inv;
        __nv_bfloat16 hi = __float2bfloat16(o);
        Oh[ob + dd] = hi;
        Ol[ob + dd] = __float2bfloat16(o - __bfloat162float(hi));
    }
}

// ---------------- launcher ----------------
extern "C" void kernel_launch(void* const* d_in, const int* in_sizes, int n_in,
                              void* d_out, int out_size) {
    const unsigned char* ego = (const unsigned char*)d_in[0];
    const float* positions  = (const float*)d_in[1];
    const float* adjacency  = (const float*)d_in[2];
    const float* gat1_W     = (const float*)d_in[3];
    const float* gat1_asrc  = (const float*)d_in[4];
    const float* gat1_adst  = (const float*)d_in[5];
    const float* gat1_b     = (const float*)d_in[6];
    const float* gatW       = (const float*)d_in[7];
    const float* gat_asrc   = (const float*)d_in[8];
    const float* gat_adst   = (const float*)d_in[9];
    const float* gat_b      = (const float*)d_in[10];
    const float* Wqkv       = (const float*)d_in[11];
    const float* bqkv       = (const float*)d_in[12];
    const float* Wo         = (const float*)d_in[13];
    const float* bo         = (const float*)d_in[14];
    const float* ln1_s      = (const float*)d_in[15];
    const float* ln1_b      = (const float*)d_in[16];
    const float* ln2_s      = (const float*)d_in[17];
    const float* ln2_b      = (const float*)d_in[18];
    const float* Wff1       = (const float*)d_in[19];
    const float* bff1       = (const float*)d_in[20];
    const float* Wff2       = (const float*)d_in[21];
    const float* bff2       = (const float*)d_in[22];
    float* out = (float*)d_out;

    float *h, *xs, *ss, *sd;
    __half* hh;
    __nv_bfloat16 *wh, *wl, *xah, *xal, *xbh, *xbl, *xsh, *xsl, *atth, *attl, *ffh, *ffl;
    cudaGetSymbolAddress((void**)&h,    g_h);
    cudaGetSymbolAddress((void**)&hh,   g_hh);
    cudaGetSymbolAddress((void**)&xs,   g_xs);
    cudaGetSymbolAddress((void**)&ss,   g_ss);
    cudaGetSymbolAddress((void**)&sd,   g_sd);
    cudaGetSymbolAddress((void**)&wh,   g_wh);
    cudaGetSymbolAddress((void**)&wl,   g_wl);
    cudaGetSymbolAddress((void**)&xah,  g_xah);
    cudaGetSymbolAddress((void**)&xal,  g_xal);
    cudaGetSymbolAddress((void**)&xbh,  g_xbh);
    cudaGetSymbolAddress((void**)&xbl,  g_xbl);
    cudaGetSymbolAddress((void**)&xsh,  g_xsh);
    cudaGetSymbolAddress((void**)&xsl,  g_xsl);
    cudaGetSymbolAddress((void**)&atth, g_atth);
    cudaGetSymbolAddress((void**)&attl, g_attl);
    cudaGetSymbolAddress((void**)&ffh,  g_ffh);
    cudaGetSymbolAddress((void**)&ffl,  g_ffl);

    cudaFuncSetAttribute(gemm_tc<0, false, true,  false>, cudaFuncAttributeMaxDynamicSharedMemorySize, GSM_TOTAL);
    cudaFuncSetAttribute(gemm_tc<0, false, false, false>, cudaFuncAttributeMaxDynamicSharedMemorySize, GSM_TOTAL);
    cudaFuncSetAttribute(gemm_tc<0, true,  false, true >, cudaFuncAttributeMaxDynamicSharedMemorySize, GSM_TOTAL);
    cudaFuncSetAttribute(gemm_tc<1, false, false, false>, cudaFuncAttributeMaxDynamicSharedMemorySize, GSM_TOTAL);

    split_weights<<<(WTOT + 255) / 256, 256>>>(gatW, Wqkv, Wo, Wff1, Wff2);
    precompute<<<1, 128>>>(gat1_W, gat1_asrc, gat1_adst);
    mask_init<<<ROWS / 256, 256>>>(ego);
    build_nbr<<<ROWS * 4, 256>>>(adjacency);

    // GAT layer 0 (FIN=2)
    gat0<<<ROWS * 512 / 256, 256>>>(positions, gat1_W);
    gat_agg<<<ROWS, 128>>>(gat1_b, xah, xal);

    // GAT layers 1..5
    __nv_bfloat16 *curh = xah, *curl = xal, *nxth = xbh, *nxtl = xbl;
    for (int i = 0; i < 5; i++) {
        dim3 gp(4, ROWS / 128);
        gemm_tc<0, false, true, false><<<gp, 256, GSM_TOTAL>>>(
            curh, curl, wh + OFF_GAT + (size_t)i * 65536, wl + OFF_GAT + (size_t)i * 65536,
            nullptr, nullptr, nullptr, nullptr, nullptr, hh,
            gat_asrc + i * 512, gat_adst + i * 512, ss, sd, nullptr, nullptr, 512, 128);
        gat_agg<<<ROWS, 128>>>(gat_b + i * 128, nxth, nxtl);
        __nv_bfloat16* t0 = curh; curh = nxth; nxth = t0;
        __nv_bfloat16* t1 = curl; curl = nxtl; nxtl = t1;
    }

    to_seq<<<ROWS * 128 / 256, 256>>>(curh, curl);

    dim3 g1(1, ROWS / 128);
    dim3 g2(4, ROWS / 128);
    dim3 gq(3, ROWS / 128);
    for (int l = 0; l < NL_TR; l++) {
        size_t oq = OFF_QKV + (size_t)l * 49152;
        gemm_tc<0, false, false, false><<<gq, 256, GSM_TOTAL>>>(
            xsh, xsl, wh + oq, wl + oq,
            bqkv + l * 384, nullptr, h, nullptr, nullptr, nullptr,
            nullptr, nullptr, nullptr, nullptr, nullptr, nullptr, 384, 128);
        attn_kernel<<<Mm, 128>>>(h, atth, attl);
        size_t owo = OFF_WO + (size_t)l * 16384;
        gemm_tc<0, true, false, true><<<g1, 256, GSM_TOTAL>>>(
            atth, attl, wh + owo, wl + owo,
            bo + l * 128, xs, xs, xsh, xsl, nullptr,
            nullptr, nullptr, nullptr, nullptr,
            ln1_s + l * 128, ln1_b + l * 128, 128, 128);
        size_t of1 = OFF_FF1 + (size_t)l * 65536;
        gemm_tc<1, false, false, false><<<g2, 256, GSM_TOTAL>>>(
            xsh, xsl, wh + of1, wl + of1,
            bff1 + l * 512, nullptr, nullptr, ffh, ffl, nullptr,
            nullptr, nullptr, nullptr, nullptr, nullptr, nullptr, 512, 128);
        size_t of2 = OFF_FF2 + (size_t)l * 65536;
        if (l == NL_TR - 1) {
            gemm_tc<0, true, false, true><<<g1, 256, GSM_TOTAL>>>(
                ffh, ffl, wh + of2, wl + of2,
                bff2 + l * 128, xs, out, nullptr, nullptr, nullptr,
                nullptr, nullptr, nullptr, nullptr,
                ln2_s + l * 128, ln2_b + l * 128, 128, 512);
        } else {
            gemm_tc<0, true, false, true><<<g1, 256, GSM_TOTAL>>>(
                ffh, ffl, wh + of2, wl + of2,
                bff2 + l * 128, xs, xs, xsh, xsl, nullptr,
                nullptr, nullptr, nullptr, nullptr,
                ln2_s + l * 128, ln2_b + l * 128, 128, 512);
        }
    }
}

// round 9
// speedup vs baseline: 1.2051x; 1.2051x over previous
#include <cuda_runtime.h>
#include <cuda_bf16.h>
#include <cuda_fp16.h>
#include <math.h>

// Problem dims
#define Tt 16
#define Mm 1024
#define Hh 128
#define ROWS 16384
#define MAXD 128
#define NL_TR 5

// ---------------- scratch (device globals; no allocations) ----------------
__device__ float g_h[ROWS * 384];          // transformer QKV fp32
__device__ __half g_hh[ROWS * 512];        // GAT projections fp16, head-major [row][head*128+d]
__device__ float g_ss[ROWS * 4];
__device__ float g_sd[ROWS * 4];
__device__ unsigned char g_m[ROWS];
__device__ int g_cnt[ROWS];
__device__ unsigned short g_nbr[ROWS * MAXD];
__device__ float g_xs[ROWS * Hh];
__device__ float g_c[16];                  // gat0 score scalars
__device__ float g_pe[Tt * Hh];            // sinusoidal PE table
__device__ __nv_bfloat16 g_xah[ROWS * Hh], g_xal[ROWS * Hh];
__device__ __nv_bfloat16 g_xbh[ROWS * Hh], g_xbl[ROWS * Hh];
__device__ __nv_bfloat16 g_xsh[ROWS * Hh], g_xsl[ROWS * Hh];
__device__ __nv_bfloat16 g_atth[ROWS * Hh], g_attl[ROWS * Hh];
__device__ __nv_bfloat16 g_ffh[ROWS * 512], g_ffl[ROWS * 512];

#define WTOT 1310720
#define OFF_GAT 0
#define OFF_QKV 327680
#define OFF_WO  573440
#define OFF_FF1 655360
#define OFF_FF2 983040
__device__ __nv_bfloat16 g_wh[WTOT];
__device__ __nv_bfloat16 g_wl[WTOT];

__device__ __forceinline__ unsigned smem_u32(const void* p) {
    unsigned a;
    asm("{ .reg .u64 t; cvta.to.shared.u64 t, %1; cvt.u32.u64 %0, t; }" : "=r"(a) : "l"(p));
    return a;
}
__device__ __forceinline__ void ldmat4(unsigned& r0, unsigned& r1, unsigned& r2, unsigned& r3, unsigned addr) {
    asm volatile("ldmatrix.sync.aligned.m8n8.x4.shared.b16 {%0,%1,%2,%3}, [%4];"
        : "=r"(r0), "=r"(r1), "=r"(r2), "=r"(r3) : "r"(addr));
}
__device__ __forceinline__ void mma16816(float* c, unsigned a0, unsigned a1, unsigned a2, unsigned a3,
                                         unsigned b0, unsigned b1) {
    asm volatile("mma.sync.aligned.m16n8k16.row.col.f32.bf16.bf16.f32 "
        "{%0,%1,%2,%3}, {%4,%5,%6,%7}, {%8,%9}, {%0,%1,%2,%3};"
        : "+f"(c[0]), "+f"(c[1]), "+f"(c[2]), "+f"(c[3])
        : "r"(a0), "r"(a1), "r"(a2), "r"(a3), "r"(b0), "r"(b1));
}
__device__ __forceinline__ void cpa16(unsigned dst, const void* src) {
    asm volatile("cp.async.ca.shared.global [%0], [%1], 16;" :: "r"(dst), "l"(src));
}
#define CPA_COMMIT() asm volatile("cp.async.commit_group;" ::: "memory")
#define CPA_WAIT1() asm volatile("cp.async.wait_group 1;" ::: "memory")
#define CPA_WAIT0() asm volatile("cp.async.wait_group 0;" ::: "memory")

__device__ __forceinline__ unsigned pack_hi2(float a, float b) {
    __nv_bfloat16 ha = __float2bfloat16(a), hb = __float2bfloat16(b);
    return (unsigned)__bfloat16_as_ushort(ha) | ((unsigned)__bfloat16_as_ushort(hb) << 16);
}
__device__ __forceinline__ unsigned pack_lo2(float a, float b) {
    __nv_bfloat16 ha = __float2bfloat16(a), hb = __float2bfloat16(b);
    float la = a - __bfloat162float(ha), lb2 = b - __bfloat162float(hb);
    __nv_bfloat16 qa = __float2bfloat16(la), qb = __float2bfloat16(lb2);
    return (unsigned)__bfloat16_as_ushort(qa) | ((unsigned)__bfloat16_as_ushort(qb) << 16);
}
__device__ __forceinline__ unsigned packh2(float a, float b) {
    __half2 h = __floats2half2_rn(a, b);
    return *(unsigned*)&h;
}

// SMEM: 2 stages x 4 planes, each 128 rows x 32 bf16 (80B stride)
#define TROW 80
#define PBUF (128 * TROW)
#define STAGE (4 * PBUF)
#define P_AHI 0
#define P_ALO PBUF
#define P_BHI (2 * PBUF)
#define P_BLO (3 * PBUF)
#define GSM_TOTAL (2 * STAGE)   // 81920 -> 2 CTA/SM

// ---------------- HMMA GEMM, planar bf16 A/B, cp.async double-buffered ----------------
// H16 != nullptr -> GAT mode: write fp16 head-major h table (coalesced uint2)
template <int ACT, bool RESID, bool SCORES, bool LNORM>
__global__ void __launch_bounds__(256, 2)
gemm_tc(const __nv_bfloat16* __restrict__ Ah, const __nv_bfloat16* __restrict__ Al,
        const __nv_bfloat16* __restrict__ Bh, const __nv_bfloat16* __restrict__ Bl,
        const float* __restrict__ bias, const float* __restrict__ Rr,
        float* __restrict__ C, __nv_bfloat16* __restrict__ Ch, __nv_bfloat16* __restrict__ Cl,
        __half* __restrict__ H16,
        const float* __restrict__ asrc, const float* __restrict__ adst,
        float* __restrict__ gss, float* __restrict__ gsd,
        const float* __restrict__ ls, const float* __restrict__ lb, int Nt, int Kt) {
    extern __shared__ char smem[];
    const unsigned sb = smem_u32(smem);
    const int tid = threadIdx.x;
    const int wid = tid >> 5, lane = tid & 31;
    const int wr = wid >> 1, wc = wid & 1;
    const int row0 = blockIdx.y * 128;
    const int col0 = blockIdx.x * 128;

    float acc[2][8][4];
#pragma unroll
    for (int mt = 0; mt < 2; mt++)
#pragma unroll
        for (int nt = 0; nt < 8; nt++)
#pragma unroll
            for (int e = 0; e < 4; e++) acc[mt][nt][e] = 0.f;

    const int ltile = lane >> 3, lrow = lane & 7;
    const int nch = Kt >> 5;

#define LOAD_CHUNK(cidx, s) do { \
    unsigned base = sb + (s) * STAGE; \
    _Pragma("unroll") \
    for (int j = 0; j < 2; j++) { \
        int i = tid + j * 256; \
        int rr = i >> 2, qq = i & 3; \
        unsigned off = (unsigned)(rr * TROW + qq * 16); \
        size_t ga = (size_t)(row0 + rr) * Kt + (cidx) * 32 + qq * 8; \
        size_t gb = (size_t)(col0 + rr) * Kt + (cidx) * 32 + qq * 8; \
        cpa16(base + P_AHI + off, Ah + ga); \
        cpa16(base + P_ALO + off, Al + ga); \
        cpa16(base + P_BHI + off, Bh + gb); \
        cpa16(base + P_BLO + off, Bl + gb); \
    } \
} while (0)

    LOAD_CHUNK(0, 0);
    CPA_COMMIT();

    for (int c = 0; c < nch; c++) {
        if (c + 1 < nch) {
            LOAD_CHUNK(c + 1, (c + 1) & 1);
            CPA_COMMIT();
            CPA_WAIT1();
        } else {
            CPA_WAIT0();
        }
        __syncthreads();
        unsigned base = sb + (c & 1) * STAGE;
#pragma unroll
        for (int ks = 0; ks < 2; ks++) {
            unsigned ah[2][4], al[2][4];
#pragma unroll
            for (int mt = 0; mt < 2; mt++) {
                int row = wr * 32 + mt * 16 + lrow + (ltile & 1) * 8;
                int kcol = ks * 16 + (ltile >> 1) * 8;
                unsigned off = (unsigned)(row * TROW + kcol * 2);
                ldmat4(ah[mt][0], ah[mt][1], ah[mt][2], ah[mt][3], base + P_AHI + off);
                ldmat4(al[mt][0], al[mt][1], al[mt][2], al[mt][3], base + P_ALO + off);
            }
#pragma unroll
            for (int g = 0; g < 4; g++) {
                int n = wc * 64 + g * 16 + lrow + (ltile >> 1) * 8;
                int kcol = ks * 16 + (ltile & 1) * 8;
                unsigned off = (unsigned)(n * TROW + kcol * 2);
                unsigned bh[4], bl[4];
                ldmat4(bh[0], bh[1], bh[2], bh[3], base + P_BHI + off);
                ldmat4(bl[0], bl[1], bl[2], bl[3], base + P_BLO + off);
#pragma unroll
                for (int mt = 0; mt < 2; mt++)
#pragma unroll
                    for (int half = 0; half < 2; half++) {
                        float* cc = acc[mt][g * 2 + half];
                        mma16816(cc, ah[mt][0], ah[mt][1], ah[mt][2], ah[mt][3],
                                 bh[half * 2], bh[half * 2 + 1]);
                        mma16816(cc, ah[mt][0], ah[mt][1], ah[mt][2], ah[mt][3],
                                 bl[half * 2], bl[half * 2 + 1]);
                        mma16816(cc, al[mt][0], al[mt][1], al[mt][2], al[mt][3],
                                 bh[half * 2], bh[half * 2 + 1]);
                    }
            }
        }
        __syncthreads();
    }
#undef LOAD_CHUNK

    float* stage = (float*)smem;
#pragma unroll
    for (int mt = 0; mt < 2; mt++)
#pragma unroll
        for (int nt = 0; nt < 8; nt++) {
            int row = wr * 32 + mt * 16 + (lane >> 2);
            int col = wc * 64 + nt * 8 + (lane & 3) * 2;
            float2 v0 = make_float2(acc[mt][nt][0], acc[mt][nt][1]);
            float2 v1 = make_float2(acc[mt][nt][2], acc[mt][nt][3]);
            *(float2*)(stage + (size_t)row * 132 + col) = v0;
            *(float2*)(stage + (size_t)(row + 8) * 132 + col) = v1;
        }
    __syncthreads();

    if (LNORM) {
        const int c = lane * 4;
        float4 bb = *(const float4*)(bias + c);
        float4 sv = *(const float4*)(ls + c);
        float4 bv = *(const float4*)(lb + c);
#pragma unroll 4
        for (int rr = 0; rr < 16; rr++) {
            int r = wid * 16 + rr;
            float4 v = *(float4*)(stage + (size_t)r * 132 + c);
            float4 res = *(const float4*)(Rr + (size_t)(row0 + r) * 128 + c);
            v.x += bb.x + res.x; v.y += bb.y + res.y;
            v.z += bb.z + res.z; v.w += bb.w + res.w;
            float s = v.x + v.y + v.z + v.w;
#pragma unroll
            for (int o = 16; o; o >>= 1) s += __shfl_xor_sync(0xFFFFFFFFu, s, o);
            float mean = s * (1.f / 128.f);
            float dx = v.x - mean, dy = v.y - mean, dz = v.z - mean, dw = v.w - mean;
            float qq = dx * dx + dy * dy + dz * dz + dw * dw;
#pragma unroll
            for (int o = 16; o; o >>= 1) qq += __shfl_xor_sync(0xFFFFFFFFu, qq, o);
            float rstd = rsqrtf(qq * (1.f / 128.f) + 1e-5f);
            float4 ov;
            ov.x = dx * rstd * sv.x + bv.x;
            ov.y = dy * rstd * sv.y + bv.y;
            ov.z = dz * rstd * sv.z + bv.z;
            ov.w = dw * rstd * sv.w + bv.w;
            if (C) *(float4*)(C + (size_t)(row0 + r) * 128 + c) = ov;
            if (Ch) {
                uint2 uh, ul;
                uh.x = pack_hi2(ov.x, ov.y); uh.y = pack_hi2(ov.z, ov.w);
                ul.x = pack_lo2(ov.x, ov.y); ul.y = pack_lo2(ov.z, ov.w);
                *(uint2*)(Ch + (size_t)(row0 + r) * 128 + c) = uh;
                *(uint2*)(Cl + (size_t)(row0 + r) * 128 + c) = ul;
            }
        }
    } else {
        for (int i = tid; i < 128 * 32; i += 256) {
            int r = i >> 5, q = i & 31;
            int c = q * 4;
            float4 v = *(float4*)(stage + (size_t)r * 132 + c);
            if (bias) {
                v.x += bias[col0 + c];
                v.y += bias[col0 + c + 1];
                v.z += bias[col0 + c + 2];
                v.w += bias[col0 + c + 3];
            }
            if (RESID) {
                float4 rr = *(const float4*)(Rr + (size_t)(row0 + r) * Nt + col0 + c);
                v.x += rr.x; v.y += rr.y; v.z += rr.z; v.w += rr.w;
            }
            if (ACT == 1) {
                v.x = fmaxf(v.x, 0.f); v.y = fmaxf(v.y, 0.f);
                v.z = fmaxf(v.z, 0.f); v.w = fmaxf(v.w, 0.f);
            }
            if (C) *(float4*)(C + (size_t)(row0 + r) * Nt + col0 + c) = v;
            if (H16) {
                // fp16 head-major: contiguous 4 halves = one 8B coalesced store
                uint2 u;
                u.x = packh2(v.x, v.y);
                u.y = packh2(v.z, v.w);
                *(uint2*)(H16 + (size_t)(row0 + r) * Nt + col0 + c) = u;
            }
            if (Ch) {
                uint2 uh, ul;
                uh.x = pack_hi2(v.x, v.y); uh.y = pack_hi2(v.z, v.w);
                ul.x = pack_lo2(v.x, v.y); ul.y = pack_lo2(v.z, v.w);
                *(uint2*)(Ch + (size_t)(row0 + r) * Nt + col0 + c) = uh;
                *(uint2*)(Cl + (size_t)(row0 + r) * Nt + col0 + c) = ul;
            }
        }
    }

    if (SCORES && tid < 128) {
        int r = tid;
        float s1 = 0.f, s2 = 0.f;
        const float* as = asrc + col0;
        const float* ad = adst + col0;
        const float* sp = stage + (size_t)r * 132;
#pragma unroll 8
        for (int c = 0; c < 128; c++) {
            float hv = sp[c];
            s1 += hv * as[c];
            s2 += hv * ad[c];
        }
        gss[(size_t)(row0 + r) * 4 + blockIdx.x] = s1;
        gsd[(size_t)(row0 + r) * 4 + blockIdx.x] = s2;
    }
}

// ---------------- weight pre-split; QKV packed per-layer [384, 128] ----------------
__global__ void split_weights(const float* __restrict__ gatW, const float* __restrict__ Wqkv,
                              const float* __restrict__ Wo, const float* __restrict__ Wff1,
                              const float* __restrict__ Wff2) {
    int idx = blockIdx.x * 256 + threadIdx.x;
    if (idx >= WTOT) return;
    float v;
    if (idx < OFF_QKV) {
        int i = idx >> 16, r = idx & 65535;
        int n = r >> 7, k = r & 127;
        v = gatW[(i << 16) + k * 512 + n];
    } else if (idx < OFF_WO) {
        int r0 = idx - OFF_QKV;
        int l = r0 / 49152;
        int rem = r0 - l * 49152;
        int n = rem >> 7, k = rem & 127;
        int s = n >> 7, nc = n & 127;
        v = Wqkv[((l * 3 + s) << 14) + k * 128 + nc];
    } else if (idx < OFF_FF1) {
        int r0 = idx - OFF_WO;
        int i = r0 >> 14, r = r0 & 16383;
        int n = r >> 7, k = r & 127;
        v = Wo[(i << 14) + k * 128 + n];
    } else if (idx < OFF_FF2) {
        int r0 = idx - OFF_FF1;
        int i = r0 >> 16, r = r0 & 65535;
        int n = r >> 7, k = r & 127;
        v = Wff1[(i << 16) + k * 512 + n];
    } else {
        int r0 = idx - OFF_FF2;
        int i = r0 >> 16, r = r0 & 65535;
        int n = r >> 9, k = r & 511;
        v = Wff2[(i << 16) + k * 128 + n];
    }
    __nv_bfloat16 h = __float2bfloat16(v);
    g_wh[idx] = h;
    g_wl[idx] = __float2bfloat16(v - __bfloat162float(h));
}

// ---------------- tiny precompute: gat0 score scalars + PE table (1 block) ----------------
__global__ void precompute(const float* __restrict__ W, const float* __restrict__ asrc,
                           const float* __restrict__ adst) {
    int tid = threadIdx.x;
    int wid = tid >> 5, lane = tid & 31;
    float a0s = 0.f, a1s = 0.f, a0d = 0.f, a1d = 0.f;
    for (int d = lane; d < 128; d += 32) {
        int c = wid * 128 + d;
        float w0 = W[c], w1 = W[512 + c], as = asrc[c], ad = adst[c];
        a0s += w0 * as; a1s += w1 * as; a0d += w0 * ad; a1d += w1 * ad;
    }
#pragma unroll
    for (int o = 16; o; o >>= 1) {
        a0s += __shfl_xor_sync(0xFFFFFFFFu, a0s, o);
        a1s += __shfl_xor_sync(0xFFFFFFFFu, a1s, o);
        a0d += __shfl_xor_sync(0xFFFFFFFFu, a0d, o);
        a1d += __shfl_xor_sync(0xFFFFFFFFu, a1d, o);
    }
    if (lane == 0) {
        g_c[wid] = a0s; g_c[4 + wid] = a1s; g_c[8 + wid] = a0d; g_c[12 + wid] = a1d;
    }
    for (int i = tid; i < Tt * Hh; i += 128) {
        int t = i >> 7, d = i & 127;
        float freq = expf(-(float)(d & ~1) * (9.210340371976184f / 128.f));
        float ang = (float)t * freq;
        g_pe[i] = (d & 1) ? cosf(ang) : sinf(ang);
    }
}

// ---------------- mask + self-loop init ----------------
__global__ void mask_init(const unsigned char* __restrict__ ego) {
    int idx = blockIdx.x * 256 + threadIdx.x;
    if (idx >= ROWS) return;
    int t = idx >> 10;
    int mm = idx & 1023;
    int b = mm >> 8;
    int n = mm & 255;
    unsigned char v = ego[(b * Tt + t) * 256 + n] ? 1 : 0;
    g_m[idx] = v;
    g_cnt[idx] = v ? 1 : 0;
    g_nbr[idx * MAXD] = (unsigned short)mm;
}

// ---------------- neighbor-list build (float4 per thread, one block per source row) ----------------
__global__ void build_nbr(const float* __restrict__ A) {
    int tj = blockIdx.x;
    if (!g_m[tj]) return;
    int t = tj >> 10;
    int j = tj & 1023;
    int i0 = threadIdx.x * 4;
    float4 a = *(const float4*)(A + (size_t)tj * 1024 + i0);
    float av[4] = {a.x, a.y, a.z, a.w};
#pragma unroll
    for (int e = 0; e < 4; e++) {
        int i = i0 + e;
        if (i == j) continue;
        int ti = (t << 10) + i;
        if (av[e] != 0.f && g_m[ti]) {
            int pos = atomicAdd(&g_cnt[ti], 1);
            if (pos < MAXD) g_nbr[(size_t)ti * MAXD + pos] = (unsigned short)j;
        }
    }
}

// ---------------- GAT layer-0: streaming projection (FIN=2), fp16 head-major + scalar scores ----------------
__global__ void gat0(const float* __restrict__ x, const float* __restrict__ W) {
    int idx = blockIdx.x * 256 + threadIdx.x;   // ROWS*512
    int row = idx >> 9;
    int c = idx & 511;         // head-major: hh*128 + d
    float x0 = x[row * 2], x1 = x[row * 2 + 1];
    g_hh[idx] = __float2half(x0 * W[c] + x1 * W[512 + c]);
    if (c < 8) {
        int hh = c & 3;
        int isd = c >> 2;      // 0: src, 1: dst
        float v = x0 * g_c[hh + isd * 8] + x1 * g_c[hh + 4 + isd * 8];
        if (isd == 0) g_ss[row * 4 + hh] = v;
        else g_sd[row * 4 + hh] = v;
    }
}

// ---------------- sparse segment-softmax + aggregation (fp16 head-major gather) ----------------
__global__ void gat_agg(const float* __restrict__ bias,
                        __nv_bfloat16* __restrict__ xh, __nv_bfloat16* __restrict__ xl) {
    int row = blockIdx.x;
    int tid = threadIdx.x;
    if (!g_m[row]) {
        xh[(size_t)row * 128 + tid] = __float2bfloat16(0.f);
        xl[(size_t)row * 128 + tid] = __float2bfloat16(0.f);
        return;
    }
    int t = row >> 10;

    __shared__ unsigned short nb[MAXD];
    __shared__ float w[4][MAXD];

    int cnt = g_cnt[row];
    if (cnt > MAXD) cnt = MAXD;
    if (tid < cnt) nb[tid] = g_nbr[(size_t)row * MAXD + tid];

    if (tid < cnt) {
        int jr = (t << 10) + nb[tid];
#pragma unroll
        for (int hh = 0; hh < 4; hh++) {
            float z = g_sd[row * 4 + hh] + g_ss[jr * 4 + hh];
            w[hh][tid] = (z > 0.f) ? z : 0.2f * z;
        }
    } else {
#pragma unroll
        for (int hh = 0; hh < 4; hh++) w[hh][tid] = -INFINITY;
    }
    __syncthreads();

    {
        int wh = tid >> 5, lane = tid & 31;
        float v0 = w[wh][lane], v1 = w[wh][lane + 32], v2 = w[wh][lane + 64], v3 = w[wh][lane + 96];
        float mx = fmaxf(fmaxf(v0, v1), fmaxf(v2, v3));
#pragma unroll
        for (int o = 16; o; o >>= 1) mx = fmaxf(mx, __shfl_xor_sync(0xFFFFFFFFu, mx, o));
        float e0 = expf(v0 - mx), e1 = expf(v1 - mx), e2 = expf(v2 - mx), e3 = expf(v3 - mx);
        float s = e0 + e1 + e2 + e3;
#pragma unroll
        for (int o = 16; o; o >>= 1) s += __shfl_xor_sync(0xFFFFFFFFu, s, o);
        float inv = 1.f / s;
        w[wh][lane] = e0 * inv;
        w[wh][lane + 32] = e1 * inv;
        w[wh][lane + 64] = e2 * inv;
        w[wh][lane + 96] = e3 * inv;
    }
    __syncthreads();

    // fp16 head-major gather: 4 LDG.U16 per neighbor per thread (half the bytes of fp32)
    float acc0 = 0.f, acc1 = 0.f, acc2 = 0.f, acc3 = 0.f;
    const __half* hb = g_hh + (((size_t)(t << 10)) << 9) + tid;
    int j = 0;
    for (; j + 4 <= cnt; j += 4) {
        const __half* p0 = hb + ((size_t)nb[j] << 9);
        const __half* p1 = hb + ((size_t)nb[j + 1] << 9);
        const __half* p2 = hb + ((size_t)nb[j + 2] << 9);
        const __half* p3 = hb + ((size_t)nb[j + 3] << 9);
#pragma unroll
        for (int hh = 0; hh < 4; hh++) {
            acc0 += w[hh][j] * __half2float(p0[hh << 7]);
            acc1 += w[hh][j + 1] * __half2float(p1[hh << 7]);
            acc2 += w[hh][j + 2] * __half2float(p2[hh << 7]);
            acc3 += w[hh][j + 3] * __half2float(p3[hh << 7]);
        }
    }
    for (; j < cnt; j++) {
        const __half* p0 = hb + ((size_t)nb[j] << 9);
#pragma unroll
        for (int hh = 0; hh < 4; hh++) acc0 += w[hh][j] * __half2float(p0[hh << 7]);
    }
    float o = (acc0 + acc1 + acc2 + acc3) * 0.25f + bias[tid];
    o = fmaxf(o, 0.f);
    __nv_bfloat16 hi = __float2bfloat16(o);
    xh[(size_t)row * 128 + tid] = hi;
    xl[(size_t)row * 128 + tid] = __float2bfloat16(o - __bfloat162float(hi));
}

// ---------------- transpose to sequence layout + PE (table lookup) ----------------
__global__ void to_seq(const __nv_bfloat16* __restrict__ xh, const __nv_bfloat16* __restrict__ xl) {
    int idx = blockIdx.x * 256 + threadIdx.x;
    int row = idx >> 7;
    int d = idx & 127;
    int t = row >> 10;
    int mm = row & 1023;
    float x = __bfloat162float(xh[idx]) + __bfloat162float(xl[idx]);
    float v = x + g_pe[t * 128 + d];
    size_t sidx = ((size_t)mm * Tt + t) * Hh + d;
    g_xs[sidx] = v;
    __nv_bfloat16 hi = __float2bfloat16(v);
    g_xsh[sidx] = hi;
    g_xsl[sidx] = __float2bfloat16(v - __bfloat162float(hi));
}

// ---------------- per-sequence attention (T=16, 4 heads of 32), packed QKV ----------------
__global__ void attn_kernel(const float* __restrict__ QKV,
                            __nv_bfloat16* __restrict__ Oh, __nv_bfloat16* __restrict__ Ol) {
    __shared__ float sq[16][128], sk[16][128], sv[16][128];
    int m = blockIdx.x;
    int tid = threadIdx.x;
    size_t base = (size_t)m * 16 * 384;
    for (int idx = tid; idx < 2048; idx += 128) {
        int t = idx >> 7, d = idx & 127;
        size_t p = base + (size_t)t * 384 + d;
        sq[t][d] = QKV[p];
        sk[t][d] = QKV[p + 128];
        sv[t][d] = QKV[p + 256];
    }
    __syncthreads();
    int h = tid >> 5;
    int tq = (tid >> 1) & 15;
    int half = tid & 1;
    const float scale = 0.17677669529663687f;
    float sc[16];
    float mx = -1e30f;
#pragma unroll
    for (int tk = 0; tk < 16; tk++) {
        float s = 0.f;
#pragma unroll
        for (int dd = 0; dd < 16; dd++) {
            int d = half * 16 + dd;
            s += sq[tq][h * 32 + d] * sk[tk][h * 32 + d];
        }
        s += __shfl_xor_sync(0xFFFFFFFFu, s, 1);
        s *= scale;
        sc[tk] = s;
        mx = fmaxf(mx, s);
    }
    float sum = 0.f;
#pragma unroll
    for (int tk = 0; tk < 16; tk++) { sc[tk] = expf(sc[tk] - mx); sum += sc[tk]; }
    float inv = 1.f / sum;
    size_t ob = (size_t)m * 16 * 128 + (size_t)tq * 128 + h * 32 + half * 16;
#pragma unroll
    for (int dd = 0; dd < 16; dd++) {
        int d = half * 16 + dd;
        float o = 0.f;
#pragma unroll
        for (int tk = 0; tk < 16; tk++) o += sc[tk] * sv[tk][h * 32 + d];
        o *= inv;
        __nv_bfloat16 hi = __float2bfloat16(o);
        Oh[ob + dd] = hi;
        Ol[ob + dd] = __float2bfloat16(o - __bfloat162float(hi));
    }
}

// ---------------- launcher ----------------
extern "C" void kernel_launch(void* const* d_in, const int* in_sizes, int n_in,
                              void* d_out, int out_size) {
    const unsigned char* ego = (const unsigned char*)d_in[0];
    const float* positions  = (const float*)d_in[1];
    const float* adjacency  = (const float*)d_in[2];
    const float* gat1_W     = (const float*)d_in[3];
    const float* gat1_asrc  = (const float*)d_in[4];
    const float* gat1_adst  = (const float*)d_in[5];
    const float* gat1_b     = (const float*)d_in[6];
    const float* gatW       = (const float*)d_in[7];
    const float* gat_asrc   = (const float*)d_in[8];
    const float* gat_adst   = (const float*)d_in[9];
    const float* gat_b      = (const float*)d_in[10];
    const float* Wqkv       = (const float*)d_in[11];
    const float* bqkv       = (const float*)d_in[12];
    const float* Wo         = (const float*)d_in[13];
    const float* bo         = (const float*)d_in[14];
    const float* ln1_s      = (const float*)d_in[15];
    const float* ln1_b      = (const float*)d_in[16];
    const float* ln2_s      = (const float*)d_in[17];
    const float* ln2_b      = (const float*)d_in[18];
    const float* Wff1       = (const float*)d_in[19];
    const float* bff1       = (const float*)d_in[20];
    const float* Wff2       = (const float*)d_in[21];
    const float* bff2       = (const float*)d_in[22];
    float* out = (float*)d_out;

    float *h, *xs, *ss, *sd;
    __half* hh;
    __nv_bfloat16 *wh, *wl, *xah, *xal, *xbh, *xbl, *xsh, *xsl, *atth, *attl, *ffh, *ffl;
    cudaGetSymbolAddress((void**)&h,    g_h);
    cudaGetSymbolAddress((void**)&hh,   g_hh);
    cudaGetSymbolAddress((void**)&xs,   g_xs);
    cudaGetSymbolAddress((void**)&ss,   g_ss);
    cudaGetSymbolAddress((void**)&sd,   g_sd);
    cudaGetSymbolAddress((void**)&wh,   g_wh);
    cudaGetSymbolAddress((void**)&wl,   g_wl);
    cudaGetSymbolAddress((void**)&xah,  g_xah);
    cudaGetSymbolAddress((void**)&xal,  g_xal);
    cudaGetSymbolAddress((void**)&xbh,  g_xbh);
    cudaGetSymbolAddress((void**)&xbl,  g_xbl);
    cudaGetSymbolAddress((void**)&xsh,  g_xsh);
    cudaGetSymbolAddress((void**)&xsl,  g_xsl);
    cudaGetSymbolAddress((void**)&atth, g_atth);
    cudaGetSymbolAddress((void**)&attl, g_attl);
    cudaGetSymbolAddress((void**)&ffh,  g_ffh);
    cudaGetSymbolAddress((void**)&ffl,  g_ffl);

    cudaFuncSetAttribute(gemm_tc<0, false, true,  false>, cudaFuncAttributeMaxDynamicSharedMemorySize, GSM_TOTAL);
    cudaFuncSetAttribute(gemm_tc<0, false, false, false>, cudaFuncAttributeMaxDynamicSharedMemorySize, GSM_TOTAL);
    cudaFuncSetAttribute(gemm_tc<0, true,  false, true >, cudaFuncAttributeMaxDynamicSharedMemorySize, GSM_TOTAL);
    cudaFuncSetAttribute(gemm_tc<1, false, false, false>, cudaFuncAttributeMaxDynamicSharedMemorySize, GSM_TOTAL);

    split_weights<<<(WTOT + 255) / 256, 256>>>(gatW, Wqkv, Wo, Wff1, Wff2);
    precompute<<<1, 128>>>(gat1_W, gat1_asrc, gat1_adst);
    mask_init<<<ROWS / 256, 256>>>(ego);
    build_nbr<<<ROWS, 256>>>(adjacency);

    // GAT layer 0 (FIN=2)
    gat0<<<ROWS * 512 / 256, 256>>>(positions, gat1_W);
    gat_agg<<<ROWS, 128>>>(gat1_b, xah, xal);

    // GAT layers 1..5
    __nv_bfloat16 *curh = xah, *curl = xal, *nxth = xbh, *nxtl = xbl;
    for (int i = 0; i < 5; i++) {
        dim3 gp(4, ROWS / 128);
        gemm_tc<0, false, true, false><<<gp, 256, GSM_TOTAL>>>(
            curh, curl, wh + OFF_GAT + (size_t)i * 65536, wl + OFF_GAT + (size_t)i * 65536,
            nullptr, nullptr, nullptr, nullptr, nullptr, hh,
            gat_asrc + i * 512, gat_adst + i * 512, ss, sd, nullptr, nullptr, 512, 128);
        gat_agg<<<ROWS, 128>>>(gat_b + i * 128, nxth, nxtl);
        __nv_bfloat16* t0 = curh; curh = nxth; nxth = t0;
        __nv_bfloat16* t1 = curl; curl = nxtl; nxtl = t1;
    }

    to_seq<<<ROWS * 128 / 256, 256>>>(curh, curl);

    dim3 g1(1, ROWS / 128);
    dim3 g2(4, ROWS / 128);
    dim3 gq(3, ROWS / 128);
    for (int l = 0; l < NL_TR; l++) {
        size_t oq = OFF_QKV + (size_t)l * 49152;
        gemm_tc<0, false, false, false><<<gq, 256, GSM_TOTAL>>>(
            xsh, xsl, wh + oq, wl + oq,
            bqkv + l * 384, nullptr, h, nullptr, nullptr, nullptr,
            nullptr, nullptr, nullptr, nullptr, nullptr, nullptr, 384, 128);
        attn_kernel<<<Mm, 128>>>(h, atth, attl);
        size_t owo = OFF_WO + (size_t)l * 16384;
        gemm_tc<0, true, false, true><<<g1, 256, GSM_TOTAL>>>(
            atth, attl, wh + owo, wl + owo,
            bo + l * 128, xs, xs, xsh, xsl, nullptr,
            nullptr, nullptr, nullptr, nullptr,
            ln1_s + l * 128, ln1_b + l * 128, 128, 128);
        size_t of1 = OFF_FF1 + (size_t)l * 65536;
        gemm_tc<1, false, false, false><<<g2, 256, GSM_TOTAL>>>(
            xsh, xsl, wh + of1, wl + of1,
            bff1 + l * 512, nullptr, nullptr, ffh, ffl, nullptr,
            nullptr, nullptr, nullptr, nullptr, nullptr, nullptr, 512, 128);
        size_t of2 = OFF_FF2 + (size_t)l * 65536;
        if (l == NL_TR - 1) {
            gemm_tc<0, true, false, true><<<g1, 256, GSM_TOTAL>>>(
                ffh, ffl, wh + of2, wl + of2,
                bff2 + l * 128, xs, out, nullptr, nullptr, nullptr,
                nullptr, nullptr, nullptr, nullptr,
                ln2_s + l * 128, ln2_b + l * 128, 128, 512);
        } else {
            gemm_tc<0, true, false, true><<<g1, 256, GSM_TOTAL>>>(
                ffh, ffl, wh + of2, wl + of2,
                bff2 + l * 128, xs, xs, xsh, xsl, nullptr,
                nullptr, nullptr, nullptr, nullptr,
                ln2_s + l * 128, ln2_b + l * 128, 128, 512);
        }
    }
}

// round 10
// speedup vs baseline: 1.3929x; 1.1558x over previous
#include <cuda_runtime.h>
#include <cuda_bf16.h>
#include <cuda_fp16.h>
#include <math.h>

// Problem dims
#define Tt 16
#define Mm 1024
#define Hh 128
#define ROWS 16384
#define MAXD 128
#define NL_TR 5

// ---------------- scratch (device globals; no allocations) ----------------
__device__ float g_h[ROWS * 384];          // transformer QKV fp32
__device__ __half g_hh[ROWS * 512];        // GAT projections fp16, head-major
__device__ float g_ss[ROWS * 4];
__device__ float g_sd[ROWS * 4];
__device__ unsigned char g_m[ROWS];
__device__ int g_cnt[ROWS];
__device__ unsigned short g_nbr[ROWS * MAXD];
__device__ float g_xs[ROWS * Hh];
__device__ float g_c[16];
__device__ float g_pe[Tt * Hh];
// planar fp16 hi/lo activations (GEMM A operands)
__device__ __half g_xah[ROWS * Hh], g_xal[ROWS * Hh];
__device__ __half g_xbh[ROWS * Hh], g_xbl[ROWS * Hh];
__device__ __half g_xsh[ROWS * Hh], g_xsl[ROWS * Hh];
__device__ __half g_atth[ROWS * Hh], g_attl[ROWS * Hh];
__device__ __half g_ffh[ROWS * 512], g_ffl[ROWS * 512];

#define WTOT 1310720
#define OFF_GAT 0
#define OFF_QKV 327680
#define OFF_WO  573440
#define OFF_FF1 655360
#define OFF_FF2 983040
__device__ __half g_w16[WTOT];             // weights, single fp16, [N,K]

__device__ __forceinline__ unsigned smem_u32(const void* p) {
    unsigned a;
    asm("{ .reg .u64 t; cvta.to.shared.u64 t, %1; cvt.u32.u64 %0, t; }" : "=r"(a) : "l"(p));
    return a;
}
__device__ __forceinline__ void ldmat4(unsigned& r0, unsigned& r1, unsigned& r2, unsigned& r3, unsigned addr) {
    asm volatile("ldmatrix.sync.aligned.m8n8.x4.shared.b16 {%0,%1,%2,%3}, [%4];"
        : "=r"(r0), "=r"(r1), "=r"(r2), "=r"(r3) : "r"(addr));
}
__device__ __forceinline__ void mma16816(float* c, unsigned a0, unsigned a1, unsigned a2, unsigned a3,
                                         unsigned b0, unsigned b1) {
    asm volatile("mma.sync.aligned.m16n8k16.row.col.f32.f16.f16.f32 "
        "{%0,%1,%2,%3}, {%4,%5,%6,%7}, {%8,%9}, {%0,%1,%2,%3};"
        : "+f"(c[0]), "+f"(c[1]), "+f"(c[2]), "+f"(c[3])
        : "r"(a0), "r"(a1), "r"(a2), "r"(a3), "r"(b0), "r"(b1));
}
__device__ __forceinline__ void cpa16(unsigned dst, const void* src) {
    asm volatile("cp.async.ca.shared.global [%0], [%1], 16;" :: "r"(dst), "l"(src));
}
#define CPA_COMMIT() asm volatile("cp.async.commit_group;" ::: "memory")
#define CPA_WAIT1() asm volatile("cp.async.wait_group 1;" ::: "memory")
#define CPA_WAIT0() asm volatile("cp.async.wait_group 0;" ::: "memory")

__device__ __forceinline__ unsigned packh_hi2(float a, float b) {
    __half2 h = __floats2half2_rn(a, b);
    return *(unsigned*)&h;
}
__device__ __forceinline__ unsigned packh_lo2(float a, float b) {
    __half ha = __float2half_rn(a), hb = __float2half_rn(b);
    __half2 l = __floats2half2_rn(a - __half2float(ha), b - __half2float(hb));
    return *(unsigned*)&l;
}

// SMEM: 2 stages x 3 planes (Ahi, Alo, B), each 128 rows x 32 fp16 (80B stride)
#define TROW 80
#define PBUF (128 * TROW)       // 10240
#define STAGE (3 * PBUF)        // 30720
#define P_AHI 0
#define P_ALO PBUF
#define P_B   (2 * PBUF)
#define GSM_TOTAL 67584         // epilogue stage 128*132*4; pipeline 2*STAGE=61440 fits

// ---------------- HMMA GEMM: A fp16 hi/lo planar, B fp16 single; 2-MMA scheme ----------------
template <int ACT, bool RESID, bool SCORES, bool LNORM>
__global__ void __launch_bounds__(256, 2)
gemm_tc(const __half* __restrict__ Ah, const __half* __restrict__ Al,
        const __half* __restrict__ B16,
        const float* __restrict__ bias, const float* __restrict__ Rr,
        float* __restrict__ C, __half* __restrict__ Ch, __half* __restrict__ Cl,
        __half* __restrict__ H16,
        const float* __restrict__ asrc, const float* __restrict__ adst,
        float* __restrict__ gss, float* __restrict__ gsd,
        const float* __restrict__ ls, const float* __restrict__ lb, int Nt, int Kt) {
    extern __shared__ char smem[];
    const unsigned sb = smem_u32(smem);
    const int tid = threadIdx.x;
    const int wid = tid >> 5, lane = tid & 31;
    const int wr = wid >> 1, wc = wid & 1;
    const int row0 = blockIdx.y * 128;
    const int col0 = blockIdx.x * 128;

    float acc[2][8][4];
#pragma unroll
    for (int mt = 0; mt < 2; mt++)
#pragma unroll
        for (int nt = 0; nt < 8; nt++)
#pragma unroll
            for (int e = 0; e < 4; e++) acc[mt][nt][e] = 0.f;

    const int ltile = lane >> 3, lrow = lane & 7;
    const int nch = Kt >> 5;

#define LOAD_CHUNK(cidx, s) do { \
    unsigned base = sb + (s) * STAGE; \
    _Pragma("unroll") \
    for (int j = 0; j < 2; j++) { \
        int i = tid + j * 256; \
        int rr = i >> 2, qq = i & 3; \
        unsigned off = (unsigned)(rr * TROW + qq * 16); \
        size_t ga = (size_t)(row0 + rr) * Kt + (cidx) * 32 + qq * 8; \
        size_t gb = (size_t)(col0 + rr) * Kt + (cidx) * 32 + qq * 8; \
        cpa16(base + P_AHI + off, Ah + ga); \
        cpa16(base + P_ALO + off, Al + ga); \
        cpa16(base + P_B + off, B16 + gb); \
    } \
} while (0)

    LOAD_CHUNK(0, 0);
    CPA_COMMIT();

    for (int c = 0; c < nch; c++) {
        if (c + 1 < nch) {
            LOAD_CHUNK(c + 1, (c + 1) & 1);
            CPA_COMMIT();
            CPA_WAIT1();
        } else {
            CPA_WAIT0();
        }
        __syncthreads();
        unsigned base = sb + (c & 1) * STAGE;
#pragma unroll
        for (int ks = 0; ks < 2; ks++) {
            unsigned ah[2][4], al[2][4];
#pragma unroll
            for (int mt = 0; mt < 2; mt++) {
                int row = wr * 32 + mt * 16 + lrow + (ltile & 1) * 8;
                int kcol = ks * 16 + (ltile >> 1) * 8;
                unsigned off = (unsigned)(row * TROW + kcol * 2);
                ldmat4(ah[mt][0], ah[mt][1], ah[mt][2], ah[mt][3], base + P_AHI + off);
                ldmat4(al[mt][0], al[mt][1], al[mt][2], al[mt][3], base + P_ALO + off);
            }
#pragma unroll
            for (int g = 0; g < 4; g++) {
                int n = wc * 64 + g * 16 + lrow + (ltile >> 1) * 8;
                int kcol = ks * 16 + (ltile & 1) * 8;
                unsigned off = (unsigned)(n * TROW + kcol * 2);
                unsigned bh[4];
                ldmat4(bh[0], bh[1], bh[2], bh[3], base + P_B + off);
#pragma unroll
                for (int mt = 0; mt < 2; mt++)
#pragma unroll
                    for (int half = 0; half < 2; half++) {
                        float* cc = acc[mt][g * 2 + half];
                        mma16816(cc, ah[mt][0], ah[mt][1], ah[mt][2], ah[mt][3],
                                 bh[half * 2], bh[half * 2 + 1]);
                        mma16816(cc, al[mt][0], al[mt][1], al[mt][2], al[mt][3],
                                 bh[half * 2], bh[half * 2 + 1]);
                    }
            }
        }
        __syncthreads();
    }
#undef LOAD_CHUNK

    float* stage = (float*)smem;
#pragma unroll
    for (int mt = 0; mt < 2; mt++)
#pragma unroll
        for (int nt = 0; nt < 8; nt++) {
            int row = wr * 32 + mt * 16 + (lane >> 2);
            int col = wc * 64 + nt * 8 + (lane & 3) * 2;
            float2 v0 = make_float2(acc[mt][nt][0], acc[mt][nt][1]);
            float2 v1 = make_float2(acc[mt][nt][2], acc[mt][nt][3]);
            *(float2*)(stage + (size_t)row * 132 + col) = v0;
            *(float2*)(stage + (size_t)(row + 8) * 132 + col) = v1;
        }
    __syncthreads();

    if (LNORM) {
        const int c = lane * 4;
        float4 bb = *(const float4*)(bias + c);
        float4 sv = *(const float4*)(ls + c);
        float4 bv = *(const float4*)(lb + c);
#pragma unroll 4
        for (int rr = 0; rr < 16; rr++) {
            int r = wid * 16 + rr;
            float4 v = *(float4*)(stage + (size_t)r * 132 + c);
            float4 res = *(const float4*)(Rr + (size_t)(row0 + r) * 128 + c);
            v.x += bb.x + res.x; v.y += bb.y + res.y;
            v.z += bb.z + res.z; v.w += bb.w + res.w;
            float s = v.x + v.y + v.z + v.w;
#pragma unroll
            for (int o = 16; o; o >>= 1) s += __shfl_xor_sync(0xFFFFFFFFu, s, o);
            float mean = s * (1.f / 128.f);
            float dx = v.x - mean, dy = v.y - mean, dz = v.z - mean, dw = v.w - mean;
            float qq = dx * dx + dy * dy + dz * dz + dw * dw;
#pragma unroll
            for (int o = 16; o; o >>= 1) qq += __shfl_xor_sync(0xFFFFFFFFu, qq, o);
            float rstd = rsqrtf(qq * (1.f / 128.f) + 1e-5f);
            float4 ov;
            ov.x = dx * rstd * sv.x + bv.x;
            ov.y = dy * rstd * sv.y + bv.y;
            ov.z = dz * rstd * sv.z + bv.z;
            ov.w = dw * rstd * sv.w + bv.w;
            if (C) *(float4*)(C + (size_t)(row0 + r) * 128 + c) = ov;
            if (Ch) {
                uint2 uh, ul;
                uh.x = packh_hi2(ov.x, ov.y); uh.y = packh_hi2(ov.z, ov.w);
                ul.x = packh_lo2(ov.x, ov.y); ul.y = packh_lo2(ov.z, ov.w);
                *(uint2*)(Ch + (size_t)(row0 + r) * 128 + c) = uh;
                *(uint2*)(Cl + (size_t)(row0 + r) * 128 + c) = ul;
            }
        }
    } else {
        for (int i = tid; i < 128 * 32; i += 256) {
            int r = i >> 5, q = i & 31;
            int c = q * 4;
            float4 v = *(float4*)(stage + (size_t)r * 132 + c);
            if (bias) {
                v.x += bias[col0 + c];
                v.y += bias[col0 + c + 1];
                v.z += bias[col0 + c + 2];
                v.w += bias[col0 + c + 3];
            }
            if (RESID) {
                float4 rr = *(const float4*)(Rr + (size_t)(row0 + r) * Nt + col0 + c);
                v.x += rr.x; v.y += rr.y; v.z += rr.z; v.w += rr.w;
            }
            if (ACT == 1) {
                v.x = fmaxf(v.x, 0.f); v.y = fmaxf(v.y, 0.f);
                v.z = fmaxf(v.z, 0.f); v.w = fmaxf(v.w, 0.f);
            }
            if (C) *(float4*)(C + (size_t)(row0 + r) * Nt + col0 + c) = v;
            if (H16) {
                uint2 u;
                u.x = packh_hi2(v.x, v.y);
                u.y = packh_hi2(v.z, v.w);
                *(uint2*)(H16 + (size_t)(row0 + r) * Nt + col0 + c) = u;
            }
            if (Ch) {
                uint2 uh, ul;
                uh.x = packh_hi2(v.x, v.y); uh.y = packh_hi2(v.z, v.w);
                ul.x = packh_lo2(v.x, v.y); ul.y = packh_lo2(v.z, v.w);
                *(uint2*)(Ch + (size_t)(row0 + r) * Nt + col0 + c) = uh;
                *(uint2*)(Cl + (size_t)(row0 + r) * Nt + col0 + c) = ul;
            }
        }
    }

    if (SCORES && tid < 128) {
        int r = tid;
        float s1 = 0.f, s2 = 0.f;
        const float* as = asrc + col0;
        const float* ad = adst + col0;
        const float* sp = stage + (size_t)r * 132;
#pragma unroll 8
        for (int c = 0; c < 128; c++) {
            float hv = sp[c];
            s1 += hv * as[c];
            s2 += hv * ad[c];
        }
        gss[(size_t)(row0 + r) * 4 + blockIdx.x] = s1;
        gsd[(size_t)(row0 + r) * 4 + blockIdx.x] = s2;
    }
}

// ---------------- weight conversion to fp16 [N,K]; QKV packed per-layer [384, 128] ----------------
__global__ void split_weights(const float* __restrict__ gatW, const float* __restrict__ Wqkv,
                              const float* __restrict__ Wo, const float* __restrict__ Wff1,
                              const float* __restrict__ Wff2) {
    int idx = blockIdx.x * 256 + threadIdx.x;
    if (idx >= WTOT) return;
    float v;
    if (idx < OFF_QKV) {
        int i = idx >> 16, r = idx & 65535;
        int n = r >> 7, k = r & 127;
        v = gatW[(i << 16) + k * 512 + n];
    } else if (idx < OFF_WO) {
        int r0 = idx - OFF_QKV;
        int l = r0 / 49152;
        int rem = r0 - l * 49152;
        int n = rem >> 7, k = rem & 127;
        int s = n >> 7, nc = n & 127;
        v = Wqkv[((l * 3 + s) << 14) + k * 128 + nc];
    } else if (idx < OFF_FF1) {
        int r0 = idx - OFF_WO;
        int i = r0 >> 14, r = r0 & 16383;
        int n = r >> 7, k = r & 127;
        v = Wo[(i << 14) + k * 128 + n];
    } else if (idx < OFF_FF2) {
        int r0 = idx - OFF_FF1;
        int i = r0 >> 16, r = r0 & 65535;
        int n = r >> 7, k = r & 127;
        v = Wff1[(i << 16) + k * 512 + n];
    } else {
        int r0 = idx - OFF_FF2;
        int i = r0 >> 16, r = r0 & 65535;
        int n = r >> 9, k = r & 511;
        v = Wff2[(i << 16) + k * 128 + n];
    }
    g_w16[idx] = __float2half_rn(v);
}

// ---------------- tiny precompute: gat0 score scalars + PE table ----------------
__global__ void precompute(const float* __restrict__ W, const float* __restrict__ asrc,
                           const float* __restrict__ adst) {
    int tid = threadIdx.x;
    int wid = tid >> 5, lane = tid & 31;
    float a0s = 0.f, a1s = 0.f, a0d = 0.f, a1d = 0.f;
    for (int d = lane; d < 128; d += 32) {
        int c = wid * 128 + d;
        float w0 = W[c], w1 = W[512 + c], as = asrc[c], ad = adst[c];
        a0s += w0 * as; a1s += w1 * as; a0d += w0 * ad; a1d += w1 * ad;
    }
#pragma unroll
    for (int o = 16; o; o >>= 1) {
        a0s += __shfl_xor_sync(0xFFFFFFFFu, a0s, o);
        a1s += __shfl_xor_sync(0xFFFFFFFFu, a1s, o);
        a0d += __shfl_xor_sync(0xFFFFFFFFu, a0d, o);
        a1d += __shfl_xor_sync(0xFFFFFFFFu, a1d, o);
    }
    if (lane == 0) {
        g_c[wid] = a0s; g_c[4 + wid] = a1s; g_c[8 + wid] = a0d; g_c[12 + wid] = a1d;
    }
    for (int i = tid; i < Tt * Hh; i += 128) {
        int t = i >> 7, d = i & 127;
        float freq = expf(-(float)(d & ~1) * (9.210340371976184f / 128.f));
        float ang = (float)t * freq;
        g_pe[i] = (d & 1) ? cosf(ang) : sinf(ang);
    }
}

// ---------------- mask + self-loop init ----------------
__global__ void mask_init(const unsigned char* __restrict__ ego) {
    int idx = blockIdx.x * 256 + threadIdx.x;
    if (idx >= ROWS) return;
    int t = idx >> 10;
    int mm = idx & 1023;
    int b = mm >> 8;
    int n = mm & 255;
    unsigned char v = ego[(b * Tt + t) * 256 + n] ? 1 : 0;
    g_m[idx] = v;
    g_cnt[idx] = v ? 1 : 0;
    g_nbr[idx * MAXD] = (unsigned short)mm;
}

// ---------------- neighbor-list build (float4 per thread) ----------------
__global__ void build_nbr(const float* __restrict__ A) {
    int tj = blockIdx.x;
    if (!g_m[tj]) return;
    int t = tj >> 10;
    int j = tj & 1023;
    int i0 = threadIdx.x * 4;
    float4 a = *(const float4*)(A + (size_t)tj * 1024 + i0);
    float av[4] = {a.x, a.y, a.z, a.w};
#pragma unroll
    for (int e = 0; e < 4; e++) {
        int i = i0 + e;
        if (i == j) continue;
        int ti = (t << 10) + i;
        if (av[e] != 0.f && g_m[ti]) {
            int pos = atomicAdd(&g_cnt[ti], 1);
            if (pos < MAXD) g_nbr[(size_t)ti * MAXD + pos] = (unsigned short)j;
        }
    }
}

// ---------------- GAT layer-0: streaming projection + scalar scores ----------------
__global__ void gat0(const float* __restrict__ x, const float* __restrict__ W) {
    int idx = blockIdx.x * 256 + threadIdx.x;   // ROWS*512
    int row = idx >> 9;
    int c = idx & 511;
    float x0 = x[row * 2], x1 = x[row * 2 + 1];
    g_hh[idx] = __float2half(x0 * W[c] + x1 * W[512 + c]);
    if (c < 8) {
        int hh = c & 3;
        int isd = c >> 2;
        float v = x0 * g_c[hh + isd * 8] + x1 * g_c[hh + 4 + isd * 8];
        if (isd == 0) g_ss[row * 4 + hh] = v;
        else g_sd[row * 4 + hh] = v;
    }
}

// ---------------- sparse segment-softmax + aggregation (fp16 gather) ----------------
__global__ void gat_agg(const float* __restrict__ bias,
                        __half* __restrict__ xh, __half* __restrict__ xl) {
    int row = blockIdx.x;
    int tid = threadIdx.x;
    if (!g_m[row]) {
        xh[(size_t)row * 128 + tid] = __float2half(0.f);
        xl[(size_t)row * 128 + tid] = __float2half(0.f);
        return;
    }
    int t = row >> 10;

    __shared__ unsigned short nb[MAXD];
    __shared__ float w[4][MAXD];

    int cnt = g_cnt[row];
    if (cnt > MAXD) cnt = MAXD;
    if (tid < cnt) nb[tid] = g_nbr[(size_t)row * MAXD + tid];

    if (tid < cnt) {
        int jr = (t << 10) + nb[tid];
#pragma unroll
        for (int hh = 0; hh < 4; hh++) {
            float z = g_sd[row * 4 + hh] + g_ss[jr * 4 + hh];
            w[hh][tid] = (z > 0.f) ? z : 0.2f * z;
        }
    } else {
#pragma unroll
        for (int hh = 0; hh < 4; hh++) w[hh][tid] = -INFINITY;
    }
    __syncthreads();

    {
        int wh = tid >> 5, lane = tid & 31;
        float v0 = w[wh][lane], v1 = w[wh][lane + 32], v2 = w[wh][lane + 64], v3 = w[wh][lane + 96];
        float mx = fmaxf(fmaxf(v0, v1), fmaxf(v2, v3));
#pragma unroll
        for (int o = 16; o; o >>= 1) mx = fmaxf(mx, __shfl_xor_sync(0xFFFFFFFFu, mx, o));
        float e0 = expf(v0 - mx), e1 = expf(v1 - mx), e2 = expf(v2 - mx), e3 = expf(v3 - mx);
        float s = e0 + e1 + e2 + e3;
#pragma unroll
        for (int o = 16; o; o >>= 1) s += __shfl_xor_sync(0xFFFFFFFFu, s, o);
        float inv = 1.f / s;
        w[wh][lane] = e0 * inv;
        w[wh][lane + 32] = e1 * inv;
        w[wh][lane + 64] = e2 * inv;
        w[wh][lane + 96] = e3 * inv;
    }
    __syncthreads();

    float acc0 = 0.f, acc1 = 0.f, acc2 = 0.f, acc3 = 0.f;
    const __half* hb = g_hh + (((size_t)(t << 10)) << 9) + tid;
    int j = 0;
    for (; j + 4 <= cnt; j += 4) {
        const __half* p0 = hb + ((size_t)nb[j] << 9);
        const __half* p1 = hb + ((size_t)nb[j + 1] << 9);
        const __half* p2 = hb + ((size_t)nb[j + 2] << 9);
        const __half* p3 = hb + ((size_t)nb[j + 3] << 9);
#pragma unroll
        for (int hh = 0; hh < 4; hh++) {
            acc0 += w[hh][j] * __half2float(p0[hh << 7]);
            acc1 += w[hh][j + 1] * __half2float(p1[hh << 7]);
            acc2 += w[hh][j + 2] * __half2float(p2[hh << 7]);
            acc3 += w[hh][j + 3] * __half2float(p3[hh << 7]);
        }
    }
    for (; j < cnt; j++) {
        const __half* p0 = hb + ((size_t)nb[j] << 9);
#pragma unroll
        for (int hh = 0; hh < 4; hh++) acc0 += w[hh][j] * __half2float(p0[hh << 7]);
    }
    float o = (acc0 + acc1 + acc2 + acc3) * 0.25f + bias[tid];
    o = fmaxf(o, 0.f);
    __half hi = __float2half_rn(o);
    xh[(size_t)row * 128 + tid] = hi;
    xl[(size_t)row * 128 + tid] = __float2half_rn(o - __half2float(hi));
}

// ---------------- transpose to sequence layout + PE ----------------
__global__ void to_seq(const __half* __restrict__ xh, const __half* __restrict__ xl) {
    int idx = blockIdx.x * 256 + threadIdx.x;
    int row = idx >> 7;
    int d = idx & 127;
    int t = row >> 10;
    int mm = row & 1023;
    float x = __half2float(xh[idx]) + __half2float(xl[idx]);
    float v = x + g_pe[t * 128 + d];
    size_t sidx = ((size_t)mm * Tt + t) * Hh + d;
    g_xs[sidx] = v;
    __half hi = __float2half_rn(v);
    g_xsh[sidx] = hi;
    g_xsl[sidx] = __float2half_rn(v - __half2float(hi));
}

// ---------------- per-sequence attention (T=16, 4 heads of 32) ----------------
__global__ void attn_kernel(const float* __restrict__ QKV,
                            __half* __restrict__ Oh, __half* __restrict__ Ol) {
    __shared__ float sq[16][128], sk[16][128], sv[16][128];
    int m = blockIdx.x;
    int tid = threadIdx.x;
    size_t base = (size_t)m * 16 * 384;
    for (int idx = tid; idx < 2048; idx += 128) {
        int t = idx >> 7, d = idx & 127;
        size_t p = base + (size_t)t * 384 + d;
        sq[t][d] = QKV[p];
        sk[t][d] = QKV[p + 128];
        sv[t][d] = QKV[p + 256];
    }
    __syncthreads();
    int h = tid >> 5;
    int tq = (tid >> 1) & 15;
    int half = tid & 1;
    const float scale = 0.17677669529663687f;
    float sc[16];
    float mx = -1e30f;
#pragma unroll
    for (int tk = 0; tk < 16; tk++) {
        float s = 0.f;
#pragma unroll
        for (int dd = 0; dd < 16; dd++) {
            int d = half * 16 + dd;
            s += sq[tq][h * 32 + d] * sk[tk][h * 32 + d];
        }
        s += __shfl_xor_sync(0xFFFFFFFFu, s, 1);
        s *= scale;
        sc[tk] = s;
        mx = fmaxf(mx, s);
    }
    float sum = 0.f;
#pragma unroll
    for (int tk = 0; tk < 16; tk++) { sc[tk] = expf(sc[tk] - mx); sum += sc[tk]; }
    float inv = 1.f / sum;
    size_t ob = (size_t)m * 16 * 128 + (size_t)tq * 128 + h * 32 + half * 16;
#pragma unroll
    for (int dd = 0; dd < 16; dd++) {
        int d = half * 16 + dd;
        float o = 0.f;
#pragma unroll
        for (int tk = 0; tk < 16; tk++) o += sc[tk] * sv[tk][h * 32 + d];
        o *= inv;
        __half hi = __float2half_rn(o);
        Oh[ob + dd] = hi;
        Ol[ob + dd] = __float2half_rn(o - __half2float(hi));
    }
}

// ---------------- launcher ----------------
extern "C" void kernel_launch(void* const* d_in, const int* in_sizes, int n_in,
                              void* d_out, int out_size) {
    const unsigned char* ego = (const unsigned char*)d_in[0];
    const float* positions  = (const float*)d_in[1];
    const float* adjacency  = (const float*)d_in[2];
    const float* gat1_W     = (const float*)d_in[3];
    const float* gat1_asrc  = (const float*)d_in[4];
    const float* gat1_adst  = (const float*)d_in[5];
    const float* gat1_b     = (const float*)d_in[6];
    const float* gatW       = (const float*)d_in[7];
    const float* gat_asrc   = (const float*)d_in[8];
    const float* gat_adst   = (const float*)d_in[9];
    const float* gat_b      = (const float*)d_in[10];
    const float* Wqkv       = (const float*)d_in[11];
    const float* bqkv       = (const float*)d_in[12];
    const float* Wo         = (const float*)d_in[13];
    const float* bo         = (const float*)d_in[14];
    const float* ln1_s      = (const float*)d_in[15];
    const float* ln1_b      = (const float*)d_in[16];
    const float* ln2_s      = (const float*)d_in[17];
    const float* ln2_b      = (const float*)d_in[18];
    const float* Wff1       = (const float*)d_in[19];
    const float* bff1       = (const float*)d_in[20];
    const float* Wff2       = (const float*)d_in[21];
    const float* bff2       = (const float*)d_in[22];
    float* out = (float*)d_out;

    float *h, *xs, *ss, *sd;
    __half *hh, *w16, *xah, *xal, *xbh, *xbl, *xsh, *xsl, *atth, *attl, *ffh, *ffl;
    cudaGetSymbolAddress((void**)&h,    g_h);
    cudaGetSymbolAddress((void**)&hh,   g_hh);
    cudaGetSymbolAddress((void**)&xs,   g_xs);
    cudaGetSymbolAddress((void**)&ss,   g_ss);
    cudaGetSymbolAddress((void**)&sd,   g_sd);
    cudaGetSymbolAddress((void**)&w16,  g_w16);
    cudaGetSymbolAddress((void**)&xah,  g_xah);
    cudaGetSymbolAddress((void**)&xal,  g_xal);
    cudaGetSymbolAddress((void**)&xbh,  g_xbh);
    cudaGetSymbolAddress((void**)&xbl,  g_xbl);
    cudaGetSymbolAddress((void**)&xsh,  g_xsh);
    cudaGetSymbolAddress((void**)&xsl,  g_xsl);
    cudaGetSymbolAddress((void**)&atth, g_atth);
    cudaGetSymbolAddress((void**)&attl, g_attl);
    cudaGetSymbolAddress((void**)&ffh,  g_ffh);
    cudaGetSymbolAddress((void**)&ffl,  g_ffl);

    cudaFuncSetAttribute(gemm_tc<0, false, true,  false>, cudaFuncAttributeMaxDynamicSharedMemorySize, GSM_TOTAL);
    cudaFuncSetAttribute(gemm_tc<0, false, false, false>, cudaFuncAttributeMaxDynamicSharedMemorySize, GSM_TOTAL);
    cudaFuncSetAttribute(gemm_tc<0, true,  false, true >, cudaFuncAttributeMaxDynamicSharedMemorySize, GSM_TOTAL);
    cudaFuncSetAttribute(gemm_tc<1, false, false, false>, cudaFuncAttributeMaxDynamicSharedMemorySize, GSM_TOTAL);

    split_weights<<<(WTOT + 255) / 256, 256>>>(gatW, Wqkv, Wo, Wff1, Wff2);
    precompute<<<1, 128>>>(gat1_W, gat1_asrc, gat1_adst);
    mask_init<<<ROWS / 256, 256>>>(ego);
    build_nbr<<<ROWS, 256>>>(adjacency);

    // GAT layer 0 (FIN=2)
    gat0<<<ROWS * 512 / 256, 256>>>(positions, gat1_W);
    gat_agg<<<ROWS, 128>>>(gat1_b, xah, xal);

    // GAT layers 1..5
    __half *curh = xah, *curl = xal, *nxth = xbh, *nxtl = xbl;
    for (int i = 0; i < 5; i++) {
        dim3 gp(4, ROWS / 128);
        gemm_tc<0, false, true, false><<<gp, 256, GSM_TOTAL>>>(
            curh, curl, w16 + OFF_GAT + (size_t)i * 65536,
            nullptr, nullptr, nullptr, nullptr, nullptr, hh,
            gat_asrc + i * 512, gat_adst + i * 512, ss, sd, nullptr, nullptr, 512, 128);
        gat_agg<<<ROWS, 128>>>(gat_b + i * 128, nxth, nxtl);
        __half* t0 = curh; curh = nxth; nxth = t0;
        __half* t1 = curl; curl = nxtl; nxtl = t1;
    }

    to_seq<<<ROWS * 128 / 256, 256>>>(curh, curl);

    dim3 g1(1, ROWS / 128);
    dim3 g2(4, ROWS / 128);
    dim3 gq(3, ROWS / 128);
    for (int l = 0; l < NL_TR; l++) {
        size_t oq = OFF_QKV + (size_t)l * 49152;
        gemm_tc<0, false, false, false><<<gq, 256, GSM_TOTAL>>>(
            xsh, xsl, w16 + oq,
            bqkv + l * 384, nullptr, h, nullptr, nullptr, nullptr,
            nullptr, nullptr, nullptr, nullptr, nullptr, nullptr, 384, 128);
        attn_kernel<<<Mm, 128>>>(h, atth, attl);
        size_t owo = OFF_WO + (size_t)l * 16384;
        gemm_tc<0, true, false, true><<<g1, 256, GSM_TOTAL>>>(
            atth, attl, w16 + owo,
            bo + l * 128, xs, xs, xsh, xsl, nullptr,
            nullptr, nullptr, nullptr, nullptr,
            ln1_s + l * 128, ln1_b + l * 128, 128, 128);
        size_t of1 = OFF_FF1 + (size_t)l * 65536;
        gemm_tc<1, false, false, false><<<g2, 256, GSM_TOTAL>>>(
            xsh, xsl, w16 + of1,
            bff1 + l * 512, nullptr, nullptr, ffh, ffl, nullptr,
            nullptr, nullptr, nullptr, nullptr, nullptr, nullptr, 512, 128);
        size_t of2 = OFF_FF2 + (size_t)l * 65536;
        if (l == NL_TR - 1) {
            gemm_tc<0, true, false, true><<<g1, 256, GSM_TOTAL>>>(
                ffh, ffl, w16 + of2,
                bff2 + l * 128, xs, out, nullptr, nullptr, nullptr,
                nullptr, nullptr, nullptr, nullptr,
                ln2_s + l * 128, ln2_b + l * 128, 128, 512);
        } else {
            gemm_tc<0, true, false, true><<<g1, 256, GSM_TOTAL>>>(
                ffh, ffl, w16 + of2,
                bff2 + l * 128, xs, xs, xsh, xsl, nullptr,
                nullptr, nullptr, nullptr, nullptr,
                ln2_s + l * 128, ln2_b + l * 128, 128, 512);
        }
    }
}

// round 11
// speedup vs baseline: 1.5326x; 1.1003x over previous
#include <cuda_runtime.h>
#include <cuda_bf16.h>
#include <cuda_fp16.h>
#include <math.h>

// Problem dims
#define Tt 16
#define Mm 1024
#define Hh 128
#define ROWS 16384
#define MAXD 128
#define NL_TR 5

// ---------------- scratch (device globals; no allocations) ----------------
__device__ __half g_qkv[ROWS * 384];       // transformer QKV fp16
__device__ __half g_hh[ROWS * 512];        // GAT projections fp16, head-major
__device__ float g_ss[ROWS * 4];
__device__ float g_sd[ROWS * 4];
__device__ unsigned char g_m[ROWS];
__device__ int g_cnt[ROWS];
__device__ unsigned short g_nbr[ROWS * MAXD];
__device__ float g_xs[ROWS * Hh];
__device__ float g_c[16];
__device__ float g_pe[Tt * Hh];
__device__ __half g_xa[ROWS * Hh];         // GAT activations (hi only)
__device__ __half g_xb[ROWS * Hh];
__device__ __half g_xsh[ROWS * Hh], g_xsl[ROWS * Hh];
__device__ __half g_atth[ROWS * Hh], g_attl[ROWS * Hh];
__device__ __half g_ffh[ROWS * 512];       // FF1 output (hi only)

#define WTOT 1310720
#define OFF_GAT 0
#define OFF_QKV 327680
#define OFF_WO  573440
#define OFF_FF1 655360
#define OFF_FF2 983040
__device__ __half g_w16[WTOT];             // weights, single fp16, [N,K]

__device__ __forceinline__ unsigned smem_u32(const void* p) {
    unsigned a;
    asm("{ .reg .u64 t; cvta.to.shared.u64 t, %1; cvt.u32.u64 %0, t; }" : "=r"(a) : "l"(p));
    return a;
}
__device__ __forceinline__ void ldmat4(unsigned& r0, unsigned& r1, unsigned& r2, unsigned& r3, unsigned addr) {
    asm volatile("ldmatrix.sync.aligned.m8n8.x4.shared.b16 {%0,%1,%2,%3}, [%4];"
        : "=r"(r0), "=r"(r1), "=r"(r2), "=r"(r3) : "r"(addr));
}
__device__ __forceinline__ void mma16816(float* c, unsigned a0, unsigned a1, unsigned a2, unsigned a3,
                                         unsigned b0, unsigned b1) {
    asm volatile("mma.sync.aligned.m16n8k16.row.col.f32.f16.f16.f32 "
        "{%0,%1,%2,%3}, {%4,%5,%6,%7}, {%8,%9}, {%0,%1,%2,%3};"
        : "+f"(c[0]), "+f"(c[1]), "+f"(c[2]), "+f"(c[3])
        : "r"(a0), "r"(a1), "r"(a2), "r"(a3), "r"(b0), "r"(b1));
}
__device__ __forceinline__ void cpa16(unsigned dst, const void* src) {
    asm volatile("cp.async.ca.shared.global [%0], [%1], 16;" :: "r"(dst), "l"(src));
}
#define CPA_COMMIT() asm volatile("cp.async.commit_group;" ::: "memory")
#define CPA_WAIT1() asm volatile("cp.async.wait_group 1;" ::: "memory")
#define CPA_WAIT0() asm volatile("cp.async.wait_group 0;" ::: "memory")

__device__ __forceinline__ unsigned packh_hi2(float a, float b) {
    __half2 h = __floats2half2_rn(a, b);
    return *(unsigned*)&h;
}
__device__ __forceinline__ unsigned packh_lo2(float a, float b) {
    __half ha = __float2half_rn(a), hb = __float2half_rn(b);
    __half2 l = __floats2half2_rn(a - __half2float(ha), b - __half2float(hb));
    return *(unsigned*)&l;
}

// SMEM: 2 stages x 3 planes (Ahi, Alo, B), each 128 rows x 32 fp16 (80B stride)
#define TROW 80
#define PBUF (128 * TROW)       // 10240
#define STAGE (3 * PBUF)        // 30720
#define P_AHI 0
#define P_ALO PBUF
#define P_B   (2 * PBUF)
#define GSM_TOTAL 67584         // epilogue stage 128*132*4; pipeline 2*STAGE fits

// ---------------- HMMA GEMM ----------------
// AMODE: 2 = A hi+lo (2 MMA), 1 = A hi only (1 MMA)
template <int ACT, bool RESID, bool SCORES, bool LNORM, int AMODE>
__global__ void __launch_bounds__(256, 2)
gemm_tc(const __half* __restrict__ Ah, const __half* __restrict__ Al,
        const __half* __restrict__ B16,
        const float* __restrict__ bias, const float* __restrict__ Rr,
        float* __restrict__ C, __half* __restrict__ Ch, __half* __restrict__ Cl,
        __half* __restrict__ H16,
        const float* __restrict__ asrc, const float* __restrict__ adst,
        float* __restrict__ gss, float* __restrict__ gsd,
        const float* __restrict__ ls, const float* __restrict__ lb, int Nt, int Kt) {
    extern __shared__ char smem[];
    const unsigned sb = smem_u32(smem);
    const int tid = threadIdx.x;
    const int wid = tid >> 5, lane = tid & 31;
    const int wr = wid >> 1, wc = wid & 1;
    const int row0 = blockIdx.y * 128;
    const int col0 = blockIdx.x * 128;

    float acc[2][8][4];
#pragma unroll
    for (int mt = 0; mt < 2; mt++)
#pragma unroll
        for (int nt = 0; nt < 8; nt++)
#pragma unroll
            for (int e = 0; e < 4; e++) acc[mt][nt][e] = 0.f;

    const int ltile = lane >> 3, lrow = lane & 7;
    const int nch = Kt >> 5;

#define LOAD_CHUNK(cidx, s) do { \
    unsigned base = sb + (s) * STAGE; \
    _Pragma("unroll") \
    for (int j = 0; j < 2; j++) { \
        int i = tid + j * 256; \
        int rr = i >> 2, qq = i & 3; \
        unsigned off = (unsigned)(rr * TROW + qq * 16); \
        size_t ga = (size_t)(row0 + rr) * Kt + (cidx) * 32 + qq * 8; \
        size_t gb = (size_t)(col0 + rr) * Kt + (cidx) * 32 + qq * 8; \
        cpa16(base + P_AHI + off, Ah + ga); \
        if (AMODE == 2) cpa16(base + P_ALO + off, Al + ga); \
        cpa16(base + P_B + off, B16 + gb); \
    } \
} while (0)

    LOAD_CHUNK(0, 0);
    CPA_COMMIT();

    for (int c = 0; c < nch; c++) {
        if (c + 1 < nch) {
            LOAD_CHUNK(c + 1, (c + 1) & 1);
            CPA_COMMIT();
            CPA_WAIT1();
        } else {
            CPA_WAIT0();
        }
        __syncthreads();
        unsigned base = sb + (c & 1) * STAGE;
#pragma unroll
        for (int ks = 0; ks < 2; ks++) {
            unsigned ah[2][4], al[2][4];
#pragma unroll
            for (int mt = 0; mt < 2; mt++) {
                int row = wr * 32 + mt * 16 + lrow + (ltile & 1) * 8;
                int kcol = ks * 16 + (ltile >> 1) * 8;
                unsigned off = (unsigned)(row * TROW + kcol * 2);
                ldmat4(ah[mt][0], ah[mt][1], ah[mt][2], ah[mt][3], base + P_AHI + off);
                if (AMODE == 2)
                    ldmat4(al[mt][0], al[mt][1], al[mt][2], al[mt][3], base + P_ALO + off);
            }
#pragma unroll
            for (int g = 0; g < 4; g++) {
                int n = wc * 64 + g * 16 + lrow + (ltile >> 1) * 8;
                int kcol = ks * 16 + (ltile & 1) * 8;
                unsigned off = (unsigned)(n * TROW + kcol * 2);
                unsigned bh[4];
                ldmat4(bh[0], bh[1], bh[2], bh[3], base + P_B + off);
#pragma unroll
                for (int mt = 0; mt < 2; mt++)
#pragma unroll
                    for (int half = 0; half < 2; half++) {
                        float* cc = acc[mt][g * 2 + half];
                        mma16816(cc, ah[mt][0], ah[mt][1], ah[mt][2], ah[mt][3],
                                 bh[half * 2], bh[half * 2 + 1]);
                        if (AMODE == 2)
                            mma16816(cc, al[mt][0], al[mt][1], al[mt][2], al[mt][3],
                                     bh[half * 2], bh[half * 2 + 1]);
                    }
            }
        }
        __syncthreads();
    }
#undef LOAD_CHUNK

    float* stage = (float*)smem;
#pragma unroll
    for (int mt = 0; mt < 2; mt++)
#pragma unroll
        for (int nt = 0; nt < 8; nt++) {
            int row = wr * 32 + mt * 16 + (lane >> 2);
            int col = wc * 64 + nt * 8 + (lane & 3) * 2;
            float2 v0 = make_float2(acc[mt][nt][0], acc[mt][nt][1]);
            float2 v1 = make_float2(acc[mt][nt][2], acc[mt][nt][3]);
            *(float2*)(stage + (size_t)row * 132 + col) = v0;
            *(float2*)(stage + (size_t)(row + 8) * 132 + col) = v1;
        }
    __syncthreads();

    if (LNORM) {
        const int c = lane * 4;
        float4 bb = *(const float4*)(bias + c);
        float4 sv = *(const float4*)(ls + c);
        float4 bv = *(const float4*)(lb + c);
#pragma unroll 4
        for (int rr = 0; rr < 16; rr++) {
            int r = wid * 16 + rr;
            float4 v = *(float4*)(stage + (size_t)r * 132 + c);
            float4 res = *(const float4*)(Rr + (size_t)(row0 + r) * 128 + c);
            v.x += bb.x + res.x; v.y += bb.y + res.y;
            v.z += bb.z + res.z; v.w += bb.w + res.w;
            float s = v.x + v.y + v.z + v.w;
#pragma unroll
            for (int o = 16; o; o >>= 1) s += __shfl_xor_sync(0xFFFFFFFFu, s, o);
            float mean = s * (1.f / 128.f);
            float dx = v.x - mean, dy = v.y - mean, dz = v.z - mean, dw = v.w - mean;
            float qq = dx * dx + dy * dy + dz * dz + dw * dw;
#pragma unroll
            for (int o = 16; o; o >>= 1) qq += __shfl_xor_sync(0xFFFFFFFFu, qq, o);
            float rstd = rsqrtf(qq * (1.f / 128.f) + 1e-5f);
            float4 ov;
            ov.x = dx * rstd * sv.x + bv.x;
            ov.y = dy * rstd * sv.y + bv.y;
            ov.z = dz * rstd * sv.z + bv.z;
            ov.w = dw * rstd * sv.w + bv.w;
            if (C) *(float4*)(C + (size_t)(row0 + r) * 128 + c) = ov;
            if (Ch) {
                uint2 uh;
                uh.x = packh_hi2(ov.x, ov.y); uh.y = packh_hi2(ov.z, ov.w);
                *(uint2*)(Ch + (size_t)(row0 + r) * 128 + c) = uh;
                if (Cl) {
                    uint2 ul;
                    ul.x = packh_lo2(ov.x, ov.y); ul.y = packh_lo2(ov.z, ov.w);
                    *(uint2*)(Cl + (size_t)(row0 + r) * 128 + c) = ul;
                }
            }
        }
    } else {
        for (int i = tid; i < 128 * 32; i += 256) {
            int r = i >> 5, q = i & 31;
            int c = q * 4;
            float4 v = *(float4*)(stage + (size_t)r * 132 + c);
            if (bias) {
                v.x += bias[col0 + c];
                v.y += bias[col0 + c + 1];
                v.z += bias[col0 + c + 2];
                v.w += bias[col0 + c + 3];
            }
            if (RESID) {
                float4 rr = *(const float4*)(Rr + (size_t)(row0 + r) * Nt + col0 + c);
                v.x += rr.x; v.y += rr.y; v.z += rr.z; v.w += rr.w;
            }
            if (ACT == 1) {
                v.x = fmaxf(v.x, 0.f); v.y = fmaxf(v.y, 0.f);
                v.z = fmaxf(v.z, 0.f); v.w = fmaxf(v.w, 0.f);
            }
            if (C) *(float4*)(C + (size_t)(row0 + r) * Nt + col0 + c) = v;
            if (H16) {
                uint2 u;
                u.x = packh_hi2(v.x, v.y);
                u.y = packh_hi2(v.z, v.w);
                *(uint2*)(H16 + (size_t)(row0 + r) * Nt + col0 + c) = u;
            }
            if (Ch) {
                uint2 uh;
                uh.x = packh_hi2(v.x, v.y); uh.y = packh_hi2(v.z, v.w);
                *(uint2*)(Ch + (size_t)(row0 + r) * Nt + col0 + c) = uh;
                if (Cl) {
                    uint2 ul;
                    ul.x = packh_lo2(v.x, v.y); ul.y = packh_lo2(v.z, v.w);
                    *(uint2*)(Cl + (size_t)(row0 + r) * Nt + col0 + c) = ul;
                }
            }
        }
    }

    if (SCORES && tid < 128) {
        int r = tid;
        float s1 = 0.f, s2 = 0.f;
        const float* as = asrc + col0;
        const float* ad = adst + col0;
        const float* sp = stage + (size_t)r * 132;
#pragma unroll 8
        for (int c = 0; c < 128; c++) {
            float hv = sp[c];
            s1 += hv * as[c];
            s2 += hv * ad[c];
        }
        gss[(size_t)(row0 + r) * 4 + blockIdx.x] = s1;
        gsd[(size_t)(row0 + r) * 4 + blockIdx.x] = s2;
    }
}

// ---------------- weight conversion to fp16 [N,K]; QKV packed per-layer [384, 128] ----------------
__global__ void split_weights(const float* __restrict__ gatW, const float* __restrict__ Wqkv,
                              const float* __restrict__ Wo, const float* __restrict__ Wff1,
                              const float* __restrict__ Wff2) {
    int idx = blockIdx.x * 256 + threadIdx.x;
    if (idx >= WTOT) return;
    float v;
    if (idx < OFF_QKV) {
        int i = idx >> 16, r = idx & 65535;
        int n = r >> 7, k = r & 127;
        v = gatW[(i << 16) + k * 512 + n];
    } else if (idx < OFF_WO) {
        int r0 = idx - OFF_QKV;
        int l = r0 / 49152;
        int rem = r0 - l * 49152;
        int n = rem >> 7, k = rem & 127;
        int s = n >> 7, nc = n & 127;
        v = Wqkv[((l * 3 + s) << 14) + k * 128 + nc];
    } else if (idx < OFF_FF1) {
        int r0 = idx - OFF_WO;
        int i = r0 >> 14, r = r0 & 16383;
        int n = r >> 7, k = r & 127;
        v = Wo[(i << 14) + k * 128 + n];
    } else if (idx < OFF_FF2) {
        int r0 = idx - OFF_FF1;
        int i = r0 >> 16, r = r0 & 65535;
        int n = r >> 7, k = r & 127;
        v = Wff1[(i << 16) + k * 512 + n];
    } else {
        int r0 = idx - OFF_FF2;
        int i = r0 >> 16, r = r0 & 65535;
        int n = r >> 9, k = r & 511;
        v = Wff2[(i << 16) + k * 128 + n];
    }
    g_w16[idx] = __float2half_rn(v);
}

// ---------------- tiny precompute ----------------
__global__ void precompute(const float* __restrict__ W, const float* __restrict__ asrc,
                           const float* __restrict__ adst) {
    int tid = threadIdx.x;
    int wid = tid >> 5, lane = tid & 31;
    float a0s = 0.f, a1s = 0.f, a0d = 0.f, a1d = 0.f;
    for (int d = lane; d < 128; d += 32) {
        int c = wid * 128 + d;
        float w0 = W[c], w1 = W[512 + c], as = asrc[c], ad = adst[c];
        a0s += w0 * as; a1s += w1 * as; a0d += w0 * ad; a1d += w1 * ad;
    }
#pragma unroll
    for (int o = 16; o; o >>= 1) {
        a0s += __shfl_xor_sync(0xFFFFFFFFu, a0s, o);
        a1s += __shfl_xor_sync(0xFFFFFFFFu, a1s, o);
        a0d += __shfl_xor_sync(0xFFFFFFFFu, a0d, o);
        a1d += __shfl_xor_sync(0xFFFFFFFFu, a1d, o);
    }
    if (lane == 0) {
        g_c[wid] = a0s; g_c[4 + wid] = a1s; g_c[8 + wid] = a0d; g_c[12 + wid] = a1d;
    }
    for (int i = tid; i < Tt * Hh; i += 128) {
        int t = i >> 7, d = i & 127;
        float freq = expf(-(float)(d & ~1) * (9.210340371976184f / 128.f));
        float ang = (float)t * freq;
        g_pe[i] = (d & 1) ? cosf(ang) : sinf(ang);
    }
}

// ---------------- mask + self-loop init ----------------
__global__ void mask_init(const unsigned char* __restrict__ ego) {
    int idx = blockIdx.x * 256 + threadIdx.x;
    if (idx >= ROWS) return;
    int t = idx >> 10;
    int mm = idx & 1023;
    int b = mm >> 8;
    int n = mm & 255;
    unsigned char v = ego[(b * Tt + t) * 256 + n] ? 1 : 0;
    g_m[idx] = v;
    g_cnt[idx] = v ? 1 : 0;
    g_nbr[idx * MAXD] = (unsigned short)mm;
}

// ---------------- neighbor-list build ----------------
__global__ void build_nbr(const float* __restrict__ A) {
    int tj = blockIdx.x;
    if (!g_m[tj]) return;
    int t = tj >> 10;
    int j = tj & 1023;
    int i0 = threadIdx.x * 4;
    float4 a = *(const float4*)(A + (size_t)tj * 1024 + i0);
    float av[4] = {a.x, a.y, a.z, a.w};
#pragma unroll
    for (int e = 0; e < 4; e++) {
        int i = i0 + e;
        if (i == j) continue;
        int ti = (t << 10) + i;
        if (av[e] != 0.f && g_m[ti]) {
            int pos = atomicAdd(&g_cnt[ti], 1);
            if (pos < MAXD) g_nbr[(size_t)ti * MAXD + pos] = (unsigned short)j;
        }
    }
}

// ---------------- GAT layer-0 ----------------
__global__ void gat0(const float* __restrict__ x, const float* __restrict__ W) {
    int idx = blockIdx.x * 256 + threadIdx.x;   // ROWS*512
    int row = idx >> 9;
    int c = idx & 511;
    float x0 = x[row * 2], x1 = x[row * 2 + 1];
    g_hh[idx] = __float2half(x0 * W[c] + x1 * W[512 + c]);
    if (c < 8) {
        int hh = c & 3;
        int isd = c >> 2;
        float v = x0 * g_c[hh + isd * 8] + x1 * g_c[hh + 4 + isd * 8];
        if (isd == 0) g_ss[row * 4 + hh] = v;
        else g_sd[row * 4 + hh] = v;
    }
}

// ---------------- sparse segment-softmax + aggregation ----------------
__global__ void gat_agg(const float* __restrict__ bias, __half* __restrict__ xh) {
    int row = blockIdx.x;
    int tid = threadIdx.x;
    if (!g_m[row]) {
        xh[(size_t)row * 128 + tid] = __float2half(0.f);
        return;
    }
    int t = row >> 10;

    __shared__ unsigned short nb[MAXD];
    __shared__ float w[4][MAXD];

    int cnt = g_cnt[row];
    if (cnt > MAXD) cnt = MAXD;
    if (tid < cnt) nb[tid] = g_nbr[(size_t)row * MAXD + tid];

    if (tid < cnt) {
        int jr = (t << 10) + nb[tid];
#pragma unroll
        for (int hh = 0; hh < 4; hh++) {
            float z = g_sd[row * 4 + hh] + g_ss[jr * 4 + hh];
            w[hh][tid] = (z > 0.f) ? z : 0.2f * z;
        }
    } else {
#pragma unroll
        for (int hh = 0; hh < 4; hh++) w[hh][tid] = -INFINITY;
    }
    __syncthreads();

    {
        int wh = tid >> 5, lane = tid & 31;
        float v0 = w[wh][lane], v1 = w[wh][lane + 32], v2 = w[wh][lane + 64], v3 = w[wh][lane + 96];
        float mx = fmaxf(fmaxf(v0, v1), fmaxf(v2, v3));
#pragma unroll
        for (int o = 16; o; o >>= 1) mx = fmaxf(mx, __shfl_xor_sync(0xFFFFFFFFu, mx, o));
        float e0 = expf(v0 - mx), e1 = expf(v1 - mx), e2 = expf(v2 - mx), e3 = expf(v3 - mx);
        float s = e0 + e1 + e2 + e3;
#pragma unroll
        for (int o = 16; o; o >>= 1) s += __shfl_xor_sync(0xFFFFFFFFu, s, o);
        float inv = 1.f / s;
        w[wh][lane] = e0 * inv;
        w[wh][lane + 32] = e1 * inv;
        w[wh][lane + 64] = e2 * inv;
        w[wh][lane + 96] = e3 * inv;
    }
    __syncthreads();

    float acc0 = 0.f, acc1 = 0.f, acc2 = 0.f, acc3 = 0.f;
    const __half* hb = g_hh + (((size_t)(t << 10)) << 9) + tid;
    int j = 0;
    for (; j + 4 <= cnt; j += 4) {
        const __half* p0 = hb + ((size_t)nb[j] << 9);
        const __half* p1 = hb + ((size_t)nb[j + 1] << 9);
        const __half* p2 = hb + ((size_t)nb[j + 2] << 9);
        const __half* p3 = hb + ((size_t)nb[j + 3] << 9);
#pragma unroll
        for (int hh = 0; hh < 4; hh++) {
            acc0 += w[hh][j] * __half2float(p0[hh << 7]);
            acc1 += w[hh][j + 1] * __half2float(p1[hh << 7]);
            acc2 += w[hh][j + 2] * __half2float(p2[hh << 7]);
            acc3 += w[hh][j + 3] * __half2float(p3[hh << 7]);
        }
    }
    for (; j < cnt; j++) {
        const __half* p0 = hb + ((size_t)nb[j] << 9);
#pragma unroll
        for (int hh = 0; hh < 4; hh++) acc0 += w[hh][j] * __half2float(p0[hh << 7]);
    }
    float o = (acc0 + acc1 + acc2 + acc3) * 0.25f + bias[tid];
    o = fmaxf(o, 0.f);
    xh[(size_t)row * 128 + tid] = __float2half_rn(o);
}

// ---------------- transpose to sequence layout + PE ----------------
__global__ void to_seq(const __half* __restrict__ xh) {
    int idx = blockIdx.x * 256 + threadIdx.x;
    int row = idx >> 7;
    int d = idx & 127;
    int t = row >> 10;
    int mm = row & 1023;
    float x = __half2float(xh[idx]);
    float v = x + g_pe[t * 128 + d];
    size_t sidx = ((size_t)mm * Tt + t) * Hh + d;
    g_xs[sidx] = v;
    __half hi = __float2half_rn(v);
    g_xsh[sidx] = hi;
    g_xsl[sidx] = __float2half_rn(v - __half2float(hi));
}

// ---------------- per-sequence attention (fp16 QKV in, fp16 hi/lo out) ----------------
__global__ void attn_kernel(const __half* __restrict__ QKV,
                            __half* __restrict__ Oh, __half* __restrict__ Ol) {
    __shared__ float sq[16][128], sk[16][128], sv[16][128];
    int m = blockIdx.x;
    int tid = threadIdx.x;
    size_t base = (size_t)m * 16 * 384;
    for (int idx = tid; idx < 2048; idx += 128) {
        int t = idx >> 7, d = idx & 127;
        size_t p = base + (size_t)t * 384 + d;
        sq[t][d] = __half2float(QKV[p]);
        sk[t][d] = __half2float(QKV[p + 128]);
        sv[t][d] = __half2float(QKV[p + 256]);
    }
    __syncthreads();
    int h = tid >> 5;
    int tq = (tid >> 1) & 15;
    int half = tid & 1;
    const float scale = 0.17677669529663687f;
    float sc[16];
    float mx = -1e30f;
#pragma unroll
    for (int tk = 0; tk < 16; tk++) {
        float s = 0.f;
#pragma unroll
        for (int dd = 0; dd < 16; dd++) {
            int d = half * 16 + dd;
            s += sq[tq][h * 32 + d] * sk[tk][h * 32 + d];
        }
        s += __shfl_xor_sync(0xFFFFFFFFu, s, 1);
        s *= scale;
        sc[tk] = s;
        mx = fmaxf(mx, s);
    }
    float sum = 0.f;
#pragma unroll
    for (int tk = 0; tk < 16; tk++) { sc[tk] = expf(sc[tk] - mx); sum += sc[tk]; }
    float inv = 1.f / sum;
    size_t ob = (size_t)m * 16 * 128 + (size_t)tq * 128 + h * 32 + half * 16;
#pragma unroll
    for (int dd = 0; dd < 16; dd++) {
        int d = half * 16 + dd;
        float o = 0.f;
#pragma unroll
        for (int tk = 0; tk < 16; tk++) o += sc[tk] * sv[tk][h * 32 + d];
        o *= inv;
        __half hi = __float2half_rn(o);
        Oh[ob + dd] = hi;
        Ol[ob + dd] = __float2half_rn(o - __half2float(hi));
    }
}

// ---------------- launcher ----------------
extern "C" void kernel_launch(void* const* d_in, const int* in_sizes, int n_in,
                              void* d_out, int out_size) {
    const unsigned char* ego = (const unsigned char*)d_in[0];
    const float* positions  = (const float*)d_in[1];
    const float* adjacency  = (const float*)d_in[2];
    const float* gat1_W     = (const float*)d_in[3];
    const float* gat1_asrc  = (const float*)d_in[4];
    const float* gat1_adst  = (const float*)d_in[5];
    const float* gat1_b     = (const float*)d_in[6];
    const float* gatW       = (const float*)d_in[7];
    const float* gat_asrc   = (const float*)d_in[8];
    const float* gat_adst   = (const float*)d_in[9];
    const float* gat_b      = (const float*)d_in[10];
    const float* Wqkv       = (const float*)d_in[11];
    const float* bqkv       = (const float*)d_in[12];
    const float* Wo         = (const float*)d_in[13];
    const float* bo         = (const float*)d_in[14];
    const float* ln1_s      = (const float*)d_in[15];
    const float* ln1_b      = (const float*)d_in[16];
    const float* ln2_s      = (const float*)d_in[17];
    const float* ln2_b      = (const float*)d_in[18];
    const float* Wff1       = (const float*)d_in[19];
    const float* bff1       = (const float*)d_in[20];
    const float* Wff2       = (const float*)d_in[21];
    const float* bff2       = (const float*)d_in[22];
    float* out = (float*)d_out;

    float *xs, *ss, *sd;
    __half *qkv, *hh, *w16, *xa, *xb, *xsh, *xsl, *atth, *attl, *ffh;
    cudaGetSymbolAddress((void**)&qkv,  g_qkv);
    cudaGetSymbolAddress((void**)&hh,   g_hh);
    cudaGetSymbolAddress((void**)&xs,   g_xs);
    cudaGetSymbolAddress((void**)&ss,   g_ss);
    cudaGetSymbolAddress((void**)&sd,   g_sd);
    cudaGetSymbolAddress((void**)&w16,  g_w16);
    cudaGetSymbolAddress((void**)&xa,   g_xa);
    cudaGetSymbolAddress((void**)&xb,   g_xb);
    cudaGetSymbolAddress((void**)&xsh,  g_xsh);
    cudaGetSymbolAddress((void**)&xsl,  g_xsl);
    cudaGetSymbolAddress((void**)&atth, g_atth);
    cudaGetSymbolAddress((void**)&attl, g_attl);
    cudaGetSymbolAddress((void**)&ffh,  g_ffh);

    cudaFuncSetAttribute(gemm_tc<0, false, true,  false, 1>, cudaFuncAttributeMaxDynamicSharedMemorySize, GSM_TOTAL);
    cudaFuncSetAttribute(gemm_tc<0, false, false, false, 2>, cudaFuncAttributeMaxDynamicSharedMemorySize, GSM_TOTAL);
    cudaFuncSetAttribute(gemm_tc<0, true,  false, true,  2>, cudaFuncAttributeMaxDynamicSharedMemorySize, GSM_TOTAL);
    cudaFuncSetAttribute(gemm_tc<1, false, false, false, 2>, cudaFuncAttributeMaxDynamicSharedMemorySize, GSM_TOTAL);
    cudaFuncSetAttribute(gemm_tc<0, true,  false, true,  1>, cudaFuncAttributeMaxDynamicSharedMemorySize, GSM_TOTAL);

    split_weights<<<(WTOT + 255) / 256, 256>>>(gatW, Wqkv, Wo, Wff1, Wff2);
    precompute<<<1, 128>>>(gat1_W, gat1_asrc, gat1_adst);
    mask_init<<<ROWS / 256, 256>>>(ego);
    build_nbr<<<ROWS, 256>>>(adjacency);

    // GAT layer 0 (FIN=2)
    gat0<<<ROWS * 512 / 256, 256>>>(positions, gat1_W);
    gat_agg<<<ROWS, 128>>>(gat1_b, xa);

    // GAT layers 1..5 (single-MMA A)
    __half *cur = xa, *nxt = xb;
    for (int i = 0; i < 5; i++) {
        dim3 gp(4, ROWS / 128);
        gemm_tc<0, false, true, false, 1><<<gp, 256, GSM_TOTAL>>>(
            cur, cur, w16 + OFF_GAT + (size_t)i * 65536,
            nullptr, nullptr, nullptr, nullptr, nullptr, hh,
            gat_asrc + i * 512, gat_adst + i * 512, ss, sd, nullptr, nullptr, 512, 128);
        gat_agg<<<ROWS, 128>>>(gat_b + i * 128, nxt);
        __half* t0 = cur; cur = nxt; nxt = t0;
    }

    to_seq<<<ROWS * 128 / 256, 256>>>(cur);

    dim3 g1(1, ROWS / 128);
    dim3 g2(4, ROWS / 128);
    dim3 gq(3, ROWS / 128);
    for (int l = 0; l < NL_TR; l++) {
        // QKV (2-MMA) -> fp16 packed
        size_t oq = OFF_QKV + (size_t)l * 49152;
        gemm_tc<0, false, false, false, 2><<<gq, 256, GSM_TOTAL>>>(
            xsh, xsl, w16 + oq,
            bqkv + l * 384, nullptr, nullptr, nullptr, nullptr, qkv,
            nullptr, nullptr, nullptr, nullptr, nullptr, nullptr, 384, 128);
        attn_kernel<<<Mm, 128>>>(qkv, atth, attl);
        // Wo (2-MMA) + LN1 -> xs fp32 + hi/lo
        size_t owo = OFF_WO + (size_t)l * 16384;
        gemm_tc<0, true, false, true, 2><<<g1, 256, GSM_TOTAL>>>(
            atth, attl, w16 + owo,
            bo + l * 128, xs, xs, xsh, xsl, nullptr,
            nullptr, nullptr, nullptr, nullptr,
            ln1_s + l * 128, ln1_b + l * 128, 128, 128);
        // FF1 (2-MMA) + ReLU -> hi only
        size_t of1 = OFF_FF1 + (size_t)l * 65536;
        gemm_tc<1, false, false, false, 2><<<g2, 256, GSM_TOTAL>>>(
            xsh, xsl, w16 + of1,
            bff1 + l * 512, nullptr, nullptr, ffh, nullptr, nullptr,
            nullptr, nullptr, nullptr, nullptr, nullptr, nullptr, 512, 128);
        // FF2 (single-MMA A) + LN2
        size_t of2 = OFF_FF2 + (size_t)l * 65536;
        if (l == NL_TR - 1) {
            gemm_tc<0, true, false, true, 1><<<g1, 256, GSM_TOTAL>>>(
                ffh, ffh, w16 + of2,
                bff2 + l * 128, xs, out, nullptr, nullptr, nullptr,
                nullptr, nullptr, nullptr, nullptr,
                ln2_s + l * 128, ln2_b + l * 128, 128, 512);
        } else {
            gemm_tc<0, true, false, true, 1><<<g1, 256, GSM_TOTAL>>>(
                ffh, ffh, w16 + of2,
                bff2 + l * 128, xs, xs, xsh, xsl, nullptr,
                nullptr, nullptr, nullptr, nullptr,
                ln2_s + l * 128, ln2_b + l * 128, 128, 512);
        }
    }
}

// round 12
// speedup vs baseline: 1.8080x; 1.1797x over previous
#include <cuda_runtime.h>
#include <cuda_bf16.h>
#include <cuda_fp16.h>
#include <math.h>

// Problem dims
#define Tt 16
#define Mm 1024
#define Hh 128
#define ROWS 16384
#define MAXD 128
#define NL_TR 5

// ---------------- scratch (device globals; no allocations) ----------------
__device__ __half g_qkv[ROWS * 384];       // transformer QKV fp16
__device__ __half g_hh[ROWS * 512];        // GAT projections fp16, head-major
__device__ float g_ss[ROWS * 4];
__device__ float g_sd[ROWS * 4];
__device__ unsigned char g_m[ROWS];
__device__ int g_cnt[ROWS];
__device__ unsigned short g_nbr[ROWS * MAXD];
__device__ float g_xs[ROWS * Hh];          // residual stream fp32
__device__ float g_c[16];
__device__ float g_pe[Tt * Hh];
__device__ __half g_xa[ROWS * Hh];
__device__ __half g_xb[ROWS * Hh];
__device__ __half g_xsh[ROWS * Hh];        // xs fp16 (GEMM A)
__device__ __half g_atth[ROWS * Hh];       // attention out fp16
__device__ __half g_ffh[ROWS * 512];       // FF1 out fp16

#define WTOT 1310720
#define OFF_GAT 0
#define OFF_QKV 327680
#define OFF_WO  573440
#define OFF_FF1 655360
#define OFF_FF2 983040
__device__ __half g_w16[WTOT];             // weights fp16 [N,K]

__device__ __forceinline__ unsigned smem_u32(const void* p) {
    unsigned a;
    asm("{ .reg .u64 t; cvta.to.shared.u64 t, %1; cvt.u32.u64 %0, t; }" : "=r"(a) : "l"(p));
    return a;
}
__device__ __forceinline__ void ldmat4(unsigned& r0, unsigned& r1, unsigned& r2, unsigned& r3, unsigned addr) {
    asm volatile("ldmatrix.sync.aligned.m8n8.x4.shared.b16 {%0,%1,%2,%3}, [%4];"
        : "=r"(r0), "=r"(r1), "=r"(r2), "=r"(r3) : "r"(addr));
}
__device__ __forceinline__ void mma16816(float* c, unsigned a0, unsigned a1, unsigned a2, unsigned a3,
                                         unsigned b0, unsigned b1) {
    asm volatile("mma.sync.aligned.m16n8k16.row.col.f32.f16.f16.f32 "
        "{%0,%1,%2,%3}, {%4,%5,%6,%7}, {%8,%9}, {%0,%1,%2,%3};"
        : "+f"(c[0]), "+f"(c[1]), "+f"(c[2]), "+f"(c[3])
        : "r"(a0), "r"(a1), "r"(a2), "r"(a3), "r"(b0), "r"(b1));
}
__device__ __forceinline__ void cpa16(unsigned dst, const void* src) {
    asm volatile("cp.async.ca.shared.global [%0], [%1], 16;" :: "r"(dst), "l"(src));
}
#define CPA_COMMIT() asm volatile("cp.async.commit_group;" ::: "memory")
#define CPA_WAIT1() asm volatile("cp.async.wait_group 1;" ::: "memory")
#define CPA_WAIT0() asm volatile("cp.async.wait_group 0;" ::: "memory")

__device__ __forceinline__ unsigned packh_hi2(float a, float b) {
    __half2 h = __floats2half2_rn(a, b);
    return *(unsigned*)&h;
}

// SMEM: 2 stages x 2 planes (A, B), each 128 rows x 32 fp16 (80B stride)
#define TROW 80
#define PBUF (128 * TROW)       // 10240
#define STAGE (2 * PBUF)        // 20480
#define P_A 0
#define P_B PBUF
#define GSM_TOTAL 67584         // epilogue stage dominates; pipeline 2*STAGE fits

// ---------------- HMMA GEMM: A fp16, B fp16, single-MMA ----------------
template <int ACT, bool RESID, bool SCORES, bool LNORM>
__global__ void __launch_bounds__(256, 2)
gemm_tc(const __half* __restrict__ Ah, const __half* __restrict__ B16,
        const float* __restrict__ bias, const float* __restrict__ Rr,
        float* __restrict__ C, __half* __restrict__ Ch,
        __half* __restrict__ H16,
        const float* __restrict__ asrc, const float* __restrict__ adst,
        float* __restrict__ gss, float* __restrict__ gsd,
        const float* __restrict__ ls, const float* __restrict__ lb, int Nt, int Kt) {
    extern __shared__ char smem[];
    const unsigned sb = smem_u32(smem);
    const int tid = threadIdx.x;
    const int wid = tid >> 5, lane = tid & 31;
    const int wr = wid >> 1, wc = wid & 1;
    const int row0 = blockIdx.y * 128;
    const int col0 = blockIdx.x * 128;

    float acc[2][8][4];
#pragma unroll
    for (int mt = 0; mt < 2; mt++)
#pragma unroll
        for (int nt = 0; nt < 8; nt++)
#pragma unroll
            for (int e = 0; e < 4; e++) acc[mt][nt][e] = 0.f;

    const int ltile = lane >> 3, lrow = lane & 7;
    const int nch = Kt >> 5;

#define LOAD_CHUNK(cidx, s) do { \
    unsigned base = sb + (s) * STAGE; \
    _Pragma("unroll") \
    for (int j = 0; j < 2; j++) { \
        int i = tid + j * 256; \
        int rr = i >> 2, qq = i & 3; \
        unsigned off = (unsigned)(rr * TROW + qq * 16); \
        size_t ga = (size_t)(row0 + rr) * Kt + (cidx) * 32 + qq * 8; \
        size_t gb = (size_t)(col0 + rr) * Kt + (cidx) * 32 + qq * 8; \
        cpa16(base + P_A + off, Ah + ga); \
        cpa16(base + P_B + off, B16 + gb); \
    } \
} while (0)

    LOAD_CHUNK(0, 0);
    CPA_COMMIT();

    for (int c = 0; c < nch; c++) {
        if (c + 1 < nch) {
            LOAD_CHUNK(c + 1, (c + 1) & 1);
            CPA_COMMIT();
            CPA_WAIT1();
        } else {
            CPA_WAIT0();
        }
        __syncthreads();
        unsigned base = sb + (c & 1) * STAGE;
#pragma unroll
        for (int ks = 0; ks < 2; ks++) {
            unsigned ah[2][4];
#pragma unroll
            for (int mt = 0; mt < 2; mt++) {
                int row = wr * 32 + mt * 16 + lrow + (ltile & 1) * 8;
                int kcol = ks * 16 + (ltile >> 1) * 8;
                unsigned off = (unsigned)(row * TROW + kcol * 2);
                ldmat4(ah[mt][0], ah[mt][1], ah[mt][2], ah[mt][3], base + P_A + off);
            }
#pragma unroll
            for (int g = 0; g < 4; g++) {
                int n = wc * 64 + g * 16 + lrow + (ltile >> 1) * 8;
                int kcol = ks * 16 + (ltile & 1) * 8;
                unsigned off = (unsigned)(n * TROW + kcol * 2);
                unsigned bh[4];
                ldmat4(bh[0], bh[1], bh[2], bh[3], base + P_B + off);
#pragma unroll
                for (int mt = 0; mt < 2; mt++)
#pragma unroll
                    for (int half = 0; half < 2; half++) {
                        mma16816(acc[mt][g * 2 + half],
                                 ah[mt][0], ah[mt][1], ah[mt][2], ah[mt][3],
                                 bh[half * 2], bh[half * 2 + 1]);
                    }
            }
        }
        __syncthreads();
    }
#undef LOAD_CHUNK

    float* stage = (float*)smem;
#pragma unroll
    for (int mt = 0; mt < 2; mt++)
#pragma unroll
        for (int nt = 0; nt < 8; nt++) {
            int row = wr * 32 + mt * 16 + (lane >> 2);
            int col = wc * 64 + nt * 8 + (lane & 3) * 2;
            float2 v0 = make_float2(acc[mt][nt][0], acc[mt][nt][1]);
            float2 v1 = make_float2(acc[mt][nt][2], acc[mt][nt][3]);
            *(float2*)(stage + (size_t)row * 132 + col) = v0;
            *(float2*)(stage + (size_t)(row + 8) * 132 + col) = v1;
        }
    __syncthreads();

    if (LNORM) {
        const int c = lane * 4;
        float4 bb = *(const float4*)(bias + c);
        float4 sv = *(const float4*)(ls + c);
        float4 bv = *(const float4*)(lb + c);
#pragma unroll 4
        for (int rr = 0; rr < 16; rr++) {
            int r = wid * 16 + rr;
            float4 v = *(float4*)(stage + (size_t)r * 132 + c);
            float4 res = *(const float4*)(Rr + (size_t)(row0 + r) * 128 + c);
            v.x += bb.x + res.x; v.y += bb.y + res.y;
            v.z += bb.z + res.z; v.w += bb.w + res.w;
            float s = v.x + v.y + v.z + v.w;
#pragma unroll
            for (int o = 16; o; o >>= 1) s += __shfl_xor_sync(0xFFFFFFFFu, s, o);
            float mean = s * (1.f / 128.f);
            float dx = v.x - mean, dy = v.y - mean, dz = v.z - mean, dw = v.w - mean;
            float qq = dx * dx + dy * dy + dz * dz + dw * dw;
#pragma unroll
            for (int o = 16; o; o >>= 1) qq += __shfl_xor_sync(0xFFFFFFFFu, qq, o);
            float rstd = rsqrtf(qq * (1.f / 128.f) + 1e-5f);
            float4 ov;
            ov.x = dx * rstd * sv.x + bv.x;
            ov.y = dy * rstd * sv.y + bv.y;
            ov.z = dz * rstd * sv.z + bv.z;
            ov.w = dw * rstd * sv.w + bv.w;
            if (C) *(float4*)(C + (size_t)(row0 + r) * 128 + c) = ov;
            if (Ch) {
                uint2 uh;
                uh.x = packh_hi2(ov.x, ov.y); uh.y = packh_hi2(ov.z, ov.w);
                *(uint2*)(Ch + (size_t)(row0 + r) * 128 + c) = uh;
            }
        }
    } else {
        for (int i = tid; i < 128 * 32; i += 256) {
            int r = i >> 5, q = i & 31;
            int c = q * 4;
            float4 v = *(float4*)(stage + (size_t)r * 132 + c);
            if (bias) {
                v.x += bias[col0 + c];
                v.y += bias[col0 + c + 1];
                v.z += bias[col0 + c + 2];
                v.w += bias[col0 + c + 3];
            }
            if (RESID) {
                float4 rr = *(const float4*)(Rr + (size_t)(row0 + r) * Nt + col0 + c);
                v.x += rr.x; v.y += rr.y; v.z += rr.z; v.w += rr.w;
            }
            if (ACT == 1) {
                v.x = fmaxf(v.x, 0.f); v.y = fmaxf(v.y, 0.f);
                v.z = fmaxf(v.z, 0.f); v.w = fmaxf(v.w, 0.f);
            }
            if (C) *(float4*)(C + (size_t)(row0 + r) * Nt + col0 + c) = v;
            if (H16) {
                uint2 u;
                u.x = packh_hi2(v.x, v.y);
                u.y = packh_hi2(v.z, v.w);
                *(uint2*)(H16 + (size_t)(row0 + r) * Nt + col0 + c) = u;
            }
            if (Ch) {
                uint2 uh;
                uh.x = packh_hi2(v.x, v.y); uh.y = packh_hi2(v.z, v.w);
                *(uint2*)(Ch + (size_t)(row0 + r) * Nt + col0 + c) = uh;
            }
        }
    }

    if (SCORES && tid < 128) {
        int r = tid;
        float s1 = 0.f, s2 = 0.f;
        const float* as = asrc + col0;
        const float* ad = adst + col0;
        const float* sp = stage + (size_t)r * 132;
#pragma unroll 8
        for (int c = 0; c < 128; c++) {
            float hv = sp[c];
            s1 += hv * as[c];
            s2 += hv * ad[c];
        }
        gss[(size_t)(row0 + r) * 4 + blockIdx.x] = s1;
        gsd[(size_t)(row0 + r) * 4 + blockIdx.x] = s2;
    }
}

// ---------------- weight conversion to fp16 [N,K]; QKV packed per-layer [384, 128] ----------------
__global__ void split_weights(const float* __restrict__ gatW, const float* __restrict__ Wqkv,
                              const float* __restrict__ Wo, const float* __restrict__ Wff1,
                              const float* __restrict__ Wff2) {
    int idx = blockIdx.x * 256 + threadIdx.x;
    if (idx >= WTOT) return;
    float v;
    if (idx < OFF_QKV) {
        int i = idx >> 16, r = idx & 65535;
        int n = r >> 7, k = r & 127;
        v = gatW[(i << 16) + k * 512 + n];
    } else if (idx < OFF_WO) {
        int r0 = idx - OFF_QKV;
        int l = r0 / 49152;
        int rem = r0 - l * 49152;
        int n = rem >> 7, k = rem & 127;
        int s = n >> 7, nc = n & 127;
        v = Wqkv[((l * 3 + s) << 14) + k * 128 + nc];
    } else if (idx < OFF_FF1) {
        int r0 = idx - OFF_WO;
        int i = r0 >> 14, r = r0 & 16383;
        int n = r >> 7, k = r & 127;
        v = Wo[(i << 14) + k * 128 + n];
    } else if (idx < OFF_FF2) {
        int r0 = idx - OFF_FF1;
        int i = r0 >> 16, r = r0 & 65535;
        int n = r >> 7, k = r & 127;
        v = Wff1[(i << 16) + k * 512 + n];
    } else {
        int r0 = idx - OFF_FF2;
        int i = r0 >> 16, r = r0 & 65535;
        int n = r >> 9, k = r & 511;
        v = Wff2[(i << 16) + k * 128 + n];
    }
    g_w16[idx] = __float2half_rn(v);
}

// ---------------- tiny precompute ----------------
__global__ void precompute(const float* __restrict__ W, const float* __restrict__ asrc,
                           const float* __restrict__ adst) {
    int tid = threadIdx.x;
    int wid = tid >> 5, lane = tid & 31;
    float a0s = 0.f, a1s = 0.f, a0d = 0.f, a1d = 0.f;
    for (int d = lane; d < 128; d += 32) {
        int c = wid * 128 + d;
        float w0 = W[c], w1 = W[512 + c], as = asrc[c], ad = adst[c];
        a0s += w0 * as; a1s += w1 * as; a0d += w0 * ad; a1d += w1 * ad;
    }
#pragma unroll
    for (int o = 16; o; o >>= 1) {
        a0s += __shfl_xor_sync(0xFFFFFFFFu, a0s, o);
        a1s += __shfl_xor_sync(0xFFFFFFFFu, a1s, o);
        a0d += __shfl_xor_sync(0xFFFFFFFFu, a0d, o);
        a1d += __shfl_xor_sync(0xFFFFFFFFu, a1d, o);
    }
    if (lane == 0) {
        g_c[wid] = a0s; g_c[4 + wid] = a1s; g_c[8 + wid] = a0d; g_c[12 + wid] = a1d;
    }
    for (int i = tid; i < Tt * Hh; i += 128) {
        int t = i >> 7, d = i & 127;
        float freq = expf(-(float)(d & ~1) * (9.210340371976184f / 128.f));
        float ang = (float)t * freq;
        g_pe[i] = (d & 1) ? cosf(ang) : sinf(ang);
    }
}

// ---------------- mask + self-loop init ----------------
__global__ void mask_init(const unsigned char* __restrict__ ego) {
    int idx = blockIdx.x * 256 + threadIdx.x;
    if (idx >= ROWS) return;
    int t = idx >> 10;
    int mm = idx & 1023;
    int b = mm >> 8;
    int n = mm & 255;
    unsigned char v = ego[(b * Tt + t) * 256 + n] ? 1 : 0;
    g_m[idx] = v;
    g_cnt[idx] = v ? 1 : 0;
    g_nbr[idx * MAXD] = (unsigned short)mm;
}

// ---------------- neighbor-list build ----------------
__global__ void build_nbr(const float* __restrict__ A) {
    int tj = blockIdx.x;
    if (!g_m[tj]) return;
    int t = tj >> 10;
    int j = tj & 1023;
    int i0 = threadIdx.x * 4;
    float4 a = *(const float4*)(A + (size_t)tj * 1024 + i0);
    float av[4] = {a.x, a.y, a.z, a.w};
#pragma unroll
    for (int e = 0; e < 4; e++) {
        int i = i0 + e;
        if (i == j) continue;
        int ti = (t << 10) + i;
        if (av[e] != 0.f && g_m[ti]) {
            int pos = atomicAdd(&g_cnt[ti], 1);
            if (pos < MAXD) g_nbr[(size_t)ti * MAXD + pos] = (unsigned short)j;
        }
    }
}

// ---------------- GAT layer-0 ----------------
__global__ void gat0(const float* __restrict__ x, const float* __restrict__ W) {
    int idx = blockIdx.x * 256 + threadIdx.x;
    int row = idx >> 9;
    int c = idx & 511;
    float x0 = x[row * 2], x1 = x[row * 2 + 1];
    g_hh[idx] = __float2half(x0 * W[c] + x1 * W[512 + c]);
    if (c < 8) {
        int hh = c & 3;
        int isd = c >> 2;
        float v = x0 * g_c[hh + isd * 8] + x1 * g_c[hh + 4 + isd * 8];
        if (isd == 0) g_ss[row * 4 + hh] = v;
        else g_sd[row * 4 + hh] = v;
    }
}

// ---------------- sparse segment-softmax + aggregation ----------------
__global__ void gat_agg(const float* __restrict__ bias, __half* __restrict__ xh) {
    int row = blockIdx.x;
    int tid = threadIdx.x;
    if (!g_m[row]) {
        xh[(size_t)row * 128 + tid] = __float2half(0.f);
        return;
    }
    int t = row >> 10;

    __shared__ unsigned short nb[MAXD];
    __shared__ float w[4][MAXD];

    int cnt = g_cnt[row];
    if (cnt > MAXD) cnt = MAXD;
    if (tid < cnt) nb[tid] = g_nbr[(size_t)row * MAXD + tid];

    if (tid < cnt) {
        int jr = (t << 10) + nb[tid];
#pragma unroll
        for (int hh = 0; hh < 4; hh++) {
            float z = g_sd[row * 4 + hh] + g_ss[jr * 4 + hh];
            w[hh][tid] = (z > 0.f) ? z : 0.2f * z;
        }
    } else {
#pragma unroll
        for (int hh = 0; hh < 4; hh++) w[hh][tid] = -INFINITY;
    }
    __syncthreads();

    {
        int wh = tid >> 5, lane = tid & 31;
        float v0 = w[wh][lane], v1 = w[wh][lane + 32], v2 = w[wh][lane + 64], v3 = w[wh][lane + 96];
        float mx = fmaxf(fmaxf(v0, v1), fmaxf(v2, v3));
#pragma unroll
        for (int o = 16; o; o >>= 1) mx = fmaxf(mx, __shfl_xor_sync(0xFFFFFFFFu, mx, o));
        float e0 = expf(v0 - mx), e1 = expf(v1 - mx), e2 = expf(v2 - mx), e3 = expf(v3 - mx);
        float s = e0 + e1 + e2 + e3;
#pragma unroll
        for (int o = 16; o; o >>= 1) s += __shfl_xor_sync(0xFFFFFFFFu, s, o);
        float inv = 1.f / s;
        w[wh][lane] = e0 * inv;
        w[wh][lane + 32] = e1 * inv;
        w[wh][lane + 64] = e2 * inv;
        w[wh][lane + 96] = e3 * inv;
    }
    __syncthreads();

    float acc0 = 0.f, acc1 = 0.f, acc2 = 0.f, acc3 = 0.f;
    const __half* hb = g_hh + (((size_t)(t << 10)) << 9) + tid;
    int j = 0;
    for (; j + 4 <= cnt; j += 4) {
        const __half* p0 = hb + ((size_t)nb[j] << 9);
        const __half* p1 = hb + ((size_t)nb[j + 1] << 9);
        const __half* p2 = hb + ((size_t)nb[j + 2] << 9);
        const __half* p3 = hb + ((size_t)nb[j + 3] << 9);
#pragma unroll
        for (int hh = 0; hh < 4; hh++) {
            acc0 += w[hh][j] * __half2float(p0[hh << 7]);
            acc1 += w[hh][j + 1] * __half2float(p1[hh << 7]);
            acc2 += w[hh][j + 2] * __half2float(p2[hh << 7]);
            acc3 += w[hh][j + 3] * __half2float(p3[hh << 7]);
        }
    }
    for (; j < cnt; j++) {
        const __half* p0 = hb + ((size_t)nb[j] << 9);
#pragma unroll
        for (int hh = 0; hh < 4; hh++) acc0 += w[hh][j] * __half2float(p0[hh << 7]);
    }
    float o = (acc0 + acc1 + acc2 + acc3) * 0.25f + bias[tid];
    o = fmaxf(o, 0.f);
    xh[(size_t)row * 128 + tid] = __float2half_rn(o);
}

// ---------------- transpose to sequence layout + PE ----------------
__global__ void to_seq(const __half* __restrict__ xh) {
    int idx = blockIdx.x * 256 + threadIdx.x;
    int row = idx >> 7;
    int d = idx & 127;
    int t = row >> 10;
    int mm = row & 1023;
    float x = __half2float(xh[idx]);
    float v = x + g_pe[t * 128 + d];
    size_t sidx = ((size_t)mm * Tt + t) * Hh + d;
    g_xs[sidx] = v;
    g_xsh[sidx] = __float2half_rn(v);
}

// ---------------- per-sequence attention (fp16 QKV in, fp16 out) ----------------
__global__ void attn_kernel(const __half* __restrict__ QKV, __half* __restrict__ Oh) {
    __shared__ float sq[16][128], sk[16][128], sv[16][128];
    int m = blockIdx.x;
    int tid = threadIdx.x;
    size_t base = (size_t)m * 16 * 384;
    for (int idx = tid; idx < 2048; idx += 128) {
        int t = idx >> 7, d = idx & 127;
        size_t p = base + (size_t)t * 384 + d;
        sq[t][d] = __half2float(QKV[p]);
        sk[t][d] = __half2float(QKV[p + 128]);
        sv[t][d] = __half2float(QKV[p + 256]);
    }
    __syncthreads();
    int h = tid >> 5;
    int tq = (tid >> 1) & 15;
    int half = tid & 1;
    const float scale = 0.17677669529663687f;
    float sc[16];
    float mx = -1e30f;
#pragma unroll
    for (int tk = 0; tk < 16; tk++) {
        float s = 0.f;
#pragma unroll
        for (int dd = 0; dd < 16; dd++) {
            int d = half * 16 + dd;
            s += sq[tq][h * 32 + d] * sk[tk][h * 32 + d];
        }
        s += __shfl_xor_sync(0xFFFFFFFFu, s, 1);
        s *= scale;
        sc[tk] = s;
        mx = fmaxf(mx, s);
    }
    float sum = 0.f;
#pragma unroll
    for (int tk = 0; tk < 16; tk++) { sc[tk] = expf(sc[tk] - mx); sum += sc[tk]; }
    float inv = 1.f / sum;
    size_t ob = (size_t)m * 16 * 128 + (size_t)tq * 128 + h * 32 + half * 16;
#pragma unroll
    for (int dd = 0; dd < 16; dd++) {
        int d = half * 16 + dd;
        float o = 0.f;
#pragma unroll
        for (int tk = 0; tk < 16; tk++) o += sc[tk] * sv[tk][h * 32 + d];
        Oh[ob + dd] = __float2half_rn(o * inv);
    }
}

// ---------------- launcher ----------------
extern "C" void kernel_launch(void* const* d_in, const int* in_sizes, int n_in,
                              void* d_out, int out_size) {
    const unsigned char* ego = (const unsigned char*)d_in[0];
    const float* positions  = (const float*)d_in[1];
    const float* adjacency  = (const float*)d_in[2];
    const float* gat1_W     = (const float*)d_in[3];
    const float* gat1_asrc  = (const float*)d_in[4];
    const float* gat1_adst  = (const float*)d_in[5];
    const float* gat1_b     = (const float*)d_in[6];
    const float* gatW       = (const float*)d_in[7];
    const float* gat_asrc   = (const float*)d_in[8];
    const float* gat_adst   = (const float*)d_in[9];
    const float* gat_b      = (const float*)d_in[10];
    const float* Wqkv       = (const float*)d_in[11];
    const float* bqkv       = (const float*)d_in[12];
    const float* Wo         = (const float*)d_in[13];
    const float* bo         = (const float*)d_in[14];
    const float* ln1_s      = (const float*)d_in[15];
    const float* ln1_b      = (const float*)d_in[16];
    const float* ln2_s      = (const float*)d_in[17];
    const float* ln2_b      = (const float*)d_in[18];
    const float* Wff1       = (const float*)d_in[19];
    const float* bff1       = (const float*)d_in[20];
    const float* Wff2       = (const float*)d_in[21];
    const float* bff2       = (const float*)d_in[22];
    float* out = (float*)d_out;

    float *xs, *ss, *sd;
    __half *qkv, *hh, *w16, *xa, *xb, *xsh, *atth, *ffh;
    cudaGetSymbolAddress((void**)&qkv,  g_qkv);
    cudaGetSymbolAddress((void**)&hh,   g_hh);
    cudaGetSymbolAddress((void**)&xs,   g_xs);
    cudaGetSymbolAddress((void**)&ss,   g_ss);
    cudaGetSymbolAddress((void**)&sd,   g_sd);
    cudaGetSymbolAddress((void**)&w16,  g_w16);
    cudaGetSymbolAddress((void**)&xa,   g_xa);
    cudaGetSymbolAddress((void**)&xb,   g_xb);
    cudaGetSymbolAddress((void**)&xsh,  g_xsh);
    cudaGetSymbolAddress((void**)&atth, g_atth);
    cudaGetSymbolAddress((void**)&ffh,  g_ffh);

    cudaFuncSetAttribute(gemm_tc<0, false, true,  false>, cudaFuncAttributeMaxDynamicSharedMemorySize, GSM_TOTAL);
    cudaFuncSetAttribute(gemm_tc<0, false, false, false>, cudaFuncAttributeMaxDynamicSharedMemorySize, GSM_TOTAL);
    cudaFuncSetAttribute(gemm_tc<0, true,  false, true >, cudaFuncAttributeMaxDynamicSharedMemorySize, GSM_TOTAL);
    cudaFuncSetAttribute(gemm_tc<1, false, false, false>, cudaFuncAttributeMaxDynamicSharedMemorySize, GSM_TOTAL);

    split_weights<<<(WTOT + 255) / 256, 256>>>(gatW, Wqkv, Wo, Wff1, Wff2);
    precompute<<<1, 128>>>(gat1_W, gat1_asrc, gat1_adst);
    mask_init<<<ROWS / 256, 256>>>(ego);
    build_nbr<<<ROWS, 256>>>(adjacency);

    // GAT layer 0 (FIN=2)
    gat0<<<ROWS * 512 / 256, 256>>>(positions, gat1_W);
    gat_agg<<<ROWS, 128>>>(gat1_b, xa);

    // GAT layers 1..5
    __half *cur = xa, *nxt = xb;
    for (int i = 0; i < 5; i++) {
        dim3 gp(4, ROWS / 128);
        gemm_tc<0, false, true, false><<<gp, 256, GSM_TOTAL>>>(
            cur, w16 + OFF_GAT + (size_t)i * 65536,
            nullptr, nullptr, nullptr, nullptr, hh,
            gat_asrc + i * 512, gat_adst + i * 512, ss, sd, nullptr, nullptr, 512, 128);
        gat_agg<<<ROWS, 128>>>(gat_b + i * 128, nxt);
        __half* t0 = cur; cur = nxt; nxt = t0;
    }

    to_seq<<<ROWS * 128 / 256, 256>>>(cur);

    dim3 g1(1, ROWS / 128);
    dim3 g2(4, ROWS / 128);
    dim3 gq(3, ROWS / 128);
    for (int l = 0; l < NL_TR; l++) {
        // QKV -> fp16 packed
        size_t oq = OFF_QKV + (size_t)l * 49152;
        gemm_tc<0, false, false, false><<<gq, 256, GSM_TOTAL>>>(
            xsh, w16 + oq,
            bqkv + l * 384, nullptr, nullptr, nullptr, qkv,
            nullptr, nullptr, nullptr, nullptr, nullptr, nullptr, 384, 128);
        attn_kernel<<<Mm, 128>>>(qkv, atth);
        // Wo + LN1 -> xs fp32 + fp16
        size_t owo = OFF_WO + (size_t)l * 16384;
        gemm_tc<0, true, false, true><<<g1, 256, GSM_TOTAL>>>(
            atth, w16 + owo,
            bo + l * 128, xs, xs, xsh, nullptr,
            nullptr, nullptr, nullptr, nullptr,
            ln1_s + l * 128, ln1_b + l * 128, 128, 128);
        // FF1 + ReLU -> fp16
        size_t of1 = OFF_FF1 + (size_t)l * 65536;
        gemm_tc<1, false, false, false><<<g2, 256, GSM_TOTAL>>>(
            xsh, w16 + of1,
            bff1 + l * 512, nullptr, nullptr, ffh, nullptr,
            nullptr, nullptr, nullptr, nullptr, nullptr, nullptr, 512, 128);
        // FF2 + LN2
        size_t of2 = OFF_FF2 + (size_t)l * 65536;
        if (l == NL_TR - 1) {
            gemm_tc<0, true, false, true><<<g1, 256, GSM_TOTAL>>>(
                ffh, w16 + of2,
                bff2 + l * 128, xs, out, nullptr, nullptr,
                nullptr, nullptr, nullptr, nullptr,
                ln2_s + l * 128, ln2_b + l * 128, 128, 512);
        } else {
            gemm_tc<0, true, false, true><<<g1, 256, GSM_TOTAL>>>(
                ffh, w16 + of2,
                bff2 + l * 128, xs, xs, xsh, nullptr,
                nullptr, nullptr, nullptr, nullptr,
                ln2_s + l * 128, ln2_b + l * 128, 128, 512);
        }
    }
}

// round 13
// speedup vs baseline: 1.8791x; 1.0393x over previous
#include <cuda_runtime.h>
#include <cuda_bf16.h>
#include <cuda_fp16.h>
#include <math.h>

// Problem dims
#define Tt 16
#define Mm 1024
#define Hh 128
#define ROWS 16384
#define MAXD 128
#define NL_TR 5

// ---------------- scratch (device globals; no allocations) ----------------
__device__ __half g_qkv[ROWS * 384];       // transformer QKV fp16
__device__ __half g_hh[ROWS * 512];        // GAT projections fp16, head-major
__device__ float g_ss[ROWS * 4];
__device__ float g_sd[ROWS * 4];
__device__ unsigned char g_m[ROWS];
__device__ int g_cnt[ROWS];
__device__ unsigned short g_nbr[ROWS * MAXD];
__device__ float g_xs[ROWS * Hh];          // residual stream fp32
__device__ float g_c[16];
__device__ float g_pe[Tt * Hh];
__device__ __half g_xa[ROWS * Hh];
__device__ __half g_xb[ROWS * Hh];
__device__ __half g_xsh[ROWS * Hh];        // xs fp16 (GEMM A)
__device__ __half g_atth[ROWS * Hh];       // attention out fp16
__device__ __half g_ffh[ROWS * 512];       // FF1 out fp16

#define WTOT 1310720
#define OFF_GAT 0
#define OFF_QKV 327680
#define OFF_WO  573440
#define OFF_FF1 655360
#define OFF_FF2 983040
__device__ __half g_w16[WTOT];             // weights fp16 [N,K]

__device__ __forceinline__ unsigned smem_u32(const void* p) {
    unsigned a;
    asm("{ .reg .u64 t; cvta.to.shared.u64 t, %1; cvt.u32.u64 %0, t; }" : "=r"(a) : "l"(p));
    return a;
}
__device__ __forceinline__ void ldmat4(unsigned& r0, unsigned& r1, unsigned& r2, unsigned& r3, unsigned addr) {
    asm volatile("ldmatrix.sync.aligned.m8n8.x4.shared.b16 {%0,%1,%2,%3}, [%4];"
        : "=r"(r0), "=r"(r1), "=r"(r2), "=r"(r3) : "r"(addr));
}
__device__ __forceinline__ void mma16816(float* c, unsigned a0, unsigned a1, unsigned a2, unsigned a3,
                                         unsigned b0, unsigned b1) {
    asm volatile("mma.sync.aligned.m16n8k16.row.col.f32.f16.f16.f32 "
        "{%0,%1,%2,%3}, {%4,%5,%6,%7}, {%8,%9}, {%0,%1,%2,%3};"
        : "+f"(c[0]), "+f"(c[1]), "+f"(c[2]), "+f"(c[3])
        : "r"(a0), "r"(a1), "r"(a2), "r"(a3), "r"(b0), "r"(b1));
}
__device__ __forceinline__ void cpa16(unsigned dst, const void* src) {
    asm volatile("cp.async.ca.shared.global [%0], [%1], 16;" :: "r"(dst), "l"(src));
}
#define CPA_COMMIT() asm volatile("cp.async.commit_group;" ::: "memory")
#define CPA_WAIT1() asm volatile("cp.async.wait_group 1;" ::: "memory")
#define CPA_WAIT0() asm volatile("cp.async.wait_group 0;" ::: "memory")

__device__ __forceinline__ unsigned packh_hi2(float a, float b) {
    __half2 h = __floats2half2_rn(a, b);
    return *(unsigned*)&h;
}

// SMEM: 2 stages x 2 planes (A, B), each 128 rows x 32 fp16 (80B stride)
#define TROW 80
#define PBUF (128 * TROW)
#define STAGE (2 * PBUF)
#define P_A 0
#define P_B PBUF
#define GSM_TOTAL 67584

// ---------------- HMMA GEMM: A fp16, B fp16, single-MMA ----------------
template <int ACT, bool RESID, bool SCORES, bool LNORM>
__global__ void __launch_bounds__(256, 2)
gemm_tc(const __half* __restrict__ Ah, const __half* __restrict__ B16,
        const float* __restrict__ bias, const float* __restrict__ Rr,
        float* __restrict__ C, __half* __restrict__ Ch,
        __half* __restrict__ H16,
        const float* __restrict__ asrc, const float* __restrict__ adst,
        float* __restrict__ gss, float* __restrict__ gsd,
        const float* __restrict__ ls, const float* __restrict__ lb, int Nt, int Kt) {
    extern __shared__ char smem[];
    const unsigned sb = smem_u32(smem);
    const int tid = threadIdx.x;
    const int wid = tid >> 5, lane = tid & 31;
    const int wr = wid >> 1, wc = wid & 1;
    const int row0 = blockIdx.y * 128;
    const int col0 = blockIdx.x * 128;

    float acc[2][8][4];
#pragma unroll
    for (int mt = 0; mt < 2; mt++)
#pragma unroll
        for (int nt = 0; nt < 8; nt++)
#pragma unroll
            for (int e = 0; e < 4; e++) acc[mt][nt][e] = 0.f;

    const int ltile = lane >> 3, lrow = lane & 7;
    const int nch = Kt >> 5;

#define LOAD_CHUNK(cidx, s) do { \
    unsigned base = sb + (s) * STAGE; \
    _Pragma("unroll") \
    for (int j = 0; j < 2; j++) { \
        int i = tid + j * 256; \
        int rr = i >> 2, qq = i & 3; \
        unsigned off = (unsigned)(rr * TROW + qq * 16); \
        size_t ga = (size_t)(row0 + rr) * Kt + (cidx) * 32 + qq * 8; \
        size_t gb = (size_t)(col0 + rr) * Kt + (cidx) * 32 + qq * 8; \
        cpa16(base + P_A + off, Ah + ga); \
        cpa16(base + P_B + off, B16 + gb); \
    } \
} while (0)

    LOAD_CHUNK(0, 0);
    CPA_COMMIT();

    for (int c = 0; c < nch; c++) {
        if (c + 1 < nch) {
            LOAD_CHUNK(c + 1, (c + 1) & 1);
            CPA_COMMIT();
            CPA_WAIT1();
        } else {
            CPA_WAIT0();
        }
        __syncthreads();
        unsigned base = sb + (c & 1) * STAGE;
#pragma unroll
        for (int ks = 0; ks < 2; ks++) {
            unsigned ah[2][4];
#pragma unroll
            for (int mt = 0; mt < 2; mt++) {
                int row = wr * 32 + mt * 16 + lrow + (ltile & 1) * 8;
                int kcol = ks * 16 + (ltile >> 1) * 8;
                unsigned off = (unsigned)(row * TROW + kcol * 2);
                ldmat4(ah[mt][0], ah[mt][1], ah[mt][2], ah[mt][3], base + P_A + off);
            }
#pragma unroll
            for (int g = 0; g < 4; g++) {
                int n = wc * 64 + g * 16 + lrow + (ltile >> 1) * 8;
                int kcol = ks * 16 + (ltile & 1) * 8;
                unsigned off = (unsigned)(n * TROW + kcol * 2);
                unsigned bh[4];
                ldmat4(bh[0], bh[1], bh[2], bh[3], base + P_B + off);
#pragma unroll
                for (int mt = 0; mt < 2; mt++)
#pragma unroll
                    for (int half = 0; half < 2; half++) {
                        mma16816(acc[mt][g * 2 + half],
                                 ah[mt][0], ah[mt][1], ah[mt][2], ah[mt][3],
                                 bh[half * 2], bh[half * 2 + 1]);
                    }
            }
        }
        __syncthreads();
    }
#undef LOAD_CHUNK

    float* stage = (float*)smem;
#pragma unroll
    for (int mt = 0; mt < 2; mt++)
#pragma unroll
        for (int nt = 0; nt < 8; nt++) {
            int row = wr * 32 + mt * 16 + (lane >> 2);
            int col = wc * 64 + nt * 8 + (lane & 3) * 2;
            float2 v0 = make_float2(acc[mt][nt][0], acc[mt][nt][1]);
            float2 v1 = make_float2(acc[mt][nt][2], acc[mt][nt][3]);
            *(float2*)(stage + (size_t)row * 132 + col) = v0;
            *(float2*)(stage + (size_t)(row + 8) * 132 + col) = v1;
        }
    __syncthreads();

    if (LNORM) {
        const int c = lane * 4;
        float4 bb = *(const float4*)(bias + c);
        float4 sv = *(const float4*)(ls + c);
        float4 bv = *(const float4*)(lb + c);
#pragma unroll 4
        for (int rr = 0; rr < 16; rr++) {
            int r = wid * 16 + rr;
            float4 v = *(float4*)(stage + (size_t)r * 132 + c);
            float4 res = *(const float4*)(Rr + (size_t)(row0 + r) * 128 + c);
            v.x += bb.x + res.x; v.y += bb.y + res.y;
            v.z += bb.z + res.z; v.w += bb.w + res.w;
            float s = v.x + v.y + v.z + v.w;
#pragma unroll
            for (int o = 16; o; o >>= 1) s += __shfl_xor_sync(0xFFFFFFFFu, s, o);
            float mean = s * (1.f / 128.f);
            float dx = v.x - mean, dy = v.y - mean, dz = v.z - mean, dw = v.w - mean;
            float qq = dx * dx + dy * dy + dz * dz + dw * dw;
#pragma unroll
            for (int o = 16; o; o >>= 1) qq += __shfl_xor_sync(0xFFFFFFFFu, qq, o);
            float rstd = rsqrtf(qq * (1.f / 128.f) + 1e-5f);
            float4 ov;
            ov.x = dx * rstd * sv.x + bv.x;
            ov.y = dy * rstd * sv.y + bv.y;
            ov.z = dz * rstd * sv.z + bv.z;
            ov.w = dw * rstd * sv.w + bv.w;
            if (C) *(float4*)(C + (size_t)(row0 + r) * 128 + c) = ov;
            if (Ch) {
                uint2 uh;
                uh.x = packh_hi2(ov.x, ov.y); uh.y = packh_hi2(ov.z, ov.w);
                *(uint2*)(Ch + (size_t)(row0 + r) * 128 + c) = uh;
            }
        }
    } else {
        for (int i = tid; i < 128 * 32; i += 256) {
            int r = i >> 5, q = i & 31;
            int c = q * 4;
            float4 v = *(float4*)(stage + (size_t)r * 132 + c);
            if (bias) {
                v.x += bias[col0 + c];
                v.y += bias[col0 + c + 1];
                v.z += bias[col0 + c + 2];
                v.w += bias[col0 + c + 3];
            }
            if (RESID) {
                float4 rr = *(const float4*)(Rr + (size_t)(row0 + r) * Nt + col0 + c);
                v.x += rr.x; v.y += rr.y; v.z += rr.z; v.w += rr.w;
            }
            if (ACT == 1) {
                v.x = fmaxf(v.x, 0.f); v.y = fmaxf(v.y, 0.f);
                v.z = fmaxf(v.z, 0.f); v.w = fmaxf(v.w, 0.f);
            }
            if (C) *(float4*)(C + (size_t)(row0 + r) * Nt + col0 + c) = v;
            if (H16) {
                uint2 u;
                u.x = packh_hi2(v.x, v.y);
                u.y = packh_hi2(v.z, v.w);
                *(uint2*)(H16 + (size_t)(row0 + r) * Nt + col0 + c) = u;
            }
            if (Ch) {
                uint2 uh;
                uh.x = packh_hi2(v.x, v.y); uh.y = packh_hi2(v.z, v.w);
                *(uint2*)(Ch + (size_t)(row0 + r) * Nt + col0 + c) = uh;
            }
        }
    }

    if (SCORES && tid < 128) {
        int r = tid;
        float s1 = 0.f, s2 = 0.f;
        const float* as = asrc + col0;
        const float* ad = adst + col0;
        const float* sp = stage + (size_t)r * 132;
#pragma unroll 8
        for (int c = 0; c < 128; c++) {
            float hv = sp[c];
            s1 += hv * as[c];
            s2 += hv * ad[c];
        }
        gss[(size_t)(row0 + r) * 4 + blockIdx.x] = s1;
        gsd[(size_t)(row0 + r) * 4 + blockIdx.x] = s2;
    }
}

// ---------------- weight conversion to fp16 [N,K] ----------------
__global__ void split_weights(const float* __restrict__ gatW, const float* __restrict__ Wqkv,
                              const float* __restrict__ Wo, const float* __restrict__ Wff1,
                              const float* __restrict__ Wff2) {
    int idx = blockIdx.x * 256 + threadIdx.x;
    if (idx >= WTOT) return;
    float v;
    if (idx < OFF_QKV) {
        int i = idx >> 16, r = idx & 65535;
        int n = r >> 7, k = r & 127;
        v = gatW[(i << 16) + k * 512 + n];
    } else if (idx < OFF_WO) {
        int r0 = idx - OFF_QKV;
        int l = r0 / 49152;
        int rem = r0 - l * 49152;
        int n = rem >> 7, k = rem & 127;
        int s = n >> 7, nc = n & 127;
        v = Wqkv[((l * 3 + s) << 14) + k * 128 + nc];
    } else if (idx < OFF_FF1) {
        int r0 = idx - OFF_WO;
        int i = r0 >> 14, r = r0 & 16383;
        int n = r >> 7, k = r & 127;
        v = Wo[(i << 14) + k * 128 + n];
    } else if (idx < OFF_FF2) {
        int r0 = idx - OFF_FF1;
        int i = r0 >> 16, r = r0 & 65535;
        int n = r >> 7, k = r & 127;
        v = Wff1[(i << 16) + k * 512 + n];
    } else {
        int r0 = idx - OFF_FF2;
        int i = r0 >> 16, r = r0 & 65535;
        int n = r >> 9, k = r & 511;
        v = Wff2[(i << 16) + k * 128 + n];
    }
    g_w16[idx] = __float2half_rn(v);
}

// ---------------- tiny precompute ----------------
__global__ void precompute(const float* __restrict__ W, const float* __restrict__ asrc,
                           const float* __restrict__ adst) {
    int tid = threadIdx.x;
    int wid = tid >> 5, lane = tid & 31;
    float a0s = 0.f, a1s = 0.f, a0d = 0.f, a1d = 0.f;
    for (int d = lane; d < 128; d += 32) {
        int c = wid * 128 + d;
        float w0 = W[c], w1 = W[512 + c], as = asrc[c], ad = adst[c];
        a0s += w0 * as; a1s += w1 * as; a0d += w0 * ad; a1d += w1 * ad;
    }
#pragma unroll
    for (int o = 16; o; o >>= 1) {
        a0s += __shfl_xor_sync(0xFFFFFFFFu, a0s, o);
        a1s += __shfl_xor_sync(0xFFFFFFFFu, a1s, o);
        a0d += __shfl_xor_sync(0xFFFFFFFFu, a0d, o);
        a1d += __shfl_xor_sync(0xFFFFFFFFu, a1d, o);
    }
    if (lane == 0) {
        g_c[wid] = a0s; g_c[4 + wid] = a1s; g_c[8 + wid] = a0d; g_c[12 + wid] = a1d;
    }
    for (int i = tid; i < Tt * Hh; i += 128) {
        int t = i >> 7, d = i & 127;
        float freq = expf(-(float)(d & ~1) * (9.210340371976184f / 128.f));
        float ang = (float)t * freq;
        g_pe[i] = (d & 1) ? cosf(ang) : sinf(ang);
    }
}

// ---------------- mask + self-loop init ----------------
__global__ void mask_init(const unsigned char* __restrict__ ego) {
    int idx = blockIdx.x * 256 + threadIdx.x;
    if (idx >= ROWS) return;
    int t = idx >> 10;
    int mm = idx & 1023;
    int b = mm >> 8;
    int n = mm & 255;
    unsigned char v = ego[(b * Tt + t) * 256 + n] ? 1 : 0;
    g_m[idx] = v;
    g_cnt[idx] = v ? 1 : 0;
    g_nbr[idx * MAXD] = (unsigned short)mm;
}

// ---------------- neighbor-list build ----------------
__global__ void build_nbr(const float* __restrict__ A) {
    int tj = blockIdx.x;
    if (!g_m[tj]) return;
    int t = tj >> 10;
    int j = tj & 1023;
    int i0 = threadIdx.x * 4;
    float4 a = *(const float4*)(A + (size_t)tj * 1024 + i0);
    float av[4] = {a.x, a.y, a.z, a.w};
#pragma unroll
    for (int e = 0; e < 4; e++) {
        int i = i0 + e;
        if (i == j) continue;
        int ti = (t << 10) + i;
        if (av[e] != 0.f && g_m[ti]) {
            int pos = atomicAdd(&g_cnt[ti], 1);
            if (pos < MAXD) g_nbr[(size_t)ti * MAXD + pos] = (unsigned short)j;
        }
    }
}

// ---------------- GAT layer-0 ----------------
__global__ void gat0(const float* __restrict__ x, const float* __restrict__ W) {
    int idx = blockIdx.x * 256 + threadIdx.x;
    int row = idx >> 9;
    int c = idx & 511;
    float x0 = x[row * 2], x1 = x[row * 2 + 1];
    g_hh[idx] = __float2half(x0 * W[c] + x1 * W[512 + c]);
    if (c < 8) {
        int hh = c & 3;
        int isd = c >> 2;
        float v = x0 * g_c[hh + isd * 8] + x1 * g_c[hh + 4 + isd * 8];
        if (isd == 0) g_ss[row * 4 + hh] = v;
        else g_sd[row * 4 + hh] = v;
    }
}

// ---------------- sparse segment-softmax + aggregation (vectorized LDG.128 gather) ----------------
// TOSEQ: fuse transpose-to-sequence + PE, writing g_xs / g_xsh directly.
template <bool TOSEQ>
__global__ void gat_agg(const float* __restrict__ bias, __half* __restrict__ xh) {
    int row = blockIdx.x;
    int tid = threadIdx.x;
    int t = row >> 10;
    int mm = row & 1023;
    bool alive = g_m[row] != 0;

    __shared__ unsigned short nb[MAXD];
    __shared__ float w[4][MAXD];
    __shared__ float part[128][9];

    float outv = 0.f;
    if (alive) {
        int cnt = g_cnt[row];
        if (cnt > MAXD) cnt = MAXD;
        if (tid < cnt) nb[tid] = g_nbr[(size_t)row * MAXD + tid];

        if (tid < cnt) {
            int jr = (t << 10) + nb[tid];
#pragma unroll
            for (int hh = 0; hh < 4; hh++) {
                float z = g_sd[row * 4 + hh] + g_ss[jr * 4 + hh];
                w[hh][tid] = (z > 0.f) ? z : 0.2f * z;
            }
        } else {
#pragma unroll
            for (int hh = 0; hh < 4; hh++) w[hh][tid] = -INFINITY;
        }
        __syncthreads();

        {
            int wh = tid >> 5, lane = tid & 31;
            float v0 = w[wh][lane], v1 = w[wh][lane + 32], v2 = w[wh][lane + 64], v3 = w[wh][lane + 96];
            float mx = fmaxf(fmaxf(v0, v1), fmaxf(v2, v3));
#pragma unroll
            for (int o = 16; o; o >>= 1) mx = fmaxf(mx, __shfl_xor_sync(0xFFFFFFFFu, mx, o));
            float e0 = expf(v0 - mx), e1 = expf(v1 - mx), e2 = expf(v2 - mx), e3 = expf(v3 - mx);
            float s = e0 + e1 + e2 + e3;
#pragma unroll
            for (int o = 16; o; o >>= 1) s += __shfl_xor_sync(0xFFFFFFFFu, s, o);
            float inv = 1.f / s;
            w[wh][lane] = e0 * inv;
            w[wh][lane + 32] = e1 * inv;
            w[wh][lane + 64] = e2 * inv;
            w[wh][lane + 96] = e3 * inv;
        }
        __syncthreads();

        // gather: thread (nh, h, dsl) loads uint4 (8 fp16) per 2 neighbors
        int h = (tid >> 4) & 3, dsl = tid & 15, nh = tid >> 6;
        float acc[8];
#pragma unroll
        for (int e = 0; e < 8; e++) acc[e] = 0.f;
        const __half* tb = g_hh + (((size_t)(t << 10)) << 9) + h * 128 + dsl * 8;
        for (int j = nh; j < cnt; j += 2) {
            float wj = w[h][j];
            uint4 q = *(const uint4*)(tb + ((size_t)nb[j] << 9));
            __half2* hp = (__half2*)&q;
#pragma unroll
            for (int e = 0; e < 4; e++) {
                float2 f = __half22float2(hp[e]);
                acc[2 * e] += wj * f.x;
                acc[2 * e + 1] += wj * f.y;
            }
        }
#pragma unroll
        for (int e = 0; e < 8; e++) part[tid][e] = acc[e];
        __syncthreads();

        // final reduce: thread = output d; sum over (nh, h)
        int dsl2 = tid >> 3, e2 = tid & 7;
        float s = 0.f;
#pragma unroll
        for (int k = 0; k < 8; k++) {
            int c = (k & 1) * 64 + (k >> 1) * 16 + dsl2;
            s += part[c][e2];
        }
        outv = fmaxf(s * 0.25f + bias[tid], 0.f);
    }

    if (TOSEQ) {
        float v = outv + g_pe[t * 128 + tid];
        size_t sidx = ((size_t)mm * Tt + t) * Hh + tid;
        g_xs[sidx] = v;
        g_xsh[sidx] = __float2half_rn(v);
    } else {
        xh[(size_t)row * 128 + tid] = __float2half_rn(outv);
    }
}

// ---------------- per-sequence attention (fp16 QKV in, fp16 out) ----------------
__global__ void attn_kernel(const __half* __restrict__ QKV, __half* __restrict__ Oh) {
    __shared__ float sq[16][128], sk[16][128], sv[16][128];
    int m = blockIdx.x;
    int tid = threadIdx.x;
    size_t base = (size_t)m * 16 * 384;
    for (int idx = tid; idx < 2048; idx += 128) {
        int t = idx >> 7, d = idx & 127;
        size_t p = base + (size_t)t * 384 + d;
        sq[t][d] = __half2float(QKV[p]);
        sk[t][d] = __half2float(QKV[p + 128]);
        sv[t][d] = __half2float(QKV[p + 256]);
    }
    __syncthreads();
    int h = tid >> 5;
    int tq = (tid >> 1) & 15;
    int half = tid & 1;
    const float scale = 0.17677669529663687f;
    float sc[16];
    float mx = -1e30f;
#pragma unroll
    for (int tk = 0; tk < 16; tk++) {
        float s = 0.f;
#pragma unroll
        for (int dd = 0; dd < 16; dd++) {
            int d = half * 16 + dd;
            s += sq[tq][h * 32 + d] * sk[tk][h * 32 + d];
        }
        s += __shfl_xor_sync(0xFFFFFFFFu, s, 1);
        s *= scale;
        sc[tk] = s;
        mx = fmaxf(mx, s);
    }
    float sum = 0.f;
#pragma unroll
    for (int tk = 0; tk < 16; tk++) { sc[tk] = expf(sc[tk] - mx); sum += sc[tk]; }
    float inv = 1.f / sum;
    size_t ob = (size_t)m * 16 * 128 + (size_t)tq * 128 + h * 32 + half * 16;
#pragma unroll
    for (int dd = 0; dd < 16; dd++) {
        int d = half * 16 + dd;
        float o = 0.f;
#pragma unroll
        for (int tk = 0; tk < 16; tk++) o += sc[tk] * sv[tk][h * 32 + d];
        Oh[ob + dd] = __float2half_rn(o * inv);
    }
}

// ---------------- launcher ----------------
extern "C" void kernel_launch(void* const* d_in, const int* in_sizes, int n_in,
                              void* d_out, int out_size) {
    const unsigned char* ego = (const unsigned char*)d_in[0];
    const float* positions  = (const float*)d_in[1];
    const float* adjacency  = (const float*)d_in[2];
    const float* gat1_W     = (const float*)d_in[3];
    const float* gat1_asrc  = (const float*)d_in[4];
    const float* gat1_adst  = (const float*)d_in[5];
    const float* gat1_b     = (const float*)d_in[6];
    const float* gatW       = (const float*)d_in[7];
    const float* gat_asrc   = (const float*)d_in[8];
    const float* gat_adst   = (const float*)d_in[9];
    const float* gat_b      = (const float*)d_in[10];
    const float* Wqkv       = (const float*)d_in[11];
    const float* bqkv       = (const float*)d_in[12];
    const float* Wo         = (const float*)d_in[13];
    const float* bo         = (const float*)d_in[14];
    const float* ln1_s      = (const float*)d_in[15];
    const float* ln1_b      = (const float*)d_in[16];
    const float* ln2_s      = (const float*)d_in[17];
    const float* ln2_b      = (const float*)d_in[18];
    const float* Wff1       = (const float*)d_in[19];
    const float* bff1       = (const float*)d_in[20];
    const float* Wff2       = (const float*)d_in[21];
    const float* bff2       = (const float*)d_in[22];
    float* out = (float*)d_out;

    float *xs, *ss, *sd;
    __half *qkv, *hh, *w16, *xa, *xb, *xsh, *atth, *ffh;
    cudaGetSymbolAddress((void**)&qkv,  g_qkv);
    cudaGetSymbolAddress((void**)&hh,   g_hh);
    cudaGetSymbolAddress((void**)&xs,   g_xs);
    cudaGetSymbolAddress((void**)&ss,   g_ss);
    cudaGetSymbolAddress((void**)&sd,   g_sd);
    cudaGetSymbolAddress((void**)&w16,  g_w16);
    cudaGetSymbolAddress((void**)&xa,   g_xa);
    cudaGetSymbolAddress((void**)&xb,   g_xb);
    cudaGetSymbolAddress((void**)&xsh,  g_xsh);
    cudaGetSymbolAddress((void**)&atth, g_atth);
    cudaGetSymbolAddress((void**)&ffh,  g_ffh);

    cudaFuncSetAttribute(gemm_tc<0, false, true,  false>, cudaFuncAttributeMaxDynamicSharedMemorySize, GSM_TOTAL);
    cudaFuncSetAttribute(gemm_tc<0, false, false, false>, cudaFuncAttributeMaxDynamicSharedMemorySize, GSM_TOTAL);
    cudaFuncSetAttribute(gemm_tc<0, true,  false, true >, cudaFuncAttributeMaxDynamicSharedMemorySize, GSM_TOTAL);
    cudaFuncSetAttribute(gemm_tc<1, false, false, false>, cudaFuncAttributeMaxDynamicSharedMemorySize, GSM_TOTAL);

    split_weights<<<(WTOT + 255) / 256, 256>>>(gatW, Wqkv, Wo, Wff1, Wff2);
    precompute<<<1, 128>>>(gat1_W, gat1_asrc, gat1_adst);
    mask_init<<<ROWS / 256, 256>>>(ego);
    build_nbr<<<ROWS, 256>>>(adjacency);

    // GAT layer 0 (FIN=2)
    gat0<<<ROWS * 512 / 256, 256>>>(positions, gat1_W);
    gat_agg<false><<<ROWS, 128>>>(gat1_b, xa);

    // GAT layers 1..5 (last one fuses to_seq + PE)
    __half *cur = xa, *nxt = xb;
    for (int i = 0; i < 5; i++) {
        dim3 gp(4, ROWS / 128);
        gemm_tc<0, false, true, false><<<gp, 256, GSM_TOTAL>>>(
            cur, w16 + OFF_GAT + (size_t)i * 65536,
            nullptr, nullptr, nullptr, nullptr, hh,
            gat_asrc + i * 512, gat_adst + i * 512, ss, sd, nullptr, nullptr, 512, 128);
        if (i < 4) {
            gat_agg<false><<<ROWS, 128>>>(gat_b + i * 128, nxt);
            __half* t0 = cur; cur = nxt; nxt = t0;
        } else {
            gat_agg<true><<<ROWS, 128>>>(gat_b + i * 128, nullptr);
        }
    }

    dim3 g1(1, ROWS / 128);
    dim3 g2(4, ROWS / 128);
    dim3 gq(3, ROWS / 128);
    for (int l = 0; l < NL_TR; l++) {
        size_t oq = OFF_QKV + (size_t)l * 49152;
        gemm_tc<0, false, false, false><<<gq, 256, GSM_TOTAL>>>(
            xsh, w16 + oq,
            bqkv + l * 384, nullptr, nullptr, nullptr, qkv,
            nullptr, nullptr, nullptr, nullptr, nullptr, nullptr, 384, 128);
        attn_kernel<<<Mm, 128>>>(qkv, atth);
        size_t owo = OFF_WO + (size_t)l * 16384;
        gemm_tc<0, true, false, true><<<g1, 256, GSM_TOTAL>>>(
            atth, w16 + owo,
            bo + l * 128, xs, xs, xsh, nullptr,
            nullptr, nullptr, nullptr, nullptr,
            ln1_s + l * 128, ln1_b + l * 128, 128, 128);
        size_t of1 = OFF_FF1 + (size_t)l * 65536;
        gemm_tc<1, false, false, false><<<g2, 256, GSM_TOTAL>>>(
            xsh, w16 + of1,
            bff1 + l * 512, nullptr, nullptr, ffh, nullptr,
            nullptr, nullptr, nullptr, nullptr, nullptr, nullptr, 512, 128);
        size_t of2 = OFF_FF2 + (size_t)l * 65536;
        if (l == NL_TR - 1) {
            gemm_tc<0, true, false, true><<<g1, 256, GSM_TOTAL>>>(
                ffh, w16 + of2,
                bff2 + l * 128, xs, out, nullptr, nullptr,
                nullptr, nullptr, nullptr, nullptr,
                ln2_s + l * 128, ln2_b + l * 128, 128, 512);
        } else {
            gemm_tc<0, true, false, true><<<g1, 256, GSM_TOTAL>>>(
                ffh, w16 + of2,
                bff2 + l * 128, xs, xs, xsh, nullptr,
                nullptr, nullptr, nullptr, nullptr,
                ln2_s + l * 128, ln2_b + l * 128, 128, 512);
        }
    }
}

// round 14
// speedup vs baseline: 1.9449x; 1.0350x over previous
#include <cuda_runtime.h>
#include <cuda_bf16.h>
#include <cuda_fp16.h>
#include <math.h>

// Problem dims
#define Tt 16
#define Mm 1024
#define Hh 128
#define ROWS 16384
#define MAXD 128
#define NL_TR 5

// ---------------- scratch ----------------
__device__ __half g_qkv[ROWS * 384];
__device__ __half g_hh[ROWS * 512];
__device__ float g_ss[ROWS * 4];
__device__ float g_sd[ROWS * 4];
__device__ unsigned char g_m[ROWS];
__device__ int g_cnt[ROWS];
__device__ unsigned short g_nbr[ROWS * MAXD];
__device__ float g_xs[ROWS * Hh];
__device__ float g_c[16];
__device__ float g_pe[Tt * Hh];
__device__ __half g_xa[ROWS * Hh];
__device__ __half g_xb[ROWS * Hh];
__device__ __half g_xsh[ROWS * Hh];
__device__ __half g_atth[ROWS * Hh];

#define WTOT 1310720
#define OFF_GAT 0
#define OFF_QKV 327680
#define OFF_WO  573440
#define OFF_FF1 655360
#define OFF_FF2 983040
__device__ __half g_w16[WTOT];

__device__ __forceinline__ unsigned smem_u32(const void* p) {
    unsigned a;
    asm("{ .reg .u64 t; cvta.to.shared.u64 t, %1; cvt.u32.u64 %0, t; }" : "=r"(a) : "l"(p));
    return a;
}
__device__ __forceinline__ void ldmat4(unsigned& r0, unsigned& r1, unsigned& r2, unsigned& r3, unsigned addr) {
    asm volatile("ldmatrix.sync.aligned.m8n8.x4.shared.b16 {%0,%1,%2,%3}, [%4];"
        : "=r"(r0), "=r"(r1), "=r"(r2), "=r"(r3) : "r"(addr));
}
__device__ __forceinline__ void mma16816(float* c, unsigned a0, unsigned a1, unsigned a2, unsigned a3,
                                         unsigned b0, unsigned b1) {
    asm volatile("mma.sync.aligned.m16n8k16.row.col.f32.f16.f16.f32 "
        "{%0,%1,%2,%3}, {%4,%5,%6,%7}, {%8,%9}, {%0,%1,%2,%3};"
        : "+f"(c[0]), "+f"(c[1]), "+f"(c[2]), "+f"(c[3])
        : "r"(a0), "r"(a1), "r"(a2), "r"(a3), "r"(b0), "r"(b1));
}
__device__ __forceinline__ void cpa16(unsigned dst, const void* src) {
    asm volatile("cp.async.ca.shared.global [%0], [%1], 16;" :: "r"(dst), "l"(src));
}
#define CPA_COMMIT() asm volatile("cp.async.commit_group;" ::: "memory")
#define CPA_WAIT1() asm volatile("cp.async.wait_group 1;" ::: "memory")
#define CPA_WAIT0() asm volatile("cp.async.wait_group 0;" ::: "memory")

__device__ __forceinline__ unsigned packh_hi2(float a, float b) {
    __half2 h = __floats2half2_rn(a, b);
    return *(unsigned*)&h;
}

// SMEM pipeline: planes of 128 rows x 32 fp16 (80B stride)
#define TROW 80
#define PBUF (128 * TROW)
#define STAGE (2 * PBUF)
#define P_A 0
#define P_B PBUF
#define GSM_TOTAL 67584

// ff_fused smem: [0,40960) pipeline; [40960, ...) staging 128 x 520 halves
#define FSM_STAGEA 40960
#define AROW 520
#define FSM_TOTAL (40960 + 128 * AROW * 2)   // 174080

// ---------------- HMMA GEMM: A fp16, B fp16, single-MMA ----------------
template <int ACT, bool RESID, bool SCORES, bool LNORM>
__global__ void __launch_bounds__(256, 2)
gemm_tc(const __half* __restrict__ Ah, const __half* __restrict__ B16,
        const float* __restrict__ bias, const float* __restrict__ Rr,
        float* __restrict__ C, __half* __restrict__ Ch,
        __half* __restrict__ H16,
        const float* __restrict__ asrc, const float* __restrict__ adst,
        float* __restrict__ gss, float* __restrict__ gsd,
        const float* __restrict__ ls, const float* __restrict__ lb, int Nt, int Kt) {
    extern __shared__ char smem[];
    const unsigned sb = smem_u32(smem);
    const int tid = threadIdx.x;
    const int wid = tid >> 5, lane = tid & 31;
    const int wr = wid >> 1, wc = wid & 1;
    const int row0 = blockIdx.y * 128;
    const int col0 = blockIdx.x * 128;

    float acc[2][8][4];
#pragma unroll
    for (int mt = 0; mt < 2; mt++)
#pragma unroll
        for (int nt = 0; nt < 8; nt++)
#pragma unroll
            for (int e = 0; e < 4; e++) acc[mt][nt][e] = 0.f;

    const int ltile = lane >> 3, lrow = lane & 7;
    const int nch = Kt >> 5;

#define LOAD_CHUNK(cidx, s) do { \
    unsigned base = sb + (s) * STAGE; \
    _Pragma("unroll") \
    for (int j = 0; j < 2; j++) { \
        int i = tid + j * 256; \
        int rr = i >> 2, qq = i & 3; \
        unsigned off = (unsigned)(rr * TROW + qq * 16); \
        size_t ga = (size_t)(row0 + rr) * Kt + (cidx) * 32 + qq * 8; \
        size_t gb = (size_t)(col0 + rr) * Kt + (cidx) * 32 + qq * 8; \
        cpa16(base + P_A + off, Ah + ga); \
        cpa16(base + P_B + off, B16 + gb); \
    } \
} while (0)

    LOAD_CHUNK(0, 0);
    CPA_COMMIT();

    for (int c = 0; c < nch; c++) {
        if (c + 1 < nch) {
            LOAD_CHUNK(c + 1, (c + 1) & 1);
            CPA_COMMIT();
            CPA_WAIT1();
        } else {
            CPA_WAIT0();
        }
        __syncthreads();
        unsigned base = sb + (c & 1) * STAGE;
#pragma unroll
        for (int ks = 0; ks < 2; ks++) {
            unsigned ah[2][4];
#pragma unroll
            for (int mt = 0; mt < 2; mt++) {
                int row = wr * 32 + mt * 16 + lrow + (ltile & 1) * 8;
                int kcol = ks * 16 + (ltile >> 1) * 8;
                unsigned off = (unsigned)(row * TROW + kcol * 2);
                ldmat4(ah[mt][0], ah[mt][1], ah[mt][2], ah[mt][3], base + P_A + off);
            }
#pragma unroll
            for (int g = 0; g < 4; g++) {
                int n = wc * 64 + g * 16 + lrow + (ltile >> 1) * 8;
                int kcol = ks * 16 + (ltile & 1) * 8;
                unsigned off = (unsigned)(n * TROW + kcol * 2);
                unsigned bh[4];
                ldmat4(bh[0], bh[1], bh[2], bh[3], base + P_B + off);
#pragma unroll
                for (int mt = 0; mt < 2; mt++)
#pragma unroll
                    for (int half = 0; half < 2; half++) {
                        mma16816(acc[mt][g * 2 + half],
                                 ah[mt][0], ah[mt][1], ah[mt][2], ah[mt][3],
                                 bh[half * 2], bh[half * 2 + 1]);
                    }
            }
        }
        __syncthreads();
    }
#undef LOAD_CHUNK

    float* stage = (float*)smem;
#pragma unroll
    for (int mt = 0; mt < 2; mt++)
#pragma unroll
        for (int nt = 0; nt < 8; nt++) {
            int row = wr * 32 + mt * 16 + (lane >> 2);
            int col = wc * 64 + nt * 8 + (lane & 3) * 2;
            float2 v0 = make_float2(acc[mt][nt][0], acc[mt][nt][1]);
            float2 v1 = make_float2(acc[mt][nt][2], acc[mt][nt][3]);
            *(float2*)(stage + (size_t)row * 132 + col) = v0;
            *(float2*)(stage + (size_t)(row + 8) * 132 + col) = v1;
        }
    __syncthreads();

    if (LNORM) {
        const int c = lane * 4;
        float4 bb = *(const float4*)(bias + c);
        float4 sv = *(const float4*)(ls + c);
        float4 bv = *(const float4*)(lb + c);
#pragma unroll 4
        for (int rr = 0; rr < 16; rr++) {
            int r = wid * 16 + rr;
            float4 v = *(float4*)(stage + (size_t)r * 132 + c);
            float4 res = *(const float4*)(Rr + (size_t)(row0 + r) * 128 + c);
            v.x += bb.x + res.x; v.y += bb.y + res.y;
            v.z += bb.z + res.z; v.w += bb.w + res.w;
            float s = v.x + v.y + v.z + v.w;
#pragma unroll
            for (int o = 16; o; o >>= 1) s += __shfl_xor_sync(0xFFFFFFFFu, s, o);
            float mean = s * (1.f / 128.f);
            float dx = v.x - mean, dy = v.y - mean, dz = v.z - mean, dw = v.w - mean;
            float qq = dx * dx + dy * dy + dz * dz + dw * dw;
#pragma unroll
            for (int o = 16; o; o >>= 1) qq += __shfl_xor_sync(0xFFFFFFFFu, qq, o);
            float rstd = rsqrtf(qq * (1.f / 128.f) + 1e-5f);
            float4 ov;
            ov.x = dx * rstd * sv.x + bv.x;
            ov.y = dy * rstd * sv.y + bv.y;
            ov.z = dz * rstd * sv.z + bv.z;
            ov.w = dw * rstd * sv.w + bv.w;
            if (C) *(float4*)(C + (size_t)(row0 + r) * 128 + c) = ov;
            if (Ch) {
                uint2 uh;
                uh.x = packh_hi2(ov.x, ov.y); uh.y = packh_hi2(ov.z, ov.w);
                *(uint2*)(Ch + (size_t)(row0 + r) * 128 + c) = uh;
            }
        }
    } else {
        for (int i = tid; i < 128 * 32; i += 256) {
            int r = i >> 5, q = i & 31;
            int c = q * 4;
            float4 v = *(float4*)(stage + (size_t)r * 132 + c);
            if (bias) {
                v.x += bias[col0 + c];
                v.y += bias[col0 + c + 1];
                v.z += bias[col0 + c + 2];
                v.w += bias[col0 + c + 3];
            }
            if (RESID) {
                float4 rr = *(const float4*)(Rr + (size_t)(row0 + r) * Nt + col0 + c);
                v.x += rr.x; v.y += rr.y; v.z += rr.z; v.w += rr.w;
            }
            if (ACT == 1) {
                v.x = fmaxf(v.x, 0.f); v.y = fmaxf(v.y, 0.f);
                v.z = fmaxf(v.z, 0.f); v.w = fmaxf(v.w, 0.f);
            }
            if (C) *(float4*)(C + (size_t)(row0 + r) * Nt + col0 + c) = v;
            if (H16) {
                uint2 u;
                u.x = packh_hi2(v.x, v.y);
                u.y = packh_hi2(v.z, v.w);
                *(uint2*)(H16 + (size_t)(row0 + r) * Nt + col0 + c) = u;
            }
            if (Ch) {
                uint2 uh;
                uh.x = packh_hi2(v.x, v.y); uh.y = packh_hi2(v.z, v.w);
                *(uint2*)(Ch + (size_t)(row0 + r) * Nt + col0 + c) = uh;
            }
        }
    }

    if (SCORES && tid < 128) {
        int r = tid;
        float s1 = 0.f, s2 = 0.f;
        const float* as = asrc + col0;
        const float* ad = adst + col0;
        const float* sp = stage + (size_t)r * 132;
#pragma unroll 8
        for (int c = 0; c < 128; c++) {
            float hv = sp[c];
            s1 += hv * as[c];
            s2 += hv * ad[c];
        }
        gss[(size_t)(row0 + r) * 4 + blockIdx.x] = s1;
        gsd[(size_t)(row0 + r) * 4 + blockIdx.x] = s2;
    }
}

// ---------------- fused FF1+FF2 (+bias+resid+LN2) ----------------
template <bool LAST>
__global__ void __launch_bounds__(256, 1)
ff_fused(const __half* __restrict__ Ah, const __half* __restrict__ W1,
         const float* __restrict__ b1, const __half* __restrict__ W2,
         const float* __restrict__ b2, const float* __restrict__ Rr,
         float* __restrict__ C, __half* __restrict__ Ch,
         const float* __restrict__ ls, const float* __restrict__ lb) {
    extern __shared__ char smem[];
    const unsigned sb = smem_u32(smem);
    __half* stageA = (__half*)(smem + FSM_STAGEA);
    const unsigned sa = sb + FSM_STAGEA;
    const int tid = threadIdx.x;
    const int wid = tid >> 5, lane = tid & 31;
    const int wr = wid >> 1, wc = wid & 1;
    const int row0 = blockIdx.x * 128;
    const int ltile = lane >> 3, lrow = lane & 7;

    float acc[2][8][4];

    // ---- Phase 1: FF1, 4 column tiles of 128, K=128 ----
    for (int ct = 0; ct < 4; ct++) {
#pragma unroll
        for (int mt = 0; mt < 2; mt++)
#pragma unroll
            for (int nt = 0; nt < 8; nt++)
#pragma unroll
                for (int e = 0; e < 4; e++) acc[mt][nt][e] = 0.f;

#define LOAD1(cidx, s) do { \
    unsigned base = sb + (s) * STAGE; \
    _Pragma("unroll") \
    for (int j = 0; j < 2; j++) { \
        int i = tid + j * 256; \
        int rr = i >> 2, qq = i & 3; \
        unsigned off = (unsigned)(rr * TROW + qq * 16); \
        cpa16(base + P_A + off, Ah + (size_t)(row0 + rr) * 128 + (cidx) * 32 + qq * 8); \
        cpa16(base + P_B + off, W1 + (size_t)(ct * 128 + rr) * 128 + (cidx) * 32 + qq * 8); \
    } \
} while (0)
        LOAD1(0, 0);
        CPA_COMMIT();
        for (int c = 0; c < 4; c++) {
            if (c + 1 < 4) { LOAD1(c + 1, (c + 1) & 1); CPA_COMMIT(); CPA_WAIT1(); }
            else CPA_WAIT0();
            __syncthreads();
            unsigned base = sb + (c & 1) * STAGE;
#pragma unroll
            for (int ks = 0; ks < 2; ks++) {
                unsigned ah[2][4];
#pragma unroll
                for (int mt = 0; mt < 2; mt++) {
                    int row = wr * 32 + mt * 16 + lrow + (ltile & 1) * 8;
                    int kcol = ks * 16 + (ltile >> 1) * 8;
                    ldmat4(ah[mt][0], ah[mt][1], ah[mt][2], ah[mt][3],
                           base + P_A + (unsigned)(row * TROW + kcol * 2));
                }
#pragma unroll
                for (int g = 0; g < 4; g++) {
                    int n = wc * 64 + g * 16 + lrow + (ltile >> 1) * 8;
                    int kcol = ks * 16 + (ltile & 1) * 8;
                    unsigned bh[4];
                    ldmat4(bh[0], bh[1], bh[2], bh[3],
                           base + P_B + (unsigned)(n * TROW + kcol * 2));
#pragma unroll
                    for (int mt = 0; mt < 2; mt++)
#pragma unroll
                        for (int half = 0; half < 2; half++)
                            mma16816(acc[mt][g * 2 + half],
                                     ah[mt][0], ah[mt][1], ah[mt][2], ah[mt][3],
                                     bh[half * 2], bh[half * 2 + 1]);
                }
            }
            __syncthreads();
        }
#undef LOAD1
        // bias + relu -> staging fp16
#pragma unroll
        for (int mt = 0; mt < 2; mt++)
#pragma unroll
            for (int nt = 0; nt < 8; nt++) {
                int row = wr * 32 + mt * 16 + (lane >> 2);
                int colt = wc * 64 + nt * 8 + (lane & 3) * 2;
                int col = ct * 128 + colt;
                float bx = b1[col], by = b1[col + 1];
                float v0 = fmaxf(acc[mt][nt][0] + bx, 0.f);
                float v1 = fmaxf(acc[mt][nt][1] + by, 0.f);
                float v2 = fmaxf(acc[mt][nt][2] + bx, 0.f);
                float v3 = fmaxf(acc[mt][nt][3] + by, 0.f);
                *(unsigned*)(stageA + (size_t)row * AROW + col) = packh_hi2(v0, v1);
                *(unsigned*)(stageA + (size_t)(row + 8) * AROW + col) = packh_hi2(v2, v3);
            }
        __syncthreads();
    }

    // ---- Phase 2: FF2, K=512, A from staging, B pipelined ----
#pragma unroll
    for (int mt = 0; mt < 2; mt++)
#pragma unroll
        for (int nt = 0; nt < 8; nt++)
#pragma unroll
            for (int e = 0; e < 4; e++) acc[mt][nt][e] = 0.f;

#define LOAD2(cidx, s) do { \
    unsigned base = sb + (s) * PBUF; \
    _Pragma("unroll") \
    for (int j = 0; j < 2; j++) { \
        int i = tid + j * 256; \
        int rr = i >> 2, qq = i & 3; \
        cpa16(base + (unsigned)(rr * TROW + qq * 16), \
              W2 + (size_t)rr * 512 + (cidx) * 32 + qq * 8); \
    } \
} while (0)
    LOAD2(0, 0);
    CPA_COMMIT();
    for (int c = 0; c < 16; c++) {
        if (c + 1 < 16) { LOAD2(c + 1, (c + 1) & 1); CPA_COMMIT(); CPA_WAIT1(); }
        else CPA_WAIT0();
        __syncthreads();
        unsigned base = sb + (c & 1) * PBUF;
#pragma unroll
        for (int ks = 0; ks < 2; ks++) {
            unsigned ah[2][4];
#pragma unroll
            for (int mt = 0; mt < 2; mt++) {
                int row = wr * 32 + mt * 16 + lrow + (ltile & 1) * 8;
                int kcol = c * 32 + ks * 16 + (ltile >> 1) * 8;
                ldmat4(ah[mt][0], ah[mt][1], ah[mt][2], ah[mt][3],
                       sa + (unsigned)(row * (AROW * 2) + kcol * 2));
            }
#pragma unroll
            for (int g = 0; g < 4; g++) {
                int n = wc * 64 + g * 16 + lrow + (ltile >> 1) * 8;
                int kcol = ks * 16 + (ltile & 1) * 8;
                unsigned bh[4];
                ldmat4(bh[0], bh[1], bh[2], bh[3],
                       base + (unsigned)(n * TROW + kcol * 2));
#pragma unroll
                for (int mt = 0; mt < 2; mt++)
#pragma unroll
                    for (int half = 0; half < 2; half++)
                        mma16816(acc[mt][g * 2 + half],
                                 ah[mt][0], ah[mt][1], ah[mt][2], ah[mt][3],
                                 bh[half * 2], bh[half * 2 + 1]);
            }
        }
        __syncthreads();
    }
#undef LOAD2

    // stage accumulators as floats into the (now free) staging region
    float* stage = (float*)stageA;
    __syncthreads();
#pragma unroll
    for (int mt = 0; mt < 2; mt++)
#pragma unroll
        for (int nt = 0; nt < 8; nt++) {
            int row = wr * 32 + mt * 16 + (lane >> 2);
            int col = wc * 64 + nt * 8 + (lane & 3) * 2;
            *(float2*)(stage + (size_t)row * 132 + col) = make_float2(acc[mt][nt][0], acc[mt][nt][1]);
            *(float2*)(stage + (size_t)(row + 8) * 132 + col) = make_float2(acc[mt][nt][2], acc[mt][nt][3]);
        }
    __syncthreads();

    // bias + residual + LayerNorm epilogue
    {
        const int c = lane * 4;
        float4 bb = *(const float4*)(b2 + c);
        float4 sv = *(const float4*)(ls + c);
        float4 bv = *(const float4*)(lb + c);
#pragma unroll 4
        for (int rr = 0; rr < 16; rr++) {
            int r = wid * 16 + rr;
            float4 v = *(float4*)(stage + (size_t)r * 132 + c);
            float4 res = *(const float4*)(Rr + (size_t)(row0 + r) * 128 + c);
            v.x += bb.x + res.x; v.y += bb.y + res.y;
            v.z += bb.z + res.z; v.w += bb.w + res.w;
            float s = v.x + v.y + v.z + v.w;
#pragma unroll
            for (int o = 16; o; o >>= 1) s += __shfl_xor_sync(0xFFFFFFFFu, s, o);
            float mean = s * (1.f / 128.f);
            float dx = v.x - mean, dy = v.y - mean, dz = v.z - mean, dw = v.w - mean;
            float qq = dx * dx + dy * dy + dz * dz + dw * dw;
#pragma unroll
            for (int o = 16; o; o >>= 1) qq += __shfl_xor_sync(0xFFFFFFFFu, qq, o);
            float rstd = rsqrtf(qq * (1.f / 128.f) + 1e-5f);
            float4 ov;
            ov.x = dx * rstd * sv.x + bv.x;
            ov.y = dy * rstd * sv.y + bv.y;
            ov.z = dz * rstd * sv.z + bv.z;
            ov.w = dw * rstd * sv.w + bv.w;
            *(float4*)(C + (size_t)(row0 + r) * 128 + c) = ov;
            if (!LAST) {
                uint2 uh;
                uh.x = packh_hi2(ov.x, ov.y); uh.y = packh_hi2(ov.z, ov.w);
                *(uint2*)(Ch + (size_t)(row0 + r) * 128 + c) = uh;
            }
        }
    }
}

// ---------------- weight conversion ----------------
__global__ void split_weights(const float* __restrict__ gatW, const float* __restrict__ Wqkv,
                              const float* __restrict__ Wo, const float* __restrict__ Wff1,
                              const float* __restrict__ Wff2) {
    int idx = blockIdx.x * 256 + threadIdx.x;
    if (idx >= WTOT) return;
    float v;
    if (idx < OFF_QKV) {
        int i = idx >> 16, r = idx & 65535;
        int n = r >> 7, k = r & 127;
        v = gatW[(i << 16) + k * 512 + n];
    } else if (idx < OFF_WO) {
        int r0 = idx - OFF_QKV;
        int l = r0 / 49152;
        int rem = r0 - l * 49152;
        int n = rem >> 7, k = rem & 127;
        int s = n >> 7, nc = n & 127;
        v = Wqkv[((l * 3 + s) << 14) + k * 128 + nc];
    } else if (idx < OFF_FF1) {
        int r0 = idx - OFF_WO;
        int i = r0 >> 14, r = r0 & 16383;
        int n = r >> 7, k = r & 127;
        v = Wo[(i << 14) + k * 128 + n];
    } else if (idx < OFF_FF2) {
        int r0 = idx - OFF_FF1;
        int i = r0 >> 16, r = r0 & 65535;
        int n = r >> 7, k = r & 127;
        v = Wff1[(i << 16) + k * 512 + n];
    } else {
        int r0 = idx - OFF_FF2;
        int i = r0 >> 16, r = r0 & 65535;
        int n = r >> 9, k = r & 511;
        v = Wff2[(i << 16) + k * 128 + n];
    }
    g_w16[idx] = __float2half_rn(v);
}

// ---------------- tiny precompute ----------------
__global__ void precompute(const float* __restrict__ W, const float* __restrict__ asrc,
                           const float* __restrict__ adst) {
    int tid = threadIdx.x;
    int wid = tid >> 5, lane = tid & 31;
    float a0s = 0.f, a1s = 0.f, a0d = 0.f, a1d = 0.f;
    for (int d = lane; d < 128; d += 32) {
        int c = wid * 128 + d;
        float w0 = W[c], w1 = W[512 + c], as = asrc[c], ad = adst[c];
        a0s += w0 * as; a1s += w1 * as; a0d += w0 * ad; a1d += w1 * ad;
    }
#pragma unroll
    for (int o = 16; o; o >>= 1) {
        a0s += __shfl_xor_sync(0xFFFFFFFFu, a0s, o);
        a1s += __shfl_xor_sync(0xFFFFFFFFu, a1s, o);
        a0d += __shfl_xor_sync(0xFFFFFFFFu, a0d, o);
        a1d += __shfl_xor_sync(0xFFFFFFFFu, a1d, o);
    }
    if (lane == 0) {
        g_c[wid] = a0s; g_c[4 + wid] = a1s; g_c[8 + wid] = a0d; g_c[12 + wid] = a1d;
    }
    for (int i = tid; i < Tt * Hh; i += 128) {
        int t = i >> 7, d = i & 127;
        float freq = expf(-(float)(d & ~1) * (9.210340371976184f / 128.f));
        float ang = (float)t * freq;
        g_pe[i] = (d & 1) ? cosf(ang) : sinf(ang);
    }
}

// ---------------- mask + self-loop init ----------------
__global__ void mask_init(const unsigned char* __restrict__ ego) {
    int idx = blockIdx.x * 256 + threadIdx.x;
    if (idx >= ROWS) return;
    int t = idx >> 10;
    int mm = idx & 1023;
    int b = mm >> 8;
    int n = mm & 255;
    unsigned char v = ego[(b * Tt + t) * 256 + n] ? 1 : 0;
    g_m[idx] = v;
    g_cnt[idx] = v ? 1 : 0;
    g_nbr[idx * MAXD] = (unsigned short)mm;
}

// ---------------- neighbor-list build (2 rows per block, MLP=2) ----------------
__global__ void build_nbr(const float* __restrict__ A) {
    int tj0 = blockIdx.x * 2;
    int tj1 = tj0 + 1;
    bool m0 = g_m[tj0] != 0, m1 = g_m[tj1] != 0;
    int i0 = threadIdx.x * 4;
    float4 a0, a1;
    if (m0) a0 = *(const float4*)(A + (size_t)tj0 * 1024 + i0);
    if (m1) a1 = *(const float4*)(A + (size_t)tj1 * 1024 + i0);
    if (m0) {
        int t = tj0 >> 10, j = tj0 & 1023;
        float av[4] = {a0.x, a0.y, a0.z, a0.w};
#pragma unroll
        for (int e = 0; e < 4; e++) {
            int i = i0 + e;
            if (i == j) continue;
            int ti = (t << 10) + i;
            if (av[e] != 0.f && g_m[ti]) {
                int pos = atomicAdd(&g_cnt[ti], 1);
                if (pos < MAXD) g_nbr[(size_t)ti * MAXD + pos] = (unsigned short)j;
            }
        }
    }
    if (m1) {
        int t = tj1 >> 10, j = tj1 & 1023;
        float av[4] = {a1.x, a1.y, a1.z, a1.w};
#pragma unroll
        for (int e = 0; e < 4; e++) {
            int i = i0 + e;
            if (i == j) continue;
            int ti = (t << 10) + i;
            if (av[e] != 0.f && g_m[ti]) {
                int pos = atomicAdd(&g_cnt[ti], 1);
                if (pos < MAXD) g_nbr[(size_t)ti * MAXD + pos] = (unsigned short)j;
            }
        }
    }
}

// ---------------- GAT layer-0 ----------------
__global__ void gat0(const float* __restrict__ x, const float* __restrict__ W) {
    int idx = blockIdx.x * 256 + threadIdx.x;
    int row = idx >> 9;
    int c = idx & 511;
    float x0 = x[row * 2], x1 = x[row * 2 + 1];
    g_hh[idx] = __float2half(x0 * W[c] + x1 * W[512 + c]);
    if (c < 8) {
        int hh = c & 3;
        int isd = c >> 2;
        float v = x0 * g_c[hh + isd * 8] + x1 * g_c[hh + 4 + isd * 8];
        if (isd == 0) g_ss[row * 4 + hh] = v;
        else g_sd[row * 4 + hh] = v;
    }
}

// ---------------- sparse segment-softmax + aggregation ----------------
template <bool TOSEQ>
__global__ void gat_agg(const float* __restrict__ bias, __half* __restrict__ xh) {
    int row = blockIdx.x;
    int tid = threadIdx.x;
    int t = row >> 10;
    int mm = row & 1023;
    bool alive = g_m[row] != 0;

    __shared__ unsigned short nb[MAXD];
    __shared__ float w[4][MAXD];
    __shared__ float part[128][9];

    float outv = 0.f;
    if (alive) {
        int cnt = g_cnt[row];
        if (cnt > MAXD) cnt = MAXD;
        if (tid < cnt) nb[tid] = g_nbr[(size_t)row * MAXD + tid];

        if (tid < cnt) {
            int jr = (t << 10) + nb[tid];
#pragma unroll
            for (int hh = 0; hh < 4; hh++) {
                float z = g_sd[row * 4 + hh] + g_ss[jr * 4 + hh];
                w[hh][tid] = (z > 0.f) ? z : 0.2f * z;
            }
        } else {
#pragma unroll
            for (int hh = 0; hh < 4; hh++) w[hh][tid] = -INFINITY;
        }
        __syncthreads();

        {
            int wh = tid >> 5, lane = tid & 31;
            float v0 = w[wh][lane], v1 = w[wh][lane + 32], v2 = w[wh][lane + 64], v3 = w[wh][lane + 96];
            float mx = fmaxf(fmaxf(v0, v1), fmaxf(v2, v3));
#pragma unroll
            for (int o = 16; o; o >>= 1) mx = fmaxf(mx, __shfl_xor_sync(0xFFFFFFFFu, mx, o));
            float e0 = expf(v0 - mx), e1 = expf(v1 - mx), e2 = expf(v2 - mx), e3 = expf(v3 - mx);
            float s = e0 + e1 + e2 + e3;
#pragma unroll
            for (int o = 16; o; o >>= 1) s += __shfl_xor_sync(0xFFFFFFFFu, s, o);
            float inv = 1.f / s;
            w[wh][lane] = e0 * inv;
            w[wh][lane + 32] = e1 * inv;
            w[wh][lane + 64] = e2 * inv;
            w[wh][lane + 96] = e3 * inv;
        }
        __syncthreads();

        int h = (tid >> 4) & 3, dsl = tid & 15, nh = tid >> 6;
        float acc[8];
#pragma unroll
        for (int e = 0; e < 8; e++) acc[e] = 0.f;
        const __half* tb = g_hh + (((size_t)(t << 10)) << 9) + h * 128 + dsl * 8;
        for (int j = nh; j < cnt; j += 2) {
            float wj = w[h][j];
            uint4 q = *(const uint4*)(tb + ((size_t)nb[j] << 9));
            __half2* hp = (__half2*)&q;
#pragma unroll
            for (int e = 0; e < 4; e++) {
                float2 f = __half22float2(hp[e]);
                acc[2 * e] += wj * f.x;
                acc[2 * e + 1] += wj * f.y;
            }
        }
#pragma unroll
        for (int e = 0; e < 8; e++) part[tid][e] = acc[e];
        __syncthreads();

        int dsl2 = tid >> 3, e2 = tid & 7;
        float s = 0.f;
#pragma unroll
        for (int k = 0; k < 8; k++) {
            int c = (k & 1) * 64 + (k >> 1) * 16 + dsl2;
            s += part[c][e2];
        }
        outv = fmaxf(s * 0.25f + bias[tid], 0.f);
    }

    if (TOSEQ) {
        float v = outv + g_pe[t * 128 + tid];
        size_t sidx = ((size_t)mm * Tt + t) * Hh + tid;
        g_xs[sidx] = v;
        g_xsh[sidx] = __float2half_rn(v);
    } else {
        xh[(size_t)row * 128 + tid] = __float2half_rn(outv);
    }
}

// ---------------- per-sequence attention ----------------
__global__ void attn_kernel(const __half* __restrict__ QKV, __half* __restrict__ Oh) {
    __shared__ float sq[16][128], sk[16][128], sv[16][128];
    int m = blockIdx.x;
    int tid = threadIdx.x;
    size_t base = (size_t)m * 16 * 384;
    for (int idx = tid; idx < 2048; idx += 128) {
        int t = idx >> 7, d = idx & 127;
        size_t p = base + (size_t)t * 384 + d;
        sq[t][d] = __half2float(QKV[p]);
        sk[t][d] = __half2float(QKV[p + 128]);
        sv[t][d] = __half2float(QKV[p + 256]);
    }
    __syncthreads();
    int h = tid >> 5;
    int tq = (tid >> 1) & 15;
    int half = tid & 1;
    const float scale = 0.17677669529663687f;
    float sc[16];
    float mx = -1e30f;
#pragma unroll
    for (int tk = 0; tk < 16; tk++) {
        float s = 0.f;
#pragma unroll
        for (int dd = 0; dd < 16; dd++) {
            int d = half * 16 + dd;
            s += sq[tq][h * 32 + d] * sk[tk][h * 32 + d];
        }
        s += __shfl_xor_sync(0xFFFFFFFFu, s, 1);
        s *= scale;
        sc[tk] = s;
        mx = fmaxf(mx, s);
    }
    float sum = 0.f;
#pragma unroll
    for (int tk = 0; tk < 16; tk++) { sc[tk] = expf(sc[tk] - mx); sum += sc[tk]; }
    float inv = 1.f / sum;
    size_t ob = (size_t)m * 16 * 128 + (size_t)tq * 128 + h * 32 + half * 16;
#pragma unroll
    for (int dd = 0; dd < 16; dd++) {
        int d = half * 16 + dd;
        float o = 0.f;
#pragma unroll
        for (int tk = 0; tk < 16; tk++) o += sc[tk] * sv[tk][h * 32 + d];
        Oh[ob + dd] = __float2half_rn(o * inv);
    }
}

// ---------------- launcher ----------------
extern "C" void kernel_launch(void* const* d_in, const int* in_sizes, int n_in,
                              void* d_out, int out_size) {
    const unsigned char* ego = (const unsigned char*)d_in[0];
    const float* positions  = (const float*)d_in[1];
    const float* adjacency  = (const float*)d_in[2];
    const float* gat1_W     = (const float*)d_in[3];
    const float* gat1_asrc  = (const float*)d_in[4];
    const float* gat1_adst  = (const float*)d_in[5];
    const float* gat1_b     = (const float*)d_in[6];
    const float* gatW       = (const float*)d_in[7];
    const float* gat_asrc   = (const float*)d_in[8];
    const float* gat_adst   = (const float*)d_in[9];
    const float* gat_b      = (const float*)d_in[10];
    const float* Wqkv       = (const float*)d_in[11];
    const float* bqkv       = (const float*)d_in[12];
    const float* Wo         = (const float*)d_in[13];
    const float* bo         = (const float*)d_in[14];
    const float* ln1_s      = (const float*)d_in[15];
    const float* ln1_b      = (const float*)d_in[16];
    const float* ln2_s      = (const float*)d_in[17];
    const float* ln2_b      = (const float*)d_in[18];
    const float* Wff1       = (const float*)d_in[19];
    const float* bff1       = (const float*)d_in[20];
    const float* Wff2       = (const float*)d_in[21];
    const float* bff2       = (const float*)d_in[22];
    float* out = (float*)d_out;

    float *xs, *ss, *sd;
    __half *qkv, *hh, *w16, *xa, *xb, *xsh, *atth;
    cudaGetSymbolAddress((void**)&qkv,  g_qkv);
    cudaGetSymbolAddress((void**)&hh,   g_hh);
    cudaGetSymbolAddress((void**)&xs,   g_xs);
    cudaGetSymbolAddress((void**)&ss,   g_ss);
    cudaGetSymbolAddress((void**)&sd,   g_sd);
    cudaGetSymbolAddress((void**)&w16,  g_w16);
    cudaGetSymbolAddress((void**)&xa,   g_xa);
    cudaGetSymbolAddress((void**)&xb,   g_xb);
    cudaGetSymbolAddress((void**)&xsh,  g_xsh);
    cudaGetSymbolAddress((void**)&atth, g_atth);

    cudaFuncSetAttribute(gemm_tc<0, false, true,  false>, cudaFuncAttributeMaxDynamicSharedMemorySize, GSM_TOTAL);
    cudaFuncSetAttribute(gemm_tc<0, false, false, false>, cudaFuncAttributeMaxDynamicSharedMemorySize, GSM_TOTAL);
    cudaFuncSetAttribute(gemm_tc<0, true,  false, true >, cudaFuncAttributeMaxDynamicSharedMemorySize, GSM_TOTAL);
    cudaFuncSetAttribute(ff_fused<false>, cudaFuncAttributeMaxDynamicSharedMemorySize, FSM_TOTAL);
    cudaFuncSetAttribute(ff_fused<true>,  cudaFuncAttributeMaxDynamicSharedMemorySize, FSM_TOTAL);

    split_weights<<<(WTOT + 255) / 256, 256>>>(gatW, Wqkv, Wo, Wff1, Wff2);
    precompute<<<1, 128>>>(gat1_W, gat1_asrc, gat1_adst);
    mask_init<<<ROWS / 256, 256>>>(ego);
    build_nbr<<<ROWS / 2, 256>>>(adjacency);

    gat0<<<ROWS * 512 / 256, 256>>>(positions, gat1_W);
    gat_agg<false><<<ROWS, 128>>>(gat1_b, xa);

    __half *cur = xa, *nxt = xb;
    for (int i = 0; i < 5; i++) {
        dim3 gp(4, ROWS / 128);
        gemm_tc<0, false, true, false><<<gp, 256, GSM_TOTAL>>>(
            cur, w16 + OFF_GAT + (size_t)i * 65536,
            nullptr, nullptr, nullptr, nullptr, hh,
            gat_asrc + i * 512, gat_adst + i * 512, ss, sd, nullptr, nullptr, 512, 128);
        if (i < 4) {
            gat_agg<false><<<ROWS, 128>>>(gat_b + i * 128, nxt);
            __half* t0 = cur; cur = nxt; nxt = t0;
        } else {
            gat_agg<true><<<ROWS, 128>>>(gat_b + i * 128, nullptr);
        }
    }

    dim3 g1(1, ROWS / 128);
    dim3 gq(3, ROWS / 128);
    for (int l = 0; l < NL_TR; l++) {
        size_t oq = OFF_QKV + (size_t)l * 49152;
        gemm_tc<0, false, false, false><<<gq, 256, GSM_TOTAL>>>(
            xsh, w16 + oq,
            bqkv + l * 384, nullptr, nullptr, nullptr, qkv,
            nullptr, nullptr, nullptr, nullptr, nullptr, nullptr, 384, 128);
        attn_kernel<<<Mm, 128>>>(qkv, atth);
        size_t owo = OFF_WO + (size_t)l * 16384;
        gemm_tc<0, true, false, true><<<g1, 256, GSM_TOTAL>>>(
            atth, w16 + owo,
            bo + l * 128, xs, xs, xsh, nullptr,
            nullptr, nullptr, nullptr, nullptr,
            ln1_s + l * 128, ln1_b + l * 128, 128, 128);
        size_t of1 = OFF_FF1 + (size_t)l * 65536;
        size_t of2 = OFF_FF2 + (size_t)l * 65536;
        if (l == NL_TR - 1) {
            ff_fused<true><<<ROWS / 128, 256, FSM_TOTAL>>>(
                xsh, w16 + of1, bff1 + l * 512, w16 + of2, bff2 + l * 128,
                xs, out, nullptr, ln2_s + l * 128, ln2_b + l * 128);
        } else {
            ff_fused<false><<<ROWS / 128, 256, FSM_TOTAL>>>(
                xsh, w16 + of1, bff1 + l * 512, w16 + of2, bff2 + l * 128,
                xs, xs, xsh, ln2_s + l * 128, ln2_b + l * 128);
        }
    }
}

// round 15
// speedup vs baseline: 2.4484x; 1.2589x over previous
#include <cuda_runtime.h>
#include <cuda_bf16.h>
#include <cuda_fp16.h>
#include <math.h>

// Problem dims
#define Tt 16
#define Mm 1024
#define Hh 128
#define ROWS 16384
#define MAXD 128
#define NL_TR 5

// ---------------- scratch ----------------
__device__ __half g_hh[ROWS * 512];
__device__ float g_ss[ROWS * 4];
__device__ float g_sd[ROWS * 4];
__device__ unsigned char g_m[ROWS];
__device__ int g_cnt[ROWS];
__device__ unsigned short g_nbr[ROWS * MAXD];
__device__ float g_xs[ROWS * Hh];
__device__ float g_c[16];
__device__ float g_pe[Tt * Hh];
__device__ __half g_xa[ROWS * Hh];
__device__ __half g_xb[ROWS * Hh];
__device__ __half g_xsh[ROWS * Hh];

#define WTOT 1310720
#define OFF_GAT 0
#define OFF_QKV 327680
#define OFF_WO  573440
#define OFF_FF1 655360
#define OFF_FF2 983040
__device__ __half g_w16[WTOT];

__device__ __forceinline__ unsigned smem_u32(const void* p) {
    unsigned a;
    asm("{ .reg .u64 t; cvta.to.shared.u64 t, %1; cvt.u32.u64 %0, t; }" : "=r"(a) : "l"(p));
    return a;
}
__device__ __forceinline__ void ldmat4(unsigned& r0, unsigned& r1, unsigned& r2, unsigned& r3, unsigned addr) {
    asm volatile("ldmatrix.sync.aligned.m8n8.x4.shared.b16 {%0,%1,%2,%3}, [%4];"
        : "=r"(r0), "=r"(r1), "=r"(r2), "=r"(r3) : "r"(addr));
}
__device__ __forceinline__ void mma16816(float* c, unsigned a0, unsigned a1, unsigned a2, unsigned a3,
                                         unsigned b0, unsigned b1) {
    asm volatile("mma.sync.aligned.m16n8k16.row.col.f32.f16.f16.f32 "
        "{%0,%1,%2,%3}, {%4,%5,%6,%7}, {%8,%9}, {%0,%1,%2,%3};"
        : "+f"(c[0]), "+f"(c[1]), "+f"(c[2]), "+f"(c[3])
        : "r"(a0), "r"(a1), "r"(a2), "r"(a3), "r"(b0), "r"(b1));
}
__device__ __forceinline__ void cpa16(unsigned dst, const void* src) {
    asm volatile("cp.async.ca.shared.global [%0], [%1], 16;" :: "r"(dst), "l"(src));
}
#define CPA_COMMIT() asm volatile("cp.async.commit_group;" ::: "memory")
#define CPA_WAIT1() asm volatile("cp.async.wait_group 1;" ::: "memory")
#define CPA_WAIT0() asm volatile("cp.async.wait_group 0;" ::: "memory")

__device__ __forceinline__ unsigned packh_hi2(float a, float b) {
    __half2 h = __floats2half2_rn(a, b);
    return *(unsigned*)&h;
}

// SMEM pipeline: planes of 128 rows x 32 fp16 (80B stride)
#define TROW 80
#define PBUF (128 * TROW)
#define STAGE (2 * PBUF)
#define P_A 0
#define P_B PBUF
#define GSM_TOTAL 67584

// ff_fused smem
#define FSM_STAGEA 40960
#define AROW 520
#define FSM_TOTAL (40960 + 128 * AROW * 2)   // 174080

// attn block smem: [0,40960) pipeline; stQKV 128 x 392 halves; stO 128 x 136 halves
#define ASM_QKV 40960
#define QROW 392
#define ASM_O (40960 + 128 * QROW * 2)       // 141312
#define OROW 136
#define ASM_TOTAL (ASM_O + 128 * OROW * 2)   // 176128

// ---------------- HMMA GEMM (GAT projection path only now) ----------------
template <int ACT, bool SCORES>
__global__ void __launch_bounds__(256, 2)
gemm_tc(const __half* __restrict__ Ah, const __half* __restrict__ B16,
        __half* __restrict__ H16,
        const float* __restrict__ asrc, const float* __restrict__ adst,
        float* __restrict__ gss, float* __restrict__ gsd, int Nt, int Kt) {
    extern __shared__ char smem[];
    const unsigned sb = smem_u32(smem);
    const int tid = threadIdx.x;
    const int wid = tid >> 5, lane = tid & 31;
    const int wr = wid >> 1, wc = wid & 1;
    const int row0 = blockIdx.y * 128;
    const int col0 = blockIdx.x * 128;

    float acc[2][8][4];
#pragma unroll
    for (int mt = 0; mt < 2; mt++)
#pragma unroll
        for (int nt = 0; nt < 8; nt++)
#pragma unroll
            for (int e = 0; e < 4; e++) acc[mt][nt][e] = 0.f;

    const int ltile = lane >> 3, lrow = lane & 7;
    const int nch = Kt >> 5;

#define LOAD_CHUNK(cidx, s) do { \
    unsigned base = sb + (s) * STAGE; \
    _Pragma("unroll") \
    for (int j = 0; j < 2; j++) { \
        int i = tid + j * 256; \
        int rr = i >> 2, qq = i & 3; \
        unsigned off = (unsigned)(rr * TROW + qq * 16); \
        cpa16(base + P_A + off, Ah + (size_t)(row0 + rr) * Kt + (cidx) * 32 + qq * 8); \
        cpa16(base + P_B + off, B16 + (size_t)(col0 + rr) * Kt + (cidx) * 32 + qq * 8); \
    } \
} while (0)

    LOAD_CHUNK(0, 0);
    CPA_COMMIT();
    for (int c = 0; c < nch; c++) {
        if (c + 1 < nch) { LOAD_CHUNK(c + 1, (c + 1) & 1); CPA_COMMIT(); CPA_WAIT1(); }
        else CPA_WAIT0();
        __syncthreads();
        unsigned base = sb + (c & 1) * STAGE;
#pragma unroll
        for (int ks = 0; ks < 2; ks++) {
            unsigned ah[2][4];
#pragma unroll
            for (int mt = 0; mt < 2; mt++) {
                int row = wr * 32 + mt * 16 + lrow + (ltile & 1) * 8;
                int kcol = ks * 16 + (ltile >> 1) * 8;
                ldmat4(ah[mt][0], ah[mt][1], ah[mt][2], ah[mt][3],
                       base + P_A + (unsigned)(row * TROW + kcol * 2));
            }
#pragma unroll
            for (int g = 0; g < 4; g++) {
                int n = wc * 64 + g * 16 + lrow + (ltile >> 1) * 8;
                int kcol = ks * 16 + (ltile & 1) * 8;
                unsigned bh[4];
                ldmat4(bh[0], bh[1], bh[2], bh[3],
                       base + P_B + (unsigned)(n * TROW + kcol * 2));
#pragma unroll
                for (int mt = 0; mt < 2; mt++)
#pragma unroll
                    for (int half = 0; half < 2; half++)
                        mma16816(acc[mt][g * 2 + half],
                                 ah[mt][0], ah[mt][1], ah[mt][2], ah[mt][3],
                                 bh[half * 2], bh[half * 2 + 1]);
            }
        }
        __syncthreads();
    }
#undef LOAD_CHUNK

    float* stage = (float*)smem;
#pragma unroll
    for (int mt = 0; mt < 2; mt++)
#pragma unroll
        for (int nt = 0; nt < 8; nt++) {
            int row = wr * 32 + mt * 16 + (lane >> 2);
            int col = wc * 64 + nt * 8 + (lane & 3) * 2;
            *(float2*)(stage + (size_t)row * 132 + col) = make_float2(acc[mt][nt][0], acc[mt][nt][1]);
            *(float2*)(stage + (size_t)(row + 8) * 132 + col) = make_float2(acc[mt][nt][2], acc[mt][nt][3]);
        }
    __syncthreads();

    for (int i = tid; i < 128 * 32; i += 256) {
        int r = i >> 5, q = i & 31;
        int c = q * 4;
        float4 v = *(float4*)(stage + (size_t)r * 132 + c);
        uint2 u;
        u.x = packh_hi2(v.x, v.y);
        u.y = packh_hi2(v.z, v.w);
        *(uint2*)(H16 + (size_t)(row0 + r) * Nt + col0 + c) = u;
    }

    if (SCORES && tid < 128) {
        int r = tid;
        float s1 = 0.f, s2 = 0.f;
        const float* as = asrc + col0;
        const float* ad = adst + col0;
        const float* sp = stage + (size_t)r * 132;
#pragma unroll 8
        for (int c = 0; c < 128; c++) {
            float hv = sp[c];
            s1 += hv * as[c];
            s2 += hv * ad[c];
        }
        gss[(size_t)(row0 + r) * 4 + blockIdx.x] = s1;
        gsd[(size_t)(row0 + r) * 4 + blockIdx.x] = s2;
    }
}

// ---------------- fused QKV + attention + Wo + LN1 ----------------
__global__ void __launch_bounds__(256, 1)
attnblock(const __half* __restrict__ Ah, const __half* __restrict__ Wqkv16,
          const float* __restrict__ bqkv, const __half* __restrict__ Wo16,
          const float* __restrict__ bo, const float* __restrict__ Rr,
          float* __restrict__ C, __half* __restrict__ Ch,
          const float* __restrict__ ls, const float* __restrict__ lb) {
    extern __shared__ char smem[];
    const unsigned sb = smem_u32(smem);
    __half* stQ = (__half*)(smem + ASM_QKV);
    __half* stO = (__half*)(smem + ASM_O);
    const unsigned so = sb + ASM_O;
    const int tid = threadIdx.x;
    const int wid = tid >> 5, lane = tid & 31;
    const int wr = wid >> 1, wc = wid & 1;
    const int row0 = blockIdx.x * 128;
    const int ltile = lane >> 3, lrow = lane & 7;

    float acc[2][8][4];

    // ---- Phase 1: QKV GEMM, 3 column tiles, K=128 ----
    for (int ct = 0; ct < 3; ct++) {
#pragma unroll
        for (int mt = 0; mt < 2; mt++)
#pragma unroll
            for (int nt = 0; nt < 8; nt++)
#pragma unroll
                for (int e = 0; e < 4; e++) acc[mt][nt][e] = 0.f;

#define LOADQ(cidx, s) do { \
    unsigned base = sb + (s) * STAGE; \
    _Pragma("unroll") \
    for (int j = 0; j < 2; j++) { \
        int i = tid + j * 256; \
        int rr = i >> 2, qq = i & 3; \
        unsigned off = (unsigned)(rr * TROW + qq * 16); \
        cpa16(base + P_A + off, Ah + (size_t)(row0 + rr) * 128 + (cidx) * 32 + qq * 8); \
        cpa16(base + P_B + off, Wqkv16 + (size_t)(ct * 128 + rr) * 128 + (cidx) * 32 + qq * 8); \
    } \
} while (0)
        LOADQ(0, 0);
        CPA_COMMIT();
        for (int c = 0; c < 4; c++) {
            if (c + 1 < 4) { LOADQ(c + 1, (c + 1) & 1); CPA_COMMIT(); CPA_WAIT1(); }
            else CPA_WAIT0();
            __syncthreads();
            unsigned base = sb + (c & 1) * STAGE;
#pragma unroll
            for (int ks = 0; ks < 2; ks++) {
                unsigned ah[2][4];
#pragma unroll
                for (int mt = 0; mt < 2; mt++) {
                    int row = wr * 32 + mt * 16 + lrow + (ltile & 1) * 8;
                    int kcol = ks * 16 + (ltile >> 1) * 8;
                    ldmat4(ah[mt][0], ah[mt][1], ah[mt][2], ah[mt][3],
                           base + P_A + (unsigned)(row * TROW + kcol * 2));
                }
#pragma unroll
                for (int g = 0; g < 4; g++) {
                    int n = wc * 64 + g * 16 + lrow + (ltile >> 1) * 8;
                    int kcol = ks * 16 + (ltile & 1) * 8;
                    unsigned bh[4];
                    ldmat4(bh[0], bh[1], bh[2], bh[3],
                           base + P_B + (unsigned)(n * TROW + kcol * 2));
#pragma unroll
                    for (int mt = 0; mt < 2; mt++)
#pragma unroll
                        for (int half = 0; half < 2; half++)
                            mma16816(acc[mt][g * 2 + half],
                                     ah[mt][0], ah[mt][1], ah[mt][2], ah[mt][3],
                                     bh[half * 2], bh[half * 2 + 1]);
                }
            }
            __syncthreads();
        }
#undef LOADQ
#pragma unroll
        for (int mt = 0; mt < 2; mt++)
#pragma unroll
            for (int nt = 0; nt < 8; nt++) {
                int row = wr * 32 + mt * 16 + (lane >> 2);
                int colt = wc * 64 + nt * 8 + (lane & 3) * 2;
                int col = ct * 128 + colt;
                float bx = bqkv[col], by = bqkv[col + 1];
                *(unsigned*)(stQ + (size_t)row * QROW + col) =
                    packh_hi2(acc[mt][nt][0] + bx, acc[mt][nt][1] + by);
                *(unsigned*)(stQ + (size_t)(row + 8) * QROW + col) =
                    packh_hi2(acc[mt][nt][2] + bx, acc[mt][nt][3] + by);
            }
        __syncthreads();
    }

    // ---- Phase 2: attention, 8 sequences, 2 at a time ----
    {
        int sl2 = tid >> 7;           // 0/1: which seq of the pair
        int t2 = tid & 127;
        int h = t2 >> 5;
        int tq = (t2 >> 1) & 15;
        int half = t2 & 1;
        const float scale = 0.17677669529663687f;
        for (int p = 0; p < 4; p++) {
            int sl = p * 2 + sl2;     // local sequence 0..7
            const __half* qb = stQ + (size_t)(sl * 16) * QROW;
            float sc[16];
            float mx = -1e30f;
#pragma unroll
            for (int tk = 0; tk < 16; tk++) {
                float s = 0.f;
                const __half* qr = qb + (size_t)tq * QROW + h * 32 + half * 16;
                const __half* kr = qb + (size_t)tk * QROW + 128 + h * 32 + half * 16;
#pragma unroll
                for (int dd = 0; dd < 16; dd++)
                    s += __half2float(qr[dd]) * __half2float(kr[dd]);
                s += __shfl_xor_sync(0xFFFFFFFFu, s, 1);
                s *= scale;
                sc[tk] = s;
                mx = fmaxf(mx, s);
            }
            float sum = 0.f;
#pragma unroll
            for (int tk = 0; tk < 16; tk++) { sc[tk] = expf(sc[tk] - mx); sum += sc[tk]; }
            float inv = 1.f / sum;
            __half* orow = stO + (size_t)(sl * 16 + tq) * OROW + h * 32 + half * 16;
#pragma unroll
            for (int dd = 0; dd < 16; dd++) {
                float o = 0.f;
                const __half* vcol = qb + 256 + h * 32 + half * 16 + dd;
#pragma unroll
                for (int tk = 0; tk < 16; tk++)
                    o += sc[tk] * __half2float(vcol[(size_t)tk * QROW]);
                orow[dd] = __float2half_rn(o * inv);
            }
        }
    }
    __syncthreads();

    // ---- Phase 3: Wo GEMM, K=128, A from stO, B pipelined ----
#pragma unroll
    for (int mt = 0; mt < 2; mt++)
#pragma unroll
        for (int nt = 0; nt < 8; nt++)
#pragma unroll
            for (int e = 0; e < 4; e++) acc[mt][nt][e] = 0.f;

#define LOADW(cidx, s) do { \
    unsigned base = sb + (s) * PBUF; \
    _Pragma("unroll") \
    for (int j = 0; j < 2; j++) { \
        int i = tid + j * 256; \
        int rr = i >> 2, qq = i & 3; \
        cpa16(base + (unsigned)(rr * TROW + qq * 16), \
              Wo16 + (size_t)rr * 128 + (cidx) * 32 + qq * 8); \
    } \
} while (0)
    LOADW(0, 0);
    CPA_COMMIT();
    for (int c = 0; c < 4; c++) {
        if (c + 1 < 4) { LOADW(c + 1, (c + 1) & 1); CPA_COMMIT(); CPA_WAIT1(); }
        else CPA_WAIT0();
        __syncthreads();
        unsigned base = sb + (c & 1) * PBUF;
#pragma unroll
        for (int ks = 0; ks < 2; ks++) {
            unsigned ah[2][4];
#pragma unroll
            for (int mt = 0; mt < 2; mt++) {
                int row = wr * 32 + mt * 16 + lrow + (ltile & 1) * 8;
                int kcol = c * 32 + ks * 16 + (ltile >> 1) * 8;
                ldmat4(ah[mt][0], ah[mt][1], ah[mt][2], ah[mt][3],
                       so + (unsigned)(row * (OROW * 2) + kcol * 2));
            }
#pragma unroll
            for (int g = 0; g < 4; g++) {
                int n = wc * 64 + g * 16 + lrow + (ltile >> 1) * 8;
                int kcol = ks * 16 + (ltile & 1) * 8;
                unsigned bh[4];
                ldmat4(bh[0], bh[1], bh[2], bh[3],
                       base + (unsigned)(n * TROW + kcol * 2));
#pragma unroll
                for (int mt = 0; mt < 2; mt++)
#pragma unroll
                    for (int half = 0; half < 2; half++)
                        mma16816(acc[mt][g * 2 + half],
                                 ah[mt][0], ah[mt][1], ah[mt][2], ah[mt][3],
                                 bh[half * 2], bh[half * 2 + 1]);
            }
        }
        __syncthreads();
    }
#undef LOADW

    float* stage = (float*)stQ;
    __syncthreads();
#pragma unroll
    for (int mt = 0; mt < 2; mt++)
#pragma unroll
        for (int nt = 0; nt < 8; nt++) {
            int row = wr * 32 + mt * 16 + (lane >> 2);
            int col = wc * 64 + nt * 8 + (lane & 3) * 2;
            *(float2*)(stage + (size_t)row * 132 + col) = make_float2(acc[mt][nt][0], acc[mt][nt][1]);
            *(float2*)(stage + (size_t)(row + 8) * 132 + col) = make_float2(acc[mt][nt][2], acc[mt][nt][3]);
        }
    __syncthreads();

    {
        const int c = lane * 4;
        float4 bb = *(const float4*)(bo + c);
        float4 sv = *(const float4*)(ls + c);
        float4 bv = *(const float4*)(lb + c);
#pragma unroll 4
        for (int rr = 0; rr < 16; rr++) {
            int r = wid * 16 + rr;
            float4 v = *(float4*)(stage + (size_t)r * 132 + c);
            float4 res = *(const float4*)(Rr + (size_t)(row0 + r) * 128 + c);
            v.x += bb.x + res.x; v.y += bb.y + res.y;
            v.z += bb.z + res.z; v.w += bb.w + res.w;
            float s = v.x + v.y + v.z + v.w;
#pragma unroll
            for (int o = 16; o; o >>= 1) s += __shfl_xor_sync(0xFFFFFFFFu, s, o);
            float mean = s * (1.f / 128.f);
            float dx = v.x - mean, dy = v.y - mean, dz = v.z - mean, dw = v.w - mean;
            float qq = dx * dx + dy * dy + dz * dz + dw * dw;
#pragma unroll
            for (int o = 16; o; o >>= 1) qq += __shfl_xor_sync(0xFFFFFFFFu, qq, o);
            float rstd = rsqrtf(qq * (1.f / 128.f) + 1e-5f);
            float4 ov;
            ov.x = dx * rstd * sv.x + bv.x;
            ov.y = dy * rstd * sv.y + bv.y;
            ov.z = dz * rstd * sv.z + bv.z;
            ov.w = dw * rstd * sv.w + bv.w;
            *(float4*)(C + (size_t)(row0 + r) * 128 + c) = ov;
            uint2 uh;
            uh.x = packh_hi2(ov.x, ov.y); uh.y = packh_hi2(ov.z, ov.w);
            *(uint2*)(Ch + (size_t)(row0 + r) * 128 + c) = uh;
        }
    }
}

// ---------------- fused FF1+FF2 (+bias+resid+LN2) ----------------
template <bool LAST>
__global__ void __launch_bounds__(256, 1)
ff_fused(const __half* __restrict__ Ah, const __half* __restrict__ W1,
         const float* __restrict__ b1, const __half* __restrict__ W2,
         const float* __restrict__ b2, const float* __restrict__ Rr,
         float* __restrict__ C, __half* __restrict__ Ch,
         const float* __restrict__ ls, const float* __restrict__ lb) {
    extern __shared__ char smem[];
    const unsigned sb = smem_u32(smem);
    __half* stageA = (__half*)(smem + FSM_STAGEA);
    const unsigned sa = sb + FSM_STAGEA;
    const int tid = threadIdx.x;
    const int wid = tid >> 5, lane = tid & 31;
    const int wr = wid >> 1, wc = wid & 1;
    const int row0 = blockIdx.x * 128;
    const int ltile = lane >> 3, lrow = lane & 7;

    float acc[2][8][4];

    for (int ct = 0; ct < 4; ct++) {
#pragma unroll
        for (int mt = 0; mt < 2; mt++)
#pragma unroll
            for (int nt = 0; nt < 8; nt++)
#pragma unroll
                for (int e = 0; e < 4; e++) acc[mt][nt][e] = 0.f;

#define LOAD1(cidx, s) do { \
    unsigned base = sb + (s) * STAGE; \
    _Pragma("unroll") \
    for (int j = 0; j < 2; j++) { \
        int i = tid + j * 256; \
        int rr = i >> 2, qq = i & 3; \
        unsigned off = (unsigned)(rr * TROW + qq * 16); \
        cpa16(base + P_A + off, Ah + (size_t)(row0 + rr) * 128 + (cidx) * 32 + qq * 8); \
        cpa16(base + P_B + off, W1 + (size_t)(ct * 128 + rr) * 128 + (cidx) * 32 + qq * 8); \
    } \
} while (0)
        LOAD1(0, 0);
        CPA_COMMIT();
        for (int c = 0; c < 4; c++) {
            if (c + 1 < 4) { LOAD1(c + 1, (c + 1) & 1); CPA_COMMIT(); CPA_WAIT1(); }
            else CPA_WAIT0();
            __syncthreads();
            unsigned base = sb + (c & 1) * STAGE;
#pragma unroll
            for (int ks = 0; ks < 2; ks++) {
                unsigned ah[2][4];
#pragma unroll
                for (int mt = 0; mt < 2; mt++) {
                    int row = wr * 32 + mt * 16 + lrow + (ltile & 1) * 8;
                    int kcol = ks * 16 + (ltile >> 1) * 8;
                    ldmat4(ah[mt][0], ah[mt][1], ah[mt][2], ah[mt][3],
                           base + P_A + (unsigned)(row * TROW + kcol * 2));
                }
#pragma unroll
                for (int g = 0; g < 4; g++) {
                    int n = wc * 64 + g * 16 + lrow + (ltile >> 1) * 8;
                    int kcol = ks * 16 + (ltile & 1) * 8;
                    unsigned bh[4];
                    ldmat4(bh[0], bh[1], bh[2], bh[3],
                           base + P_B + (unsigned)(n * TROW + kcol * 2));
#pragma unroll
                    for (int mt = 0; mt < 2; mt++)
#pragma unroll
                        for (int half = 0; half < 2; half++)
                            mma16816(acc[mt][g * 2 + half],
                                     ah[mt][0], ah[mt][1], ah[mt][2], ah[mt][3],
                                     bh[half * 2], bh[half * 2 + 1]);
                }
            }
            __syncthreads();
        }
#undef LOAD1
#pragma unroll
        for (int mt = 0; mt < 2; mt++)
#pragma unroll
            for (int nt = 0; nt < 8; nt++) {
                int row = wr * 32 + mt * 16 + (lane >> 2);
                int colt = wc * 64 + nt * 8 + (lane & 3) * 2;
                int col = ct * 128 + colt;
                float bx = b1[col], by = b1[col + 1];
                float v0 = fmaxf(acc[mt][nt][0] + bx, 0.f);
                float v1 = fmaxf(acc[mt][nt][1] + by, 0.f);
                float v2 = fmaxf(acc[mt][nt][2] + bx, 0.f);
                float v3 = fmaxf(acc[mt][nt][3] + by, 0.f);
                *(unsigned*)(stageA + (size_t)row * AROW + col) = packh_hi2(v0, v1);
                *(unsigned*)(stageA + (size_t)(row + 8) * AROW + col) = packh_hi2(v2, v3);
            }
        __syncthreads();
    }

#pragma unroll
    for (int mt = 0; mt < 2; mt++)
#pragma unroll
        for (int nt = 0; nt < 8; nt++)
#pragma unroll
            for (int e = 0; e < 4; e++) acc[mt][nt][e] = 0.f;

#define LOAD2(cidx, s) do { \
    unsigned base = sb + (s) * PBUF; \
    _Pragma("unroll") \
    for (int j = 0; j < 2; j++) { \
        int i = tid + j * 256; \
        int rr = i >> 2, qq = i & 3; \
        cpa16(base + (unsigned)(rr * TROW + qq * 16), \
              W2 + (size_t)rr * 512 + (cidx) * 32 + qq * 8); \
    } \
} while (0)
    LOAD2(0, 0);
    CPA_COMMIT();
    for (int c = 0; c < 16; c++) {
        if (c + 1 < 16) { LOAD2(c + 1, (c + 1) & 1); CPA_COMMIT(); CPA_WAIT1(); }
        else CPA_WAIT0();
        __syncthreads();
        unsigned base = sb + (c & 1) * PBUF;
#pragma unroll
        for (int ks = 0; ks < 2; ks++) {
            unsigned ah[2][4];
#pragma unroll
            for (int mt = 0; mt < 2; mt++) {
                int row = wr * 32 + mt * 16 + lrow + (ltile & 1) * 8;
                int kcol = c * 32 + ks * 16 + (ltile >> 1) * 8;
                ldmat4(ah[mt][0], ah[mt][1], ah[mt][2], ah[mt][3],
                       sa + (unsigned)(row * (AROW * 2) + kcol * 2));
            }
#pragma unroll
            for (int g = 0; g < 4; g++) {
                int n = wc * 64 + g * 16 + lrow + (ltile >> 1) * 8;
                int kcol = ks * 16 + (ltile & 1) * 8;
                unsigned bh[4];
                ldmat4(bh[0], bh[1], bh[2], bh[3],
                       base + (unsigned)(n * TROW + kcol * 2));
#pragma unroll
                for (int mt = 0; mt < 2; mt++)
#pragma unroll
                    for (int half = 0; half < 2; half++)
                        mma16816(acc[mt][g * 2 + half],
                                 ah[mt][0], ah[mt][1], ah[mt][2], ah[mt][3],
                                 bh[half * 2], bh[half * 2 + 1]);
            }
        }
        __syncthreads();
    }
#undef LOAD2

    float* stage = (float*)stageA;
    __syncthreads();
#pragma unroll
    for (int mt = 0; mt < 2; mt++)
#pragma unroll
        for (int nt = 0; nt < 8; nt++) {
            int row = wr * 32 + mt * 16 + (lane >> 2);
            int col = wc * 64 + nt * 8 + (lane & 3) * 2;
            *(float2*)(stage + (size_t)row * 132 + col) = make_float2(acc[mt][nt][0], acc[mt][nt][1]);
            *(float2*)(stage + (size_t)(row + 8) * 132 + col) = make_float2(acc[mt][nt][2], acc[mt][nt][3]);
        }
    __syncthreads();

    {
        const int c = lane * 4;
        float4 bb = *(const float4*)(b2 + c);
        float4 sv = *(const float4*)(ls + c);
        float4 bv = *(const float4*)(lb + c);
#pragma unroll 4
        for (int rr = 0; rr < 16; rr++) {
            int r = wid * 16 + rr;
            float4 v = *(float4*)(stage + (size_t)r * 132 + c);
            float4 res = *(const float4*)(Rr + (size_t)(row0 + r) * 128 + c);
            v.x += bb.x + res.x; v.y += bb.y + res.y;
            v.z += bb.z + res.z; v.w += bb.w + res.w;
            float s = v.x + v.y + v.z + v.w;
#pragma unroll
            for (int o = 16; o; o >>= 1) s += __shfl_xor_sync(0xFFFFFFFFu, s, o);
            float mean = s * (1.f / 128.f);
            float dx = v.x - mean, dy = v.y - mean, dz = v.z - mean, dw = v.w - mean;
            float qq = dx * dx + dy * dy + dz * dz + dw * dw;
#pragma unroll
            for (int o = 16; o; o >>= 1) qq += __shfl_xor_sync(0xFFFFFFFFu, qq, o);
            float rstd = rsqrtf(qq * (1.f / 128.f) + 1e-5f);
            float4 ov;
            ov.x = dx * rstd * sv.x + bv.x;
            ov.y = dy * rstd * sv.y + bv.y;
            ov.z = dz * rstd * sv.z + bv.z;
            ov.w = dw * rstd * sv.w + bv.w;
            *(float4*)(C + (size_t)(row0 + r) * 128 + c) = ov;
            if (!LAST) {
                uint2 uh;
                uh.x = packh_hi2(ov.x, ov.y); uh.y = packh_hi2(ov.z, ov.w);
                *(uint2*)(Ch + (size_t)(row0 + r) * 128 + c) = uh;
            }
        }
    }
}

// ---------------- weight conversion ----------------
__global__ void split_weights(const float* __restrict__ gatW, const float* __restrict__ Wqkv,
                              const float* __restrict__ Wo, const float* __restrict__ Wff1,
                              const float* __restrict__ Wff2) {
    int idx = blockIdx.x * 256 + threadIdx.x;
    if (idx >= WTOT) return;
    float v;
    if (idx < OFF_QKV) {
        int i = idx >> 16, r = idx & 65535;
        int n = r >> 7, k = r & 127;
        v = gatW[(i << 16) + k * 512 + n];
    } else if (idx < OFF_WO) {
        int r0 = idx - OFF_QKV;
        int l = r0 / 49152;
        int rem = r0 - l * 49152;
        int n = rem >> 7, k = rem & 127;
        int s = n >> 7, nc = n & 127;
        v = Wqkv[((l * 3 + s) << 14) + k * 128 + nc];
    } else if (idx < OFF_FF1) {
        int r0 = idx - OFF_WO;
        int i = r0 >> 14, r = r0 & 16383;
        int n = r >> 7, k = r & 127;
        v = Wo[(i << 14) + k * 128 + n];
    } else if (idx < OFF_FF2) {
        int r0 = idx - OFF_FF1;
        int i = r0 >> 16, r = r0 & 65535;
        int n = r >> 7, k = r & 127;
        v = Wff1[(i << 16) + k * 512 + n];
    } else {
        int r0 = idx - OFF_FF2;
        int i = r0 >> 16, r = r0 & 65535;
        int n = r >> 9, k = r & 511;
        v = Wff2[(i << 16) + k * 128 + n];
    }
    g_w16[idx] = __float2half_rn(v);
}

// ---------------- tiny precompute ----------------
__global__ void precompute(const float* __restrict__ W, const float* __restrict__ asrc,
                           const float* __restrict__ adst) {
    int tid = threadIdx.x;
    int wid = tid >> 5, lane = tid & 31;
    float a0s = 0.f, a1s = 0.f, a0d = 0.f, a1d = 0.f;
    for (int d = lane; d < 128; d += 32) {
        int c = wid * 128 + d;
        float w0 = W[c], w1 = W[512 + c], as = asrc[c], ad = adst[c];
        a0s += w0 * as; a1s += w1 * as; a0d += w0 * ad; a1d += w1 * ad;
    }
#pragma unroll
    for (int o = 16; o; o >>= 1) {
        a0s += __shfl_xor_sync(0xFFFFFFFFu, a0s, o);
        a1s += __shfl_xor_sync(0xFFFFFFFFu, a1s, o);
        a0d += __shfl_xor_sync(0xFFFFFFFFu, a0d, o);
        a1d += __shfl_xor_sync(0xFFFFFFFFu, a1d, o);
    }
    if (lane == 0) {
        g_c[wid] = a0s; g_c[4 + wid] = a1s; g_c[8 + wid] = a0d; g_c[12 + wid] = a1d;
    }
    for (int i = tid; i < Tt * Hh; i += 128) {
        int t = i >> 7, d = i & 127;
        float freq = expf(-(float)(d & ~1) * (9.210340371976184f / 128.f));
        float ang = (float)t * freq;
        g_pe[i] = (d & 1) ? cosf(ang) : sinf(ang);
    }
}

// ---------------- mask + self-loop init ----------------
__global__ void mask_init(const unsigned char* __restrict__ ego) {
    int idx = blockIdx.x * 256 + threadIdx.x;
    if (idx >= ROWS) return;
    int t = idx >> 10;
    int mm = idx & 1023;
    int b = mm >> 8;
    int n = mm & 255;
    unsigned char v = ego[(b * Tt + t) * 256 + n] ? 1 : 0;
    g_m[idx] = v;
    g_cnt[idx] = v ? 1 : 0;
    g_nbr[idx * MAXD] = (unsigned short)mm;
}

// ---------------- neighbor-list build ----------------
__global__ void build_nbr(const float* __restrict__ A) {
    int tj0 = blockIdx.x * 2;
    int tj1 = tj0 + 1;
    bool m0 = g_m[tj0] != 0, m1 = g_m[tj1] != 0;
    int i0 = threadIdx.x * 4;
    float4 a0, a1;
    if (m0) a0 = *(const float4*)(A + (size_t)tj0 * 1024 + i0);
    if (m1) a1 = *(const float4*)(A + (size_t)tj1 * 1024 + i0);
    if (m0) {
        int t = tj0 >> 10, j = tj0 & 1023;
        float av[4] = {a0.x, a0.y, a0.z, a0.w};
#pragma unroll
        for (int e = 0; e < 4; e++) {
            int i = i0 + e;
            if (i == j) continue;
            int ti = (t << 10) + i;
            if (av[e] != 0.f && g_m[ti]) {
                int pos = atomicAdd(&g_cnt[ti], 1);
                if (pos < MAXD) g_nbr[(size_t)ti * MAXD + pos] = (unsigned short)j;
            }
        }
    }
    if (m1) {
        int t = tj1 >> 10, j = tj1 & 1023;
        float av[4] = {a1.x, a1.y, a1.z, a1.w};
#pragma unroll
        for (int e = 0; e < 4; e++) {
            int i = i0 + e;
            if (i == j) continue;
            int ti = (t << 10) + i;
            if (av[e] != 0.f && g_m[ti]) {
                int pos = atomicAdd(&g_cnt[ti], 1);
                if (pos < MAXD) g_nbr[(size_t)ti * MAXD + pos] = (unsigned short)j;
            }
        }
    }
}

// ---------------- GAT layer-0 ----------------
__global__ void gat0(const float* __restrict__ x, const float* __restrict__ W) {
    int idx = blockIdx.x * 256 + threadIdx.x;
    int row = idx >> 9;
    int c = idx & 511;
    float x0 = x[row * 2], x1 = x[row * 2 + 1];
    g_hh[idx] = __float2half(x0 * W[c] + x1 * W[512 + c]);
    if (c < 8) {
        int hh = c & 3;
        int isd = c >> 2;
        float v = x0 * g_c[hh + isd * 8] + x1 * g_c[hh + 4 + isd * 8];
        if (isd == 0) g_ss[row * 4 + hh] = v;
        else g_sd[row * 4 + hh] = v;
    }
}

// ---------------- sparse segment-softmax + aggregation ----------------
template <bool TOSEQ>
__global__ void gat_agg(const float* __restrict__ bias, __half* __restrict__ xh) {
    int row = blockIdx.x;
    int tid = threadIdx.x;
    int t = row >> 10;
    int mm = row & 1023;
    bool alive = g_m[row] != 0;

    __shared__ unsigned short nb[MAXD];
    __shared__ float w[4][MAXD];
    __shared__ float part[128][9];

    float outv = 0.f;
    if (alive) {
        int cnt = g_cnt[row];
        if (cnt > MAXD) cnt = MAXD;
        if (tid < cnt) nb[tid] = g_nbr[(size_t)row * MAXD + tid];

        if (tid < cnt) {
            int jr = (t << 10) + nb[tid];
#pragma unroll
            for (int hh = 0; hh < 4; hh++) {
                float z = g_sd[row * 4 + hh] + g_ss[jr * 4 + hh];
                w[hh][tid] = (z > 0.f) ? z : 0.2f * z;
            }
        } else {
#pragma unroll
            for (int hh = 0; hh < 4; hh++) w[hh][tid] = -INFINITY;
        }
        __syncthreads();

        {
            int wh = tid >> 5, lane = tid & 31;
            float v0 = w[wh][lane], v1 = w[wh][lane + 32], v2 = w[wh][lane + 64], v3 = w[wh][lane + 96];
            float mx = fmaxf(fmaxf(v0, v1), fmaxf(v2, v3));
#pragma unroll
            for (int o = 16; o; o >>= 1) mx = fmaxf(mx, __shfl_xor_sync(0xFFFFFFFFu, mx, o));
            float e0 = expf(v0 - mx), e1 = expf(v1 - mx), e2 = expf(v2 - mx), e3 = expf(v3 - mx);
            float s = e0 + e1 + e2 + e3;
#pragma unroll
            for (int o = 16; o; o >>= 1) s += __shfl_xor_sync(0xFFFFFFFFu, s, o);
            float inv = 1.f / s;
            w[wh][lane] = e0 * inv;
            w[wh][lane + 32] = e1 * inv;
            w[wh][lane + 64] = e2 * inv;
            w[wh][lane + 96] = e3 * inv;
        }
        __syncthreads();

        int h = (tid >> 4) & 3, dsl = tid & 15, nh = tid >> 6;
        float acc[8];
#pragma unroll
        for (int e = 0; e < 8; e++) acc[e] = 0.f;
        const __half* tb = g_hh + (((size_t)(t << 10)) << 9) + h * 128 + dsl * 8;
        for (int j = nh; j < cnt; j += 2) {
            float wj = w[h][j];
            uint4 q = *(const uint4*)(tb + ((size_t)nb[j] << 9));
            __half2* hp = (__half2*)&q;
#pragma unroll
            for (int e = 0; e < 4; e++) {
                float2 f = __half22float2(hp[e]);
                acc[2 * e] += wj * f.x;
                acc[2 * e + 1] += wj * f.y;
            }
        }
#pragma unroll
        for (int e = 0; e < 8; e++) part[tid][e] = acc[e];
        __syncthreads();

        int dsl2 = tid >> 3, e2 = tid & 7;
        float s = 0.f;
#pragma unroll
        for (int k = 0; k < 8; k++) {
            int c = (k & 1) * 64 + (k >> 1) * 16 + dsl2;
            s += part[c][e2];
        }
        outv = fmaxf(s * 0.25f + bias[tid], 0.f);
    }

    if (TOSEQ) {
        float v = outv + g_pe[t * 128 + tid];
        size_t sidx = ((size_t)mm * Tt + t) * Hh + tid;
        g_xs[sidx] = v;
        g_xsh[sidx] = __float2half_rn(v);
    } else {
        xh[(size_t)row * 128 + tid] = __float2half_rn(outv);
    }
}

// ---------------- launcher ----------------
extern "C" void kernel_launch(void* const* d_in, const int* in_sizes, int n_in,
                              void* d_out, int out_size) {
    const unsigned char* ego = (const unsigned char*)d_in[0];
    const float* positions  = (const float*)d_in[1];
    const float* adjacency  = (const float*)d_in[2];
    const float* gat1_W     = (const float*)d_in[3];
    const float* gat1_asrc  = (const float*)d_in[4];
    const float* gat1_adst  = (const float*)d_in[5];
    const float* gat1_b     = (const float*)d_in[6];
    const float* gatW       = (const float*)d_in[7];
    const float* gat_asrc   = (const float*)d_in[8];
    const float* gat_adst   = (const float*)d_in[9];
    const float* gat_b      = (const float*)d_in[10];
    const float* Wqkv       = (const float*)d_in[11];
    const float* bqkv       = (const float*)d_in[12];
    const float* Wo         = (const float*)d_in[13];
    const float* bo         = (const float*)d_in[14];
    const float* ln1_s      = (const float*)d_in[15];
    const float* ln1_b      = (const float*)d_in[16];
    const float* ln2_s      = (const float*)d_in[17];
    const float* ln2_b      = (const float*)d_in[18];
    const float* Wff1       = (const float*)d_in[19];
    const float* bff1       = (const float*)d_in[20];
    const float* Wff2       = (const float*)d_in[21];
    const float* bff2       = (const float*)d_in[22];
    float* out = (float*)d_out;

    float *xs, *ss, *sd;
    __half *hh, *w16, *xa, *xb, *xsh;
    cudaGetSymbolAddress((void**)&hh,   g_hh);
    cudaGetSymbolAddress((void**)&xs,   g_xs);
    cudaGetSymbolAddress((void**)&ss,   g_ss);
    cudaGetSymbolAddress((void**)&sd,   g_sd);
    cudaGetSymbolAddress((void**)&w16,  g_w16);
    cudaGetSymbolAddress((void**)&xa,   g_xa);
    cudaGetSymbolAddress((void**)&xb,   g_xb);
    cudaGetSymbolAddress((void**)&xsh,  g_xsh);

    cudaFuncSetAttribute(gemm_tc<0, true>, cudaFuncAttributeMaxDynamicSharedMemorySize, GSM_TOTAL);
    cudaFuncSetAttribute(attnblock,       cudaFuncAttributeMaxDynamicSharedMemorySize, ASM_TOTAL);
    cudaFuncSetAttribute(ff_fused<false>, cudaFuncAttributeMaxDynamicSharedMemorySize, FSM_TOTAL);
    cudaFuncSetAttribute(ff_fused<true>,  cudaFuncAttributeMaxDynamicSharedMemorySize, FSM_TOTAL);

    split_weights<<<(WTOT + 255) / 256, 256>>>(gatW, Wqkv, Wo, Wff1, Wff2);
    precompute<<<1, 128>>>(gat1_W, gat1_asrc, gat1_adst);
    mask_init<<<ROWS / 256, 256>>>(ego);
    build_nbr<<<ROWS / 2, 256>>>(adjacency);

    gat0<<<ROWS * 512 / 256, 256>>>(positions, gat1_W);
    gat_agg<false><<<ROWS, 128>>>(gat1_b, xa);

    __half *cur = xa, *nxt = xb;
    for (int i = 0; i < 5; i++) {
        dim3 gp(4, ROWS / 128);
        gemm_tc<0, true><<<gp, 256, GSM_TOTAL>>>(
            cur, w16 + OFF_GAT + (size_t)i * 65536, hh,
            gat_asrc + i * 512, gat_adst + i * 512, ss, sd, 512, 128);
        if (i < 4) {
            gat_agg<false><<<ROWS, 128>>>(gat_b + i * 128, nxt);
            __half* t0 = cur; cur = nxt; nxt = t0;
        } else {
            gat_agg<true><<<ROWS, 128>>>(gat_b + i * 128, nullptr);
        }
    }

    for (int l = 0; l < NL_TR; l++) {
        size_t oq = OFF_QKV + (size_t)l * 49152;
        size_t owo = OFF_WO + (size_t)l * 16384;
        attnblock<<<ROWS / 128, 256, ASM_TOTAL>>>(
            xsh, w16 + oq, bqkv + l * 384, w16 + owo, bo + l * 128,
            xs, xs, xsh, ln1_s + l * 128, ln1_b + l * 128);
        size_t of1 = OFF_FF1 + (size_t)l * 65536;
        size_t of2 = OFF_FF2 + (size_t)l * 65536;
        if (l == NL_TR - 1) {
            ff_fused<true><<<ROWS / 128, 256, FSM_TOTAL>>>(
                xsh, w16 + of1, bff1 + l * 512, w16 + of2, bff2 + l * 128,
                xs, out, nullptr, ln2_s + l * 128, ln2_b + l * 128);
        } else {
            ff_fused<false><<<ROWS / 128, 256, FSM_TOTAL>>>(
                xsh, w16 + of1, bff1 + l * 512, w16 + of2, bff2 + l * 128,
                xs, xs, xsh, ln2_s + l * 128, ln2_b + l * 128);
        }
    }
}